// round 1
// baseline (speedup 1.0000x reference)
#include <cuda_runtime.h>
#include <math.h>

// Problem constants
#define Bb_ 2
#define Tt_ 2048
#define Cc_ 2048
#define Hh_ 16
#define HKV_ 4
#define HDv_ 128
#define Mm_ (Bb_ * Tt_)      // 4096 rows for all projections
#define KVN_ 1024            // 2*C/G

// Scratch (device globals; no allocation allowed)
__device__ float g_q[(size_t)Mm_ * Cc_];    // (B,T,H*HD) query after projection
__device__ float g_kv[(size_t)Mm_ * KVN_];  // (B,T, k(512) | v(512))
__device__ float g_y[(size_t)Mm_ * Cc_];    // attention output (B,T,H*HD)

// ---------------------------------------------------------------------------
// SGEMM: C[M,N] = A[M,K] @ B[K,N] + bias[N]   (all row-major fp32)
// 128x128 block tile, BK=8, 8x8 per-thread microtile, 256 threads.
// M%128==0, N%128==0, K%8==0 hold for all three calls (no bounds checks).
// ---------------------------------------------------------------------------
template <int BM, int BN, int BK, int TM, int TN>
__global__ void __launch_bounds__(256, 2)
sgemm_bias(int M, int N, int K,
           const float* __restrict__ A, const float* __restrict__ B,
           const float* __restrict__ bias, float* __restrict__ C)
{
    __shared__ float As[BK][BM];   // A tile stored transposed
    __shared__ float Bs[BK][BN];

    const int tid  = threadIdx.x;
    const int tcol = tid % (BN / TN);   // 0..15
    const int trow = tid / (BN / TN);   // 0..15

    // load mapping: one float4 of A and one float4 of B per thread per k-step
    const int aRow = tid / (BK / 4);          // 0..127
    const int aCol = (tid % (BK / 4)) * 4;    // 0 or 4
    const int bRow = tid / (BN / 4);          // 0..7
    const int bCol = (tid % (BN / 4)) * 4;    // 0..124

    const float* Ab = A + (size_t)blockIdx.y * BM * K;
    const float* Bblk = B + blockIdx.x * BN;

    float acc[TM][TN];
#pragma unroll
    for (int i = 0; i < TM; i++)
#pragma unroll
        for (int j = 0; j < TN; j++) acc[i][j] = 0.f;

    for (int k0 = 0; k0 < K; k0 += BK) {
        float4 a4 = *(const float4*)(Ab + (size_t)aRow * K + k0 + aCol);
        As[aCol + 0][aRow] = a4.x;
        As[aCol + 1][aRow] = a4.y;
        As[aCol + 2][aRow] = a4.z;
        As[aCol + 3][aRow] = a4.w;
        *(float4*)(&Bs[bRow][bCol]) =
            *(const float4*)(Bblk + (size_t)(k0 + bRow) * N + bCol);
        __syncthreads();

#pragma unroll
        for (int kk = 0; kk < BK; kk++) {
            float ra[TM], rb[TN];
#pragma unroll
            for (int i = 0; i < TM; i++) ra[i] = As[kk][trow * TM + i];
#pragma unroll
            for (int j = 0; j < TN; j++) rb[j] = Bs[kk][tcol * TN + j];
#pragma unroll
            for (int i = 0; i < TM; i++)
#pragma unroll
                for (int j = 0; j < TN; j++)
                    acc[i][j] = fmaf(ra[i], rb[j], acc[i][j]);
        }
        __syncthreads();
    }

#pragma unroll
    for (int i = 0; i < TM; i++) {
        const int row = blockIdx.y * BM + trow * TM + i;
#pragma unroll
        for (int j = 0; j < TN; j += 4) {
            const int col = blockIdx.x * BN + tcol * TN + j;
            float4 o;
            o.x = acc[i][j + 0] + bias[col + 0];
            o.y = acc[i][j + 1] + bias[col + 1];
            o.z = acc[i][j + 2] + bias[col + 2];
            o.w = acc[i][j + 3] + bias[col + 3];
            *(float4*)(C + (size_t)row * N + col) = o;
        }
    }
}

// ---------------------------------------------------------------------------
// Flash attention (fp32, causal, GQA).
// q: (B,T,H,HD) row-major as (B*T, 2048); kv: (B*T, 1024) = [k(4x128) | v(4x128)]
// head h uses kv head h % HKV  (matches the reference's expand:
//   reshape(B,T,HKV,HD) broadcast over G inserted BEFORE HKV -> h = g*HKV + kvh)
// Block: 256 threads as 16x16. Br=Bc=64. Per thread: S 4x4, O 4x8.
// ---------------------------------------------------------------------------
#define BR_ 64
#define BC_ 64
#define LDK_ 132   // padded row stride for Q/K/V tiles (16B aligned, conflict-light)
#define LDP_ 65    // padded row stride for P tile

#define FLASH_SMEM ((3 * BR_ * LDK_ + BR_ * LDP_) * (int)sizeof(float))

__global__ void __launch_bounds__(256, 1)
flash_kernel(const float* __restrict__ q, const float* __restrict__ kv,
             float* __restrict__ y)
{
    extern __shared__ float sm[];
    float* Qs = sm;                   // [BR_][LDK_]
    float* Ks = Qs + BR_ * LDK_;      // [BC_][LDK_]
    float* Vs = Ks + BC_ * LDK_;      // [BC_][LDK_]
    float* Ps = Vs + BC_ * LDK_;      // [BR_][LDP_]

    const int qt = blockIdx.x;        // query tile (T/64)
    const int h  = blockIdx.y;        // head
    const int b  = blockIdx.z;        // batch
    const int kvh = h & (HKV_ - 1);   // kv head = h % 4

    const int tid = threadIdx.x;
    const int tx = tid & 15;
    const int ty = tid >> 4;
    const float scale = 0.08838834764831843f;  // 1/sqrt(128)

    // ---- load Q tile (scaled) ----
    for (int i = tid; i < BR_ * HDv_ / 4; i += 256) {
        const int r = i >> 5;           // / (HD/4 = 32)
        const int c = (i & 31) << 2;
        const float4 v4 = *(const float4*)(
            q + (size_t)(b * Tt_ + qt * BR_ + r) * Cc_ + h * HDv_ + c);
        float4 s4;
        s4.x = v4.x * scale; s4.y = v4.y * scale;
        s4.z = v4.z * scale; s4.w = v4.w * scale;
        *(float4*)(Qs + r * LDK_ + c) = s4;
    }

    float acc[4][8];
    float m_[4], l_[4];
#pragma unroll
    for (int r = 0; r < 4; r++) {
        m_[r] = -INFINITY; l_[r] = 0.f;
#pragma unroll
        for (int j = 0; j < 8; j++) acc[r][j] = 0.f;
    }

    for (int kt = 0; kt <= qt; ++kt) {
        __syncthreads();   // prior iteration's Vs/Ps reads done; Qs visible (1st iter)

        // ---- load K,V tiles ----
        for (int i = tid; i < BC_ * HDv_ / 4; i += 256) {
            const int r = i >> 5;
            const int c = (i & 31) << 2;
            const float* base =
                kv + (size_t)(b * Tt_ + kt * BC_ + r) * KVN_ + kvh * HDv_ + c;
            *(float4*)(Ks + r * LDK_ + c) = *(const float4*)(base);
            *(float4*)(Vs + r * LDK_ + c) = *(const float4*)(base + 512);
        }
        __syncthreads();

        // ---- S = Q K^T  (4x4 per thread; rows ty*4+rr, cols cc*16+tx) ----
        float s[4][4];
#pragma unroll
        for (int r = 0; r < 4; r++)
#pragma unroll
            for (int c = 0; c < 4; c++) s[r][c] = 0.f;

#pragma unroll 4
        for (int d = 0; d < HDv_; d++) {
            float qr[4], kr[4];
#pragma unroll
            for (int rr = 0; rr < 4; rr++) qr[rr] = Qs[(ty * 4 + rr) * LDK_ + d];
#pragma unroll
            for (int cc = 0; cc < 4; cc++) kr[cc] = Ks[(cc * 16 + tx) * LDK_ + d];
#pragma unroll
            for (int rr = 0; rr < 4; rr++)
#pragma unroll
                for (int cc = 0; cc < 4; cc++)
                    s[rr][cc] = fmaf(qr[rr], kr[cc], s[rr][cc]);
        }

        // ---- causal mask on diagonal tile ----
        if (kt == qt) {
#pragma unroll
            for (int rr = 0; rr < 4; rr++)
#pragma unroll
                for (int cc = 0; cc < 4; cc++)
                    if ((cc * 16 + tx) > (ty * 4 + rr)) s[rr][cc] = -1e30f;
        }

        // ---- online softmax update ----
#pragma unroll
        for (int rr = 0; rr < 4; rr++) {
            float rm = s[rr][0];
#pragma unroll
            for (int cc = 1; cc < 4; cc++) rm = fmaxf(rm, s[rr][cc]);
#pragma unroll
            for (int off = 8; off >= 1; off >>= 1)
                rm = fmaxf(rm, __shfl_xor_sync(0xffffffffu, rm, off));

            const float newm = fmaxf(m_[rr], rm);
            float p[4], rs = 0.f;
#pragma unroll
            for (int cc = 0; cc < 4; cc++) {
                p[cc] = __expf(s[rr][cc] - newm);
                rs += p[cc];
            }
#pragma unroll
            for (int off = 8; off >= 1; off >>= 1)
                rs += __shfl_xor_sync(0xffffffffu, rs, off);

            const float alpha = __expf(m_[rr] - newm);
            l_[rr] = l_[rr] * alpha + rs;
            m_[rr] = newm;
#pragma unroll
            for (int j = 0; j < 8; j++) acc[rr][j] *= alpha;
#pragma unroll
            for (int cc = 0; cc < 4; cc++)
                Ps[(ty * 4 + rr) * LDP_ + cc * 16 + tx] = p[cc];
        }
        __syncthreads();   // Ps visible to all

        // ---- O += P V  (rows ty*4+rr, cols j*16+tx) ----
#pragma unroll 4
        for (int k = 0; k < BC_; k++) {
            float pr[4], vr[8];
#pragma unroll
            for (int rr = 0; rr < 4; rr++) pr[rr] = Ps[(ty * 4 + rr) * LDP_ + k];
#pragma unroll
            for (int j = 0; j < 8; j++) vr[j] = Vs[k * LDK_ + j * 16 + tx];
#pragma unroll
            for (int rr = 0; rr < 4; rr++)
#pragma unroll
                for (int j = 0; j < 8; j++)
                    acc[rr][j] = fmaf(pr[rr], vr[j], acc[rr][j]);
        }
    }

    // ---- normalize + store (B,T,H,HD) ----
#pragma unroll
    for (int rr = 0; rr < 4; rr++) {
        const float inv = 1.f / l_[rr];
        const int row = qt * BR_ + ty * 4 + rr;
        float* dst = y + (size_t)(b * Tt_ + row) * Cc_ + h * HDv_;
#pragma unroll
        for (int j = 0; j < 8; j++) dst[j * 16 + tx] = acc[rr][j] * inv;
    }
}

// ---------------------------------------------------------------------------
// Launch
// ---------------------------------------------------------------------------
extern "C" void kernel_launch(void* const* d_in, const int* in_sizes, int n_in,
                              void* d_out, int out_size)
{
    const float* x   = (const float*)d_in[0];
    const float* Wkv = (const float*)d_in[1];
    const float* bkv = (const float*)d_in[2];
    const float* Wq  = (const float*)d_in[3];
    const float* bq  = (const float*)d_in[4];
    const float* Wp  = (const float*)d_in[5];
    const float* bp  = (const float*)d_in[6];
    float* out = (float*)d_out;

    float *qp, *kvp, *yp;
    cudaGetSymbolAddress((void**)&qp,  g_q);
    cudaGetSymbolAddress((void**)&kvp, g_kv);
    cudaGetSymbolAddress((void**)&yp,  g_y);

    cudaFuncSetAttribute(flash_kernel,
                         cudaFuncAttributeMaxDynamicSharedMemorySize,
                         FLASH_SMEM);

    // q = x @ Wq + bq        (4096 x 2048 x 2048)
    sgemm_bias<128, 128, 8, 8, 8>
        <<<dim3(Cc_ / 128, Mm_ / 128), 256>>>(Mm_, Cc_, Cc_, x, Wq, bq, qp);
    // kv = x @ Wkv + bkv     (4096 x 1024 x 2048)
    sgemm_bias<128, 128, 8, 8, 8>
        <<<dim3(KVN_ / 128, Mm_ / 128), 256>>>(Mm_, KVN_, Cc_, x, Wkv, bkv, kvp);
    // y = causal GQA attention
    flash_kernel<<<dim3(Tt_ / BR_, Hh_, Bb_), 256, FLASH_SMEM>>>(qp, kvp, yp);
    // out = y @ Wp + bp      (4096 x 2048 x 2048)
    sgemm_bias<128, 128, 8, 8, 8>
        <<<dim3(Cc_ / 128, Mm_ / 128), 256>>>(Mm_, Cc_, Cc_, yp, Wp, bp, out);
}

// round 2
// speedup vs baseline: 1.0538x; 1.0538x over previous
#include <cuda_runtime.h>
#include <math.h>

// Problem constants
#define Bb_ 2
#define Tt_ 2048
#define Cc_ 2048
#define Hh_ 16
#define HKV_ 4
#define HDv_ 128
#define Mm_ (Bb_ * Tt_)      // 4096 rows for all projections
#define KVN_ 1024            // 2*C/G

// Scratch (device globals; no allocation allowed)
__device__ float g_q[(size_t)Mm_ * Cc_];    // (B,T,H*HD) query after projection
__device__ float g_kv[(size_t)Mm_ * KVN_];  // (B,T, k(512) | v(512))
__device__ float g_y[(size_t)Mm_ * Cc_];    // attention output (B,T,H*HD)

// ---------------------------------------------------------------------------
// SGEMM: C[M,N] = A[M,K] @ B[K,N] + bias[N]   (all row-major fp32)
// 128x128 block tile, BK=16, double-buffered smem, LDG->reg->STS pipeline,
// 8x8 per-thread microtile, 256 threads. One __syncthreads per k-tile.
// M%128==0, N%128==0, K%16==0 hold for all three calls (no bounds checks).
// ---------------------------------------------------------------------------
#define GBM 128
#define GBN 128
#define GBK 16

__global__ void __launch_bounds__(256, 2)
sgemm_bias(int M, int N, int K,
           const float* __restrict__ A, const float* __restrict__ B,
           const float* __restrict__ bias, float* __restrict__ C)
{
    __shared__ float As[2][GBK][GBM];   // A tile stored transposed
    __shared__ float Bs[2][GBK][GBN];

    const int tid  = threadIdx.x;
    const int tcol = tid & 15;          // 0..15
    const int trow = tid >> 4;          // 0..15

    // load mapping: 2 float4 of A + 2 float4 of B per thread per k-tile
    const int aRow = tid >> 2;          // 0..63   (also aRow+64)
    const int aCol = (tid & 3) << 2;    // 0,4,8,12
    const int bRow = tid >> 5;          // 0..7    (also bRow+8)
    const int bCol = (tid & 31) << 2;   // 0..124

    const float* Ab   = A + (size_t)blockIdx.y * GBM * K;
    const float* Bblk = B + blockIdx.x * GBN;

    float acc[8][8];
#pragma unroll
    for (int i = 0; i < 8; i++)
#pragma unroll
        for (int j = 0; j < 8; j++) acc[i][j] = 0.f;

    const int nt = K / GBK;

    // ---- prologue: fill buffer 0 ----
    {
        float4 a0 = *(const float4*)(Ab + (size_t)aRow * K + aCol);
        float4 a1 = *(const float4*)(Ab + (size_t)(aRow + 64) * K + aCol);
        float4 b0 = *(const float4*)(Bblk + (size_t)bRow * N + bCol);
        float4 b1 = *(const float4*)(Bblk + (size_t)(bRow + 8) * N + bCol);
        As[0][aCol + 0][aRow] = a0.x;
        As[0][aCol + 1][aRow] = a0.y;
        As[0][aCol + 2][aRow] = a0.z;
        As[0][aCol + 3][aRow] = a0.w;
        As[0][aCol + 0][aRow + 64] = a1.x;
        As[0][aCol + 1][aRow + 64] = a1.y;
        As[0][aCol + 2][aRow + 64] = a1.z;
        As[0][aCol + 3][aRow + 64] = a1.w;
        *(float4*)(&Bs[0][bRow][bCol])     = b0;
        *(float4*)(&Bs[0][bRow + 8][bCol]) = b1;
    }
    __syncthreads();

    for (int t = 0; t < nt; ++t) {
        const int cur = t & 1;
        float4 a0, a1, b0, b1;
        const bool more = (t + 1 < nt);
        if (more) {
            const int k0 = (t + 1) * GBK;
            a0 = *(const float4*)(Ab + (size_t)aRow * K + k0 + aCol);
            a1 = *(const float4*)(Ab + (size_t)(aRow + 64) * K + k0 + aCol);
            b0 = *(const float4*)(Bblk + (size_t)(k0 + bRow) * N + bCol);
            b1 = *(const float4*)(Bblk + (size_t)(k0 + bRow + 8) * N + bCol);
        }

#pragma unroll
        for (int kk = 0; kk < GBK; kk++) {
            float ra[8], rb[8];
            *(float4*)(&ra[0]) = *(const float4*)(&As[cur][kk][trow * 8]);
            *(float4*)(&ra[4]) = *(const float4*)(&As[cur][kk][trow * 8 + 4]);
            *(float4*)(&rb[0]) = *(const float4*)(&Bs[cur][kk][tcol * 8]);
            *(float4*)(&rb[4]) = *(const float4*)(&Bs[cur][kk][tcol * 8 + 4]);
#pragma unroll
            for (int i = 0; i < 8; i++)
#pragma unroll
                for (int j = 0; j < 8; j++)
                    acc[i][j] = fmaf(ra[i], rb[j], acc[i][j]);
        }

        if (more) {
            const int nxt = cur ^ 1;
            As[nxt][aCol + 0][aRow] = a0.x;
            As[nxt][aCol + 1][aRow] = a0.y;
            As[nxt][aCol + 2][aRow] = a0.z;
            As[nxt][aCol + 3][aRow] = a0.w;
            As[nxt][aCol + 0][aRow + 64] = a1.x;
            As[nxt][aCol + 1][aRow + 64] = a1.y;
            As[nxt][aCol + 2][aRow + 64] = a1.z;
            As[nxt][aCol + 3][aRow + 64] = a1.w;
            *(float4*)(&Bs[nxt][bRow][bCol])     = b0;
            *(float4*)(&Bs[nxt][bRow + 8][bCol]) = b1;
            __syncthreads();
        }
    }

#pragma unroll
    for (int i = 0; i < 8; i++) {
        const int row = blockIdx.y * GBM + trow * 8 + i;
#pragma unroll
        for (int j = 0; j < 8; j += 4) {
            const int col = blockIdx.x * GBN + tcol * 8 + j;
            float4 o;
            o.x = acc[i][j + 0] + bias[col + 0];
            o.y = acc[i][j + 1] + bias[col + 1];
            o.z = acc[i][j + 2] + bias[col + 2];
            o.w = acc[i][j + 3] + bias[col + 3];
            *(float4*)(C + (size_t)row * N + col) = o;
        }
    }
}

// ---------------------------------------------------------------------------
// Flash attention (fp32, causal, GQA).
// q: (B,T,H,HD) row-major as (B*T, 2048); kv: (B*T, 1024) = [k(4x128) | v(4x128)]
// head h uses kv head h % HKV.
// Block: 256 threads as 16x16. Br=Bc=64. Per thread: S 4x4, O 4x8.
// ---------------------------------------------------------------------------
#define BR_ 64
#define BC_ 64
#define LDK_ 132   // padded row stride for Q/K/V tiles
#define LDP_ 65    // padded row stride for P tile

#define FLASH_SMEM ((3 * BR_ * LDK_ + BR_ * LDP_) * (int)sizeof(float))

__global__ void __launch_bounds__(256, 1)
flash_kernel(const float* __restrict__ q, const float* __restrict__ kv,
             float* __restrict__ y)
{
    extern __shared__ float sm[];
    float* Qs = sm;                   // [BR_][LDK_]
    float* Ks = Qs + BR_ * LDK_;      // [BC_][LDK_]
    float* Vs = Ks + BC_ * LDK_;      // [BC_][LDK_]
    float* Ps = Vs + BC_ * LDK_;      // [BR_][LDP_]

    const int qt = blockIdx.x;
    const int h  = blockIdx.y;
    const int b  = blockIdx.z;
    const int kvh = h & (HKV_ - 1);

    const int tid = threadIdx.x;
    const int tx = tid & 15;
    const int ty = tid >> 4;
    const float scale = 0.08838834764831843f;  // 1/sqrt(128)

    for (int i = tid; i < BR_ * HDv_ / 4; i += 256) {
        const int r = i >> 5;
        const int c = (i & 31) << 2;
        const float4 v4 = *(const float4*)(
            q + (size_t)(b * Tt_ + qt * BR_ + r) * Cc_ + h * HDv_ + c);
        float4 s4;
        s4.x = v4.x * scale; s4.y = v4.y * scale;
        s4.z = v4.z * scale; s4.w = v4.w * scale;
        *(float4*)(Qs + r * LDK_ + c) = s4;
    }

    float acc[4][8];
    float m_[4], l_[4];
#pragma unroll
    for (int r = 0; r < 4; r++) {
        m_[r] = -INFINITY; l_[r] = 0.f;
#pragma unroll
        for (int j = 0; j < 8; j++) acc[r][j] = 0.f;
    }

    for (int kt = 0; kt <= qt; ++kt) {
        __syncthreads();

        for (int i = tid; i < BC_ * HDv_ / 4; i += 256) {
            const int r = i >> 5;
            const int c = (i & 31) << 2;
            const float* base =
                kv + (size_t)(b * Tt_ + kt * BC_ + r) * KVN_ + kvh * HDv_ + c;
            *(float4*)(Ks + r * LDK_ + c) = *(const float4*)(base);
            *(float4*)(Vs + r * LDK_ + c) = *(const float4*)(base + 512);
        }
        __syncthreads();

        float s[4][4];
#pragma unroll
        for (int r = 0; r < 4; r++)
#pragma unroll
            for (int c = 0; c < 4; c++) s[r][c] = 0.f;

#pragma unroll 4
        for (int d = 0; d < HDv_; d++) {
            float qr[4], kr[4];
#pragma unroll
            for (int rr = 0; rr < 4; rr++) qr[rr] = Qs[(ty * 4 + rr) * LDK_ + d];
#pragma unroll
            for (int cc = 0; cc < 4; cc++) kr[cc] = Ks[(cc * 16 + tx) * LDK_ + d];
#pragma unroll
            for (int rr = 0; rr < 4; rr++)
#pragma unroll
                for (int cc = 0; cc < 4; cc++)
                    s[rr][cc] = fmaf(qr[rr], kr[cc], s[rr][cc]);
        }

        if (kt == qt) {
#pragma unroll
            for (int rr = 0; rr < 4; rr++)
#pragma unroll
                for (int cc = 0; cc < 4; cc++)
                    if ((cc * 16 + tx) > (ty * 4 + rr)) s[rr][cc] = -1e30f;
        }

#pragma unroll
        for (int rr = 0; rr < 4; rr++) {
            float rm = s[rr][0];
#pragma unroll
            for (int cc = 1; cc < 4; cc++) rm = fmaxf(rm, s[rr][cc]);
#pragma unroll
            for (int off = 8; off >= 1; off >>= 1)
                rm = fmaxf(rm, __shfl_xor_sync(0xffffffffu, rm, off));

            const float newm = fmaxf(m_[rr], rm);
            float p[4], rs = 0.f;
#pragma unroll
            for (int cc = 0; cc < 4; cc++) {
                p[cc] = __expf(s[rr][cc] - newm);
                rs += p[cc];
            }
#pragma unroll
            for (int off = 8; off >= 1; off >>= 1)
                rs += __shfl_xor_sync(0xffffffffu, rs, off);

            const float alpha = __expf(m_[rr] - newm);
            l_[rr] = l_[rr] * alpha + rs;
            m_[rr] = newm;
#pragma unroll
            for (int j = 0; j < 8; j++) acc[rr][j] *= alpha;
#pragma unroll
            for (int cc = 0; cc < 4; cc++)
                Ps[(ty * 4 + rr) * LDP_ + cc * 16 + tx] = p[cc];
        }
        __syncthreads();

#pragma unroll 4
        for (int k = 0; k < BC_; k++) {
            float pr[4], vr[8];
#pragma unroll
            for (int rr = 0; rr < 4; rr++) pr[rr] = Ps[(ty * 4 + rr) * LDP_ + k];
#pragma unroll
            for (int j = 0; j < 8; j++) vr[j] = Vs[k * LDK_ + j * 16 + tx];
#pragma unroll
            for (int rr = 0; rr < 4; rr++)
#pragma unroll
                for (int j = 0; j < 8; j++)
                    acc[rr][j] = fmaf(pr[rr], vr[j], acc[rr][j]);
        }
    }

#pragma unroll
    for (int rr = 0; rr < 4; rr++) {
        const float inv = 1.f / l_[rr];
        const int row = qt * BR_ + ty * 4 + rr;
        float* dst = y + (size_t)(b * Tt_ + row) * Cc_ + h * HDv_;
#pragma unroll
        for (int j = 0; j < 8; j++) dst[j * 16 + tx] = acc[rr][j] * inv;
    }
}

// ---------------------------------------------------------------------------
// Launch
// ---------------------------------------------------------------------------
extern "C" void kernel_launch(void* const* d_in, const int* in_sizes, int n_in,
                              void* d_out, int out_size)
{
    const float* x   = (const float*)d_in[0];
    const float* Wkv = (const float*)d_in[1];
    const float* bkv = (const float*)d_in[2];
    const float* Wq  = (const float*)d_in[3];
    const float* bq  = (const float*)d_in[4];
    const float* Wp  = (const float*)d_in[5];
    const float* bp  = (const float*)d_in[6];
    float* out = (float*)d_out;

    float *qp, *kvp, *yp;
    cudaGetSymbolAddress((void**)&qp,  g_q);
    cudaGetSymbolAddress((void**)&kvp, g_kv);
    cudaGetSymbolAddress((void**)&yp,  g_y);

    cudaFuncSetAttribute(flash_kernel,
                         cudaFuncAttributeMaxDynamicSharedMemorySize,
                         FLASH_SMEM);

    // q = x @ Wq + bq        (4096 x 2048 x 2048)
    sgemm_bias<<<dim3(Cc_ / GBN, Mm_ / GBM), 256>>>(Mm_, Cc_, Cc_, x, Wq, bq, qp);
    // kv = x @ Wkv + bkv     (4096 x 1024 x 2048)
    sgemm_bias<<<dim3(KVN_ / GBN, Mm_ / GBM), 256>>>(Mm_, KVN_, Cc_, x, Wkv, bkv, kvp);
    // y = causal GQA attention
    flash_kernel<<<dim3(Tt_ / BR_, Hh_, Bb_), 256, FLASH_SMEM>>>(qp, kvp, yp);
    // out = y @ Wp + bp      (4096 x 2048 x 2048)
    sgemm_bias<<<dim3(Cc_ / GBN, Mm_ / GBM), 256>>>(Mm_, Cc_, Cc_, yp, Wp, bp, out);
}

// round 3
// speedup vs baseline: 1.1084x; 1.0518x over previous
#include <cuda_runtime.h>
#include <math.h>

// Problem constants
#define Bb_ 2
#define Tt_ 2048
#define Cc_ 2048
#define Hh_ 16
#define HKV_ 4
#define HDv_ 128
#define Mm_ (Bb_ * Tt_)
#define KVN_ 1024

// Scratch (device globals; no allocation allowed)
__device__ float g_q[(size_t)Mm_ * Cc_];
__device__ float g_kv[(size_t)Mm_ * KVN_];
__device__ float g_y[(size_t)Mm_ * Cc_];

// ---- packed f32x2 helpers (FFMA2 path; Blackwell-only) ----------------------
typedef unsigned long long u64t;

__device__ __forceinline__ u64t pk2(float lo, float hi) {
    u64t r;
    asm("mov.b64 %0, {%1, %2};" : "=l"(r) : "f"(lo), "f"(hi));
    return r;
}
__device__ __forceinline__ void fma2(u64t& d, u64t a, u64t b) {
    asm("fma.rn.f32x2 %0, %1, %2, %0;" : "+l"(d) : "l"(a), "l"(b));
}
__device__ __forceinline__ void mul2(u64t& d, u64t a, u64t b) {
    asm("mul.rn.f32x2 %0, %1, %2;" : "=l"(d) : "l"(a), "l"(b));
}
__device__ __forceinline__ float2 upk(u64t v) {
    float2 f;
    asm("mov.b64 {%0, %1}, %2;" : "=f"(f.x), "=f"(f.y) : "l"(v));
    return f;
}

// ---------------------------------------------------------------------------
// SGEMM: C = A@B + bias, row-major fp32. 128x128x16 tile, double-buffered,
// 8x8 microtile computed as 8x(4 f32x2) packed FMAs. 256 threads.
// ---------------------------------------------------------------------------
#define GBM 128
#define GBN 128
#define GBK 16

__global__ void __launch_bounds__(256, 2)
sgemm_bias(int M, int N, int K,
           const float* __restrict__ A, const float* __restrict__ B,
           const float* __restrict__ bias, float* __restrict__ C)
{
    __shared__ float As[2][GBK][GBM];
    __shared__ float Bs[2][GBK][GBN];

    const int tid  = threadIdx.x;
    const int tcol = tid & 15;
    const int trow = tid >> 4;

    const int aRow = tid >> 2;
    const int aCol = (tid & 3) << 2;
    const int bRow = tid >> 5;
    const int bCol = (tid & 31) << 2;

    const float* Ab   = A + (size_t)blockIdx.y * GBM * K;
    const float* Bblk = B + blockIdx.x * GBN;

    u64t acc2[8][4];
#pragma unroll
    for (int i = 0; i < 8; i++)
#pragma unroll
        for (int j = 0; j < 4; j++) acc2[i][j] = 0ull;

    const int nt = K / GBK;

    {
        float4 a0 = *(const float4*)(Ab + (size_t)aRow * K + aCol);
        float4 a1 = *(const float4*)(Ab + (size_t)(aRow + 64) * K + aCol);
        float4 b0 = *(const float4*)(Bblk + (size_t)bRow * N + bCol);
        float4 b1 = *(const float4*)(Bblk + (size_t)(bRow + 8) * N + bCol);
        As[0][aCol + 0][aRow] = a0.x;
        As[0][aCol + 1][aRow] = a0.y;
        As[0][aCol + 2][aRow] = a0.z;
        As[0][aCol + 3][aRow] = a0.w;
        As[0][aCol + 0][aRow + 64] = a1.x;
        As[0][aCol + 1][aRow + 64] = a1.y;
        As[0][aCol + 2][aRow + 64] = a1.z;
        As[0][aCol + 3][aRow + 64] = a1.w;
        *(float4*)(&Bs[0][bRow][bCol])     = b0;
        *(float4*)(&Bs[0][bRow + 8][bCol]) = b1;
    }
    __syncthreads();

    for (int t = 0; t < nt; ++t) {
        const int cur = t & 1;
        float4 a0, a1, b0, b1;
        const bool more = (t + 1 < nt);
        if (more) {
            const int k0 = (t + 1) * GBK;
            a0 = *(const float4*)(Ab + (size_t)aRow * K + k0 + aCol);
            a1 = *(const float4*)(Ab + (size_t)(aRow + 64) * K + k0 + aCol);
            b0 = *(const float4*)(Bblk + (size_t)(k0 + bRow) * N + bCol);
            b1 = *(const float4*)(Bblk + (size_t)(k0 + bRow + 8) * N + bCol);
        }

#pragma unroll
        for (int kk = 0; kk < GBK; kk++) {
            float ra[8], rb[8];
            *(float4*)(&ra[0]) = *(const float4*)(&As[cur][kk][trow * 8]);
            *(float4*)(&ra[4]) = *(const float4*)(&As[cur][kk][trow * 8 + 4]);
            *(float4*)(&rb[0]) = *(const float4*)(&Bs[cur][kk][tcol * 8]);
            *(float4*)(&rb[4]) = *(const float4*)(&Bs[cur][kk][tcol * 8 + 4]);
            u64t rbp[4];
#pragma unroll
            for (int jp = 0; jp < 4; jp++) rbp[jp] = pk2(rb[2 * jp], rb[2 * jp + 1]);
#pragma unroll
            for (int i = 0; i < 8; i++) {
                const u64t aa = pk2(ra[i], ra[i]);
#pragma unroll
                for (int jp = 0; jp < 4; jp++) fma2(acc2[i][jp], aa, rbp[jp]);
            }
        }

        if (more) {
            const int nxt = cur ^ 1;
            As[nxt][aCol + 0][aRow] = a0.x;
            As[nxt][aCol + 1][aRow] = a0.y;
            As[nxt][aCol + 2][aRow] = a0.z;
            As[nxt][aCol + 3][aRow] = a0.w;
            As[nxt][aCol + 0][aRow + 64] = a1.x;
            As[nxt][aCol + 1][aRow + 64] = a1.y;
            As[nxt][aCol + 2][aRow + 64] = a1.z;
            As[nxt][aCol + 3][aRow + 64] = a1.w;
            *(float4*)(&Bs[nxt][bRow][bCol])     = b0;
            *(float4*)(&Bs[nxt][bRow + 8][bCol]) = b1;
            __syncthreads();
        }
    }

#pragma unroll
    for (int i = 0; i < 8; i++) {
        const int row = blockIdx.y * GBM + trow * 8 + i;
#pragma unroll
        for (int jp = 0; jp < 4; jp += 2) {
            const int col = blockIdx.x * GBN + tcol * 8 + jp * 2;
            const float2 lo = upk(acc2[i][jp]);
            const float2 hi = upk(acc2[i][jp + 1]);
            float4 o;
            o.x = lo.x + bias[col + 0];
            o.y = lo.y + bias[col + 1];
            o.z = hi.x + bias[col + 2];
            o.w = hi.y + bias[col + 3];
            *(float4*)(C + (size_t)row * N + col) = o;
        }
    }
}

// ---------------------------------------------------------------------------
// Flash attention (fp32, causal, GQA), f32x2 inner loops.
// Block: 256 threads as 16x16. Br=Bc=64. S: 4x4/thread, O: 4x8/thread.
// ---------------------------------------------------------------------------
#define BR_ 64
#define BC_ 64
#define LDK_ 132
#define LDP_ 65

#define FLASH_SMEM ((3 * BR_ * LDK_ + BR_ * LDP_) * (int)sizeof(float))

__global__ void __launch_bounds__(256, 1)
flash_kernel(const float* __restrict__ q, const float* __restrict__ kv,
             float* __restrict__ y)
{
    extern __shared__ float sm[];
    float* Qs = sm;
    float* Ks = Qs + BR_ * LDK_;
    float* Vs = Ks + BC_ * LDK_;
    float* Ps = Vs + BC_ * LDK_;

    const int qt = blockIdx.x;
    const int h  = blockIdx.y;
    const int b  = blockIdx.z;
    const int kvh = h & (HKV_ - 1);

    const int tid = threadIdx.x;
    const int tx = tid & 15;
    const int ty = tid >> 4;
    const float scale = 0.08838834764831843f;  // 1/sqrt(128)

    for (int i = tid; i < BR_ * HDv_ / 4; i += 256) {
        const int r = i >> 5;
        const int c = (i & 31) << 2;
        const float4 v4 = *(const float4*)(
            q + (size_t)(b * Tt_ + qt * BR_ + r) * Cc_ + h * HDv_ + c);
        float4 s4;
        s4.x = v4.x * scale; s4.y = v4.y * scale;
        s4.z = v4.z * scale; s4.w = v4.w * scale;
        *(float4*)(Qs + r * LDK_ + c) = s4;
    }

    u64t acc2[4][4];   // O accumulator, cols (2jp)*16+tx, (2jp+1)*16+tx
    float m_[4], l_[4];
#pragma unroll
    for (int r = 0; r < 4; r++) {
        m_[r] = -INFINITY; l_[r] = 0.f;
#pragma unroll
        for (int j = 0; j < 4; j++) acc2[r][j] = 0ull;
    }

    for (int kt = 0; kt <= qt; ++kt) {
        __syncthreads();

        for (int i = tid; i < BC_ * HDv_ / 4; i += 256) {
            const int r = i >> 5;
            const int c = (i & 31) << 2;
            const float* base =
                kv + (size_t)(b * Tt_ + kt * BC_ + r) * KVN_ + kvh * HDv_ + c;
            *(float4*)(Ks + r * LDK_ + c) = *(const float4*)(base);
            *(float4*)(Vs + r * LDK_ + c) = *(const float4*)(base + 512);
        }
        __syncthreads();

        // ---- S = Q K^T with d-pair f32x2 ----
        u64t s2[4][4];
#pragma unroll
        for (int r = 0; r < 4; r++)
#pragma unroll
            for (int c = 0; c < 4; c++) s2[r][c] = 0ull;

#pragma unroll 4
        for (int d = 0; d < HDv_; d += 2) {
            u64t qp[4], kp[4];
#pragma unroll
            for (int rr = 0; rr < 4; rr++)
                qp[rr] = *(const u64t*)(Qs + (ty * 4 + rr) * LDK_ + d);
#pragma unroll
            for (int cc = 0; cc < 4; cc++)
                kp[cc] = *(const u64t*)(Ks + (cc * 16 + tx) * LDK_ + d);
#pragma unroll
            for (int rr = 0; rr < 4; rr++)
#pragma unroll
                for (int cc = 0; cc < 4; cc++)
                    fma2(s2[rr][cc], qp[rr], kp[cc]);
        }

        float s[4][4];
#pragma unroll
        for (int rr = 0; rr < 4; rr++)
#pragma unroll
            for (int cc = 0; cc < 4; cc++) {
                const float2 f = upk(s2[rr][cc]);
                s[rr][cc] = f.x + f.y;
            }

        if (kt == qt) {
#pragma unroll
            for (int rr = 0; rr < 4; rr++)
#pragma unroll
                for (int cc = 0; cc < 4; cc++)
                    if ((cc * 16 + tx) > (ty * 4 + rr)) s[rr][cc] = -1e30f;
        }

        // ---- online softmax ----
#pragma unroll
        for (int rr = 0; rr < 4; rr++) {
            float rm = s[rr][0];
#pragma unroll
            for (int cc = 1; cc < 4; cc++) rm = fmaxf(rm, s[rr][cc]);
#pragma unroll
            for (int off = 8; off >= 1; off >>= 1)
                rm = fmaxf(rm, __shfl_xor_sync(0xffffffffu, rm, off));

            const float newm = fmaxf(m_[rr], rm);
            float p[4], rs = 0.f;
#pragma unroll
            for (int cc = 0; cc < 4; cc++) {
                p[cc] = __expf(s[rr][cc] - newm);
                rs += p[cc];
            }
#pragma unroll
            for (int off = 8; off >= 1; off >>= 1)
                rs += __shfl_xor_sync(0xffffffffu, rs, off);

            const float alpha = __expf(m_[rr] - newm);
            l_[rr] = l_[rr] * alpha + rs;
            m_[rr] = newm;
            const u64t ap = pk2(alpha, alpha);
#pragma unroll
            for (int jp = 0; jp < 4; jp++) mul2(acc2[rr][jp], acc2[rr][jp], ap);
#pragma unroll
            for (int cc = 0; cc < 4; cc++)
                Ps[(ty * 4 + rr) * LDP_ + cc * 16 + tx] = p[cc];
        }
        __syncthreads();

        // ---- O += P V with j-pair f32x2 ----
#pragma unroll 4
        for (int k = 0; k < BC_; k++) {
            float vr[8];
#pragma unroll
            for (int j = 0; j < 8; j++) vr[j] = Vs[k * LDK_ + j * 16 + tx];
            u64t vp[4];
#pragma unroll
            for (int jp = 0; jp < 4; jp++) vp[jp] = pk2(vr[2 * jp], vr[2 * jp + 1]);
#pragma unroll
            for (int rr = 0; rr < 4; rr++) {
                const float pv = Ps[(ty * 4 + rr) * LDP_ + k];
                const u64t pp = pk2(pv, pv);
#pragma unroll
                for (int jp = 0; jp < 4; jp++) fma2(acc2[rr][jp], pp, vp[jp]);
            }
        }
    }

    // ---- normalize + store ----
#pragma unroll
    for (int rr = 0; rr < 4; rr++) {
        const float inv = 1.f / l_[rr];
        const int row = qt * BR_ + ty * 4 + rr;
        float* dst = y + (size_t)(b * Tt_ + row) * Cc_ + h * HDv_;
#pragma unroll
        for (int jp = 0; jp < 4; jp++) {
            const float2 f = upk(acc2[rr][jp]);
            dst[(2 * jp) * 16 + tx]     = f.x * inv;
            dst[(2 * jp + 1) * 16 + tx] = f.y * inv;
        }
    }
}

// ---------------------------------------------------------------------------
extern "C" void kernel_launch(void* const* d_in, const int* in_sizes, int n_in,
                              void* d_out, int out_size)
{
    const float* x   = (const float*)d_in[0];
    const float* Wkv = (const float*)d_in[1];
    const float* bkv = (const float*)d_in[2];
    const float* Wq  = (const float*)d_in[3];
    const float* bq  = (const float*)d_in[4];
    const float* Wp  = (const float*)d_in[5];
    const float* bp  = (const float*)d_in[6];
    float* out = (float*)d_out;

    float *qp, *kvp, *yp;
    cudaGetSymbolAddress((void**)&qp,  g_q);
    cudaGetSymbolAddress((void**)&kvp, g_kv);
    cudaGetSymbolAddress((void**)&yp,  g_y);

    cudaFuncSetAttribute(flash_kernel,
                         cudaFuncAttributeMaxDynamicSharedMemorySize,
                         FLASH_SMEM);

    sgemm_bias<<<dim3(Cc_ / GBN, Mm_ / GBM), 256>>>(Mm_, Cc_, Cc_, x, Wq, bq, qp);
    sgemm_bias<<<dim3(KVN_ / GBN, Mm_ / GBM), 256>>>(Mm_, KVN_, Cc_, x, Wkv, bkv, kvp);
    flash_kernel<<<dim3(Tt_ / BR_, Hh_, Bb_), 256, FLASH_SMEM>>>(qp, kvp, yp);
    sgemm_bias<<<dim3(Cc_ / GBN, Mm_ / GBM), 256>>>(Mm_, Cc_, Cc_, yp, Wp, bp, out);
}

// round 4
// speedup vs baseline: 1.7303x; 1.5611x over previous
#include <cuda_runtime.h>
#include <math.h>
#include <stdint.h>

// Problem constants
#define Bb_ 2
#define Tt_ 2048
#define Cc_ 2048
#define Hh_ 16
#define HKV_ 4
#define HDv_ 128
#define Mm_ (Bb_ * Tt_)
#define KVN_ 1024

// Scratch (device globals; no allocation allowed)
__device__ float g_q[(size_t)Mm_ * Cc_];
__device__ float g_kv[(size_t)Mm_ * KVN_];
__device__ float g_y[(size_t)Mm_ * Cc_];

// ---- helpers ----------------------------------------------------------------
typedef unsigned long long u64t;

__device__ __forceinline__ u64t pk2(float lo, float hi) {
    u64t r;
    asm("mov.b64 %0, {%1, %2};" : "=l"(r) : "f"(lo), "f"(hi));
    return r;
}
__device__ __forceinline__ void fma2(u64t& d, u64t a, u64t b) {
    asm("fma.rn.f32x2 %0, %1, %2, %0;" : "+l"(d) : "l"(a), "l"(b));
}
__device__ __forceinline__ void mul2(u64t& d, u64t a, u64t b) {
    asm("mul.rn.f32x2 %0, %1, %2;" : "=l"(d) : "l"(a), "l"(b));
}
__device__ __forceinline__ float2 upk(u64t v) {
    float2 f;
    asm("mov.b64 {%0, %1}, %2;" : "=f"(f.x), "=f"(f.y) : "l"(v));
    return f;
}
__device__ __forceinline__ uint32_t to_tf32(float f) {
    uint32_t r;
    asm("cvt.rna.tf32.f32 %0, %1;" : "=r"(r) : "f"(f));
    return r;
}
__device__ __forceinline__ void mma_tf32(float (&d)[4],
                                         const uint32_t (&a)[4],
                                         const uint32_t (&b)[2]) {
    asm volatile(
        "mma.sync.aligned.m16n8k8.row.col.f32.tf32.tf32.f32 "
        "{%0,%1,%2,%3}, {%4,%5,%6,%7}, {%8,%9}, {%0,%1,%2,%3};\n"
        : "+f"(d[0]), "+f"(d[1]), "+f"(d[2]), "+f"(d[3])
        : "r"(a[0]), "r"(a[1]), "r"(a[2]), "r"(a[3]), "r"(b[0]), "r"(b[1]));
}

// ---------------------------------------------------------------------------
// tf32 tensor-core GEMM: C[M,N] = A[M,K] @ B[K,N] + bias[N]  (row-major fp32)
// 128x128 block, BK=16, double-buffered, 8 warps each computing 64x32 via
// m16n8k8 tf32 mma.sync. cvt.rna on the smem-store path; fp32 accumulate.
// ---------------------------------------------------------------------------
#define TBK 16
#define LDA_S 20    // As row stride (words): banks (4g+tg) -> conflict-free
#define LDB_S 132   // Bs row stride (words): banks (4tg+g) -> conflict-free

__global__ void __launch_bounds__(256, 2)
tgemm_bias(int M, int N, int K,
           const float* __restrict__ A, const float* __restrict__ B,
           const float* __restrict__ bias, float* __restrict__ C)
{
    __shared__ uint32_t As[2][128][LDA_S];   // [m][k]
    __shared__ uint32_t Bs[2][TBK][LDB_S];   // [k][n]

    const int tid  = threadIdx.x;
    const int wid  = tid >> 5;
    const int lane = tid & 31;
    const int g    = lane >> 2;     // groupID 0..7
    const int tg   = lane & 3;      // thread-in-group 0..3
    const int wm   = wid & 1;       // 2 warps in M
    const int wn   = wid >> 1;      // 4 warps in N

    // global->smem mapping
    const int aRow = tid >> 1;          // 0..127
    const int aK   = (tid & 1) << 3;    // 0 or 8
    const int bK   = tid >> 4;          // 0..15
    const int bN   = (tid & 15) << 3;   // 0..120

    const float* Ab   = A + (size_t)blockIdx.y * 128 * K;
    const float* Bblk = B + blockIdx.x * 128;

    float acc[4][4][4];
#pragma unroll
    for (int mi = 0; mi < 4; mi++)
#pragma unroll
        for (int ni = 0; ni < 4; ni++)
#pragma unroll
            for (int r = 0; r < 4; r++) acc[mi][ni][r] = 0.f;

    const int nt = K / TBK;

    // ---- prologue: fill buffer 0 ----
    {
        float4 a0 = *(const float4*)(Ab + (size_t)aRow * K + aK);
        float4 a1 = *(const float4*)(Ab + (size_t)aRow * K + aK + 4);
        float4 b0 = *(const float4*)(Bblk + (size_t)bK * N + bN);
        float4 b1 = *(const float4*)(Bblk + (size_t)bK * N + bN + 4);
        uint4 ca0 = {to_tf32(a0.x), to_tf32(a0.y), to_tf32(a0.z), to_tf32(a0.w)};
        uint4 ca1 = {to_tf32(a1.x), to_tf32(a1.y), to_tf32(a1.z), to_tf32(a1.w)};
        uint4 cb0 = {to_tf32(b0.x), to_tf32(b0.y), to_tf32(b0.z), to_tf32(b0.w)};
        uint4 cb1 = {to_tf32(b1.x), to_tf32(b1.y), to_tf32(b1.z), to_tf32(b1.w)};
        *(uint4*)(&As[0][aRow][aK])     = ca0;
        *(uint4*)(&As[0][aRow][aK + 4]) = ca1;
        *(uint4*)(&Bs[0][bK][bN])       = cb0;
        *(uint4*)(&Bs[0][bK][bN + 4])   = cb1;
    }
    __syncthreads();

    for (int t = 0; t < nt; ++t) {
        const int cur = t & 1;
        float4 a0, a1, b0, b1;
        const bool more = (t + 1 < nt);
        if (more) {
            const int k0 = (t + 1) * TBK;
            a0 = *(const float4*)(Ab + (size_t)aRow * K + k0 + aK);
            a1 = *(const float4*)(Ab + (size_t)aRow * K + k0 + aK + 4);
            b0 = *(const float4*)(Bblk + (size_t)(k0 + bK) * N + bN);
            b1 = *(const float4*)(Bblk + (size_t)(k0 + bK) * N + bN + 4);
        }

        // ---- compute on cur: 2 k-steps x 16 mma ----
#pragma unroll
        for (int ks = 0; ks < 2; ks++) {
            const int k0f = ks * 8;
            uint32_t afr[4][4];
#pragma unroll
            for (int mi = 0; mi < 4; mi++) {
                const int r0 = wm * 64 + mi * 16 + g;
                afr[mi][0] = As[cur][r0][k0f + tg];
                afr[mi][1] = As[cur][r0 + 8][k0f + tg];
                afr[mi][2] = As[cur][r0][k0f + tg + 4];
                afr[mi][3] = As[cur][r0 + 8][k0f + tg + 4];
            }
            uint32_t bfr[4][2];
#pragma unroll
            for (int ni = 0; ni < 4; ni++) {
                const int c0 = wn * 32 + ni * 8 + g;
                bfr[ni][0] = Bs[cur][k0f + tg][c0];
                bfr[ni][1] = Bs[cur][k0f + tg + 4][c0];
            }
#pragma unroll
            for (int mi = 0; mi < 4; mi++)
#pragma unroll
                for (int ni = 0; ni < 4; ni++)
                    mma_tf32(acc[mi][ni], afr[mi], bfr[ni]);
        }

        if (more) {
            const int nxt = cur ^ 1;
            uint4 ca0 = {to_tf32(a0.x), to_tf32(a0.y), to_tf32(a0.z), to_tf32(a0.w)};
            uint4 ca1 = {to_tf32(a1.x), to_tf32(a1.y), to_tf32(a1.z), to_tf32(a1.w)};
            uint4 cb0 = {to_tf32(b0.x), to_tf32(b0.y), to_tf32(b0.z), to_tf32(b0.w)};
            uint4 cb1 = {to_tf32(b1.x), to_tf32(b1.y), to_tf32(b1.z), to_tf32(b1.w)};
            *(uint4*)(&As[nxt][aRow][aK])     = ca0;
            *(uint4*)(&As[nxt][aRow][aK + 4]) = ca1;
            *(uint4*)(&Bs[nxt][bK][bN])       = cb0;
            *(uint4*)(&Bs[nxt][bK][bN + 4])   = cb1;
            __syncthreads();
        }
    }

    // ---- epilogue: fragment layout -> global, fused bias ----
#pragma unroll
    for (int mi = 0; mi < 4; mi++) {
        const int r0 = blockIdx.y * 128 + wm * 64 + mi * 16 + g;
#pragma unroll
        for (int ni = 0; ni < 4; ni++) {
            const int c0 = blockIdx.x * 128 + wn * 32 + ni * 8 + tg * 2;
            const float bx0 = bias[c0], bx1 = bias[c0 + 1];
            float2 v0 = {acc[mi][ni][0] + bx0, acc[mi][ni][1] + bx1};
            float2 v1 = {acc[mi][ni][2] + bx0, acc[mi][ni][3] + bx1};
            *(float2*)(C + (size_t)r0 * N + c0)       = v0;
            *(float2*)(C + (size_t)(r0 + 8) * N + c0) = v1;
        }
    }
}

// ---------------------------------------------------------------------------
// Flash attention (fp32, causal, GQA), f32x2 inner loops. Unchanged from R3.
// ---------------------------------------------------------------------------
#define BR_ 64
#define BC_ 64
#define LDK_ 132
#define LDP_ 65

#define FLASH_SMEM ((3 * BR_ * LDK_ + BR_ * LDP_) * (int)sizeof(float))

__global__ void __launch_bounds__(256, 1)
flash_kernel(const float* __restrict__ q, const float* __restrict__ kv,
             float* __restrict__ y)
{
    extern __shared__ float sm[];
    float* Qs = sm;
    float* Ks = Qs + BR_ * LDK_;
    float* Vs = Ks + BC_ * LDK_;
    float* Ps = Vs + BC_ * LDK_;

    const int qt = blockIdx.x;
    const int h  = blockIdx.y;
    const int b  = blockIdx.z;
    const int kvh = h & (HKV_ - 1);

    const int tid = threadIdx.x;
    const int tx = tid & 15;
    const int ty = tid >> 4;
    const float scale = 0.08838834764831843f;

    for (int i = tid; i < BR_ * HDv_ / 4; i += 256) {
        const int r = i >> 5;
        const int c = (i & 31) << 2;
        const float4 v4 = *(const float4*)(
            q + (size_t)(b * Tt_ + qt * BR_ + r) * Cc_ + h * HDv_ + c);
        float4 s4;
        s4.x = v4.x * scale; s4.y = v4.y * scale;
        s4.z = v4.z * scale; s4.w = v4.w * scale;
        *(float4*)(Qs + r * LDK_ + c) = s4;
    }

    u64t acc2[4][4];
    float m_[4], l_[4];
#pragma unroll
    for (int r = 0; r < 4; r++) {
        m_[r] = -INFINITY; l_[r] = 0.f;
#pragma unroll
        for (int j = 0; j < 4; j++) acc2[r][j] = 0ull;
    }

    for (int kt = 0; kt <= qt; ++kt) {
        __syncthreads();

        for (int i = tid; i < BC_ * HDv_ / 4; i += 256) {
            const int r = i >> 5;
            const int c = (i & 31) << 2;
            const float* base =
                kv + (size_t)(b * Tt_ + kt * BC_ + r) * KVN_ + kvh * HDv_ + c;
            *(float4*)(Ks + r * LDK_ + c) = *(const float4*)(base);
            *(float4*)(Vs + r * LDK_ + c) = *(const float4*)(base + 512);
        }
        __syncthreads();

        u64t s2[4][4];
#pragma unroll
        for (int r = 0; r < 4; r++)
#pragma unroll
            for (int c = 0; c < 4; c++) s2[r][c] = 0ull;

#pragma unroll 4
        for (int d = 0; d < HDv_; d += 2) {
            u64t qp[4], kp[4];
#pragma unroll
            for (int rr = 0; rr < 4; rr++)
                qp[rr] = *(const u64t*)(Qs + (ty * 4 + rr) * LDK_ + d);
#pragma unroll
            for (int cc = 0; cc < 4; cc++)
                kp[cc] = *(const u64t*)(Ks + (cc * 16 + tx) * LDK_ + d);
#pragma unroll
            for (int rr = 0; rr < 4; rr++)
#pragma unroll
                for (int cc = 0; cc < 4; cc++)
                    fma2(s2[rr][cc], qp[rr], kp[cc]);
        }

        float s[4][4];
#pragma unroll
        for (int rr = 0; rr < 4; rr++)
#pragma unroll
            for (int cc = 0; cc < 4; cc++) {
                const float2 f = upk(s2[rr][cc]);
                s[rr][cc] = f.x + f.y;
            }

        if (kt == qt) {
#pragma unroll
            for (int rr = 0; rr < 4; rr++)
#pragma unroll
                for (int cc = 0; cc < 4; cc++)
                    if ((cc * 16 + tx) > (ty * 4 + rr)) s[rr][cc] = -1e30f;
        }

#pragma unroll
        for (int rr = 0; rr < 4; rr++) {
            float rm = s[rr][0];
#pragma unroll
            for (int cc = 1; cc < 4; cc++) rm = fmaxf(rm, s[rr][cc]);
#pragma unroll
            for (int off = 8; off >= 1; off >>= 1)
                rm = fmaxf(rm, __shfl_xor_sync(0xffffffffu, rm, off));

            const float newm = fmaxf(m_[rr], rm);
            float p[4], rs = 0.f;
#pragma unroll
            for (int cc = 0; cc < 4; cc++) {
                p[cc] = __expf(s[rr][cc] - newm);
                rs += p[cc];
            }
#pragma unroll
            for (int off = 8; off >= 1; off >>= 1)
                rs += __shfl_xor_sync(0xffffffffu, rs, off);

            const float alpha = __expf(m_[rr] - newm);
            l_[rr] = l_[rr] * alpha + rs;
            m_[rr] = newm;
            const u64t ap = pk2(alpha, alpha);
#pragma unroll
            for (int jp = 0; jp < 4; jp++) mul2(acc2[rr][jp], acc2[rr][jp], ap);
#pragma unroll
            for (int cc = 0; cc < 4; cc++)
                Ps[(ty * 4 + rr) * LDP_ + cc * 16 + tx] = p[cc];
        }
        __syncthreads();

#pragma unroll 4
        for (int k = 0; k < BC_; k++) {
            float vr[8];
#pragma unroll
            for (int j = 0; j < 8; j++) vr[j] = Vs[k * LDK_ + j * 16 + tx];
            u64t vp[4];
#pragma unroll
            for (int jp = 0; jp < 4; jp++) vp[jp] = pk2(vr[2 * jp], vr[2 * jp + 1]);
#pragma unroll
            for (int rr = 0; rr < 4; rr++) {
                const float pv = Ps[(ty * 4 + rr) * LDP_ + k];
                const u64t pp = pk2(pv, pv);
#pragma unroll
                for (int jp = 0; jp < 4; jp++) fma2(acc2[rr][jp], pp, vp[jp]);
            }
        }
    }

#pragma unroll
    for (int rr = 0; rr < 4; rr++) {
        const float inv = 1.f / l_[rr];
        const int row = qt * BR_ + ty * 4 + rr;
        float* dst = y + (size_t)(b * Tt_ + row) * Cc_ + h * HDv_;
#pragma unroll
        for (int jp = 0; jp < 4; jp++) {
            const float2 f = upk(acc2[rr][jp]);
            dst[(2 * jp) * 16 + tx]     = f.x * inv;
            dst[(2 * jp + 1) * 16 + tx] = f.y * inv;
        }
    }
}

// ---------------------------------------------------------------------------
extern "C" void kernel_launch(void* const* d_in, const int* in_sizes, int n_in,
                              void* d_out, int out_size)
{
    const float* x   = (const float*)d_in[0];
    const float* Wkv = (const float*)d_in[1];
    const float* bkv = (const float*)d_in[2];
    const float* Wq  = (const float*)d_in[3];
    const float* bq  = (const float*)d_in[4];
    const float* Wp  = (const float*)d_in[5];
    const float* bp  = (const float*)d_in[6];
    float* out = (float*)d_out;

    float *qp, *kvp, *yp;
    cudaGetSymbolAddress((void**)&qp,  g_q);
    cudaGetSymbolAddress((void**)&kvp, g_kv);
    cudaGetSymbolAddress((void**)&yp,  g_y);

    cudaFuncSetAttribute(flash_kernel,
                         cudaFuncAttributeMaxDynamicSharedMemorySize,
                         FLASH_SMEM);

    // q = x @ Wq + bq        (4096 x 2048 x 2048)
    tgemm_bias<<<dim3(Cc_ / 128, Mm_ / 128), 256>>>(Mm_, Cc_, Cc_, x, Wq, bq, qp);
    // kv = x @ Wkv + bkv     (4096 x 1024 x 2048)
    tgemm_bias<<<dim3(KVN_ / 128, Mm_ / 128), 256>>>(Mm_, KVN_, Cc_, x, Wkv, bkv, kvp);
    // attention
    flash_kernel<<<dim3(Tt_ / BR_, Hh_, Bb_), 256, FLASH_SMEM>>>(qp, kvp, yp);
    // out = y @ Wp + bp      (4096 x 2048 x 2048)
    tgemm_bias<<<dim3(Cc_ / 128, Mm_ / 128), 256>>>(Mm_, Cc_, Cc_, yp, Wp, bp, out);
}

// round 5
// speedup vs baseline: 2.6310x; 1.5206x over previous
#include <cuda_runtime.h>
#include <math.h>
#include <stdint.h>

// Problem constants
#define Bb_ 2
#define Tt_ 2048
#define Cc_ 2048
#define Hh_ 16
#define HKV_ 4
#define HDv_ 128
#define Mm_ (Bb_ * Tt_)
#define KVN_ 1024

// Scratch (device globals; no allocation allowed)
__device__ float g_q[(size_t)Mm_ * Cc_];
__device__ float g_kv[(size_t)Mm_ * KVN_];
__device__ float g_y[(size_t)Mm_ * Cc_];

// ---- helpers ----------------------------------------------------------------
typedef unsigned long long u64t;

__device__ __forceinline__ u64t pk2(float lo, float hi) {
    u64t r;
    asm("mov.b64 %0, {%1, %2};" : "=l"(r) : "f"(lo), "f"(hi));
    return r;
}
__device__ __forceinline__ void mul2(u64t& d, u64t a, u64t b) {
    asm("mul.rn.f32x2 %0, %1, %2;" : "=l"(d) : "l"(a), "l"(b));
}
__device__ __forceinline__ float2 upk(u64t v) {
    float2 f;
    asm("mov.b64 {%0, %1}, %2;" : "=f"(f.x), "=f"(f.y) : "l"(v));
    return f;
}
__device__ __forceinline__ uint32_t to_tf32(float f) {
    uint32_t r;
    asm("cvt.rna.tf32.f32 %0, %1;" : "=r"(r) : "f"(f));
    return r;
}
__device__ __forceinline__ void mma_tf32(float (&d)[4],
                                         const uint32_t (&a)[4],
                                         const uint32_t (&b)[2]) {
    asm volatile(
        "mma.sync.aligned.m16n8k8.row.col.f32.tf32.tf32.f32 "
        "{%0,%1,%2,%3}, {%4,%5,%6,%7}, {%8,%9}, {%0,%1,%2,%3};\n"
        : "+f"(d[0]), "+f"(d[1]), "+f"(d[2]), "+f"(d[3])
        : "r"(a[0]), "r"(a[1]), "r"(a[2]), "r"(a[3]), "r"(b[0]), "r"(b[1]));
}

// ---------------------------------------------------------------------------
// tf32 tensor-core GEMM (unchanged from R4): C = A@B + bias
// ---------------------------------------------------------------------------
#define TBK 16
#define LDA_S 20
#define LDB_S 132

__global__ void __launch_bounds__(256, 2)
tgemm_bias(int M, int N, int K,
           const float* __restrict__ A, const float* __restrict__ B,
           const float* __restrict__ bias, float* __restrict__ C)
{
    __shared__ uint32_t As[2][128][LDA_S];
    __shared__ uint32_t Bs[2][TBK][LDB_S];

    const int tid  = threadIdx.x;
    const int wid  = tid >> 5;
    const int lane = tid & 31;
    const int g    = lane >> 2;
    const int tg   = lane & 3;
    const int wm   = wid & 1;
    const int wn   = wid >> 1;

    const int aRow = tid >> 1;
    const int aK   = (tid & 1) << 3;
    const int bK   = tid >> 4;
    const int bN   = (tid & 15) << 3;

    const float* Ab   = A + (size_t)blockIdx.y * 128 * K;
    const float* Bblk = B + blockIdx.x * 128;

    float acc[4][4][4];
#pragma unroll
    for (int mi = 0; mi < 4; mi++)
#pragma unroll
        for (int ni = 0; ni < 4; ni++)
#pragma unroll
            for (int r = 0; r < 4; r++) acc[mi][ni][r] = 0.f;

    const int nt = K / TBK;

    {
        float4 a0 = *(const float4*)(Ab + (size_t)aRow * K + aK);
        float4 a1 = *(const float4*)(Ab + (size_t)aRow * K + aK + 4);
        float4 b0 = *(const float4*)(Bblk + (size_t)bK * N + bN);
        float4 b1 = *(const float4*)(Bblk + (size_t)bK * N + bN + 4);
        uint4 ca0 = {to_tf32(a0.x), to_tf32(a0.y), to_tf32(a0.z), to_tf32(a0.w)};
        uint4 ca1 = {to_tf32(a1.x), to_tf32(a1.y), to_tf32(a1.z), to_tf32(a1.w)};
        uint4 cb0 = {to_tf32(b0.x), to_tf32(b0.y), to_tf32(b0.z), to_tf32(b0.w)};
        uint4 cb1 = {to_tf32(b1.x), to_tf32(b1.y), to_tf32(b1.z), to_tf32(b1.w)};
        *(uint4*)(&As[0][aRow][aK])     = ca0;
        *(uint4*)(&As[0][aRow][aK + 4]) = ca1;
        *(uint4*)(&Bs[0][bK][bN])       = cb0;
        *(uint4*)(&Bs[0][bK][bN + 4])   = cb1;
    }
    __syncthreads();

    for (int t = 0; t < nt; ++t) {
        const int cur = t & 1;
        float4 a0, a1, b0, b1;
        const bool more = (t + 1 < nt);
        if (more) {
            const int k0 = (t + 1) * TBK;
            a0 = *(const float4*)(Ab + (size_t)aRow * K + k0 + aK);
            a1 = *(const float4*)(Ab + (size_t)aRow * K + k0 + aK + 4);
            b0 = *(const float4*)(Bblk + (size_t)(k0 + bK) * N + bN);
            b1 = *(const float4*)(Bblk + (size_t)(k0 + bK) * N + bN + 4);
        }

#pragma unroll
        for (int ks = 0; ks < 2; ks++) {
            const int k0f = ks * 8;
            uint32_t afr[4][4];
#pragma unroll
            for (int mi = 0; mi < 4; mi++) {
                const int r0 = wm * 64 + mi * 16 + g;
                afr[mi][0] = As[cur][r0][k0f + tg];
                afr[mi][1] = As[cur][r0 + 8][k0f + tg];
                afr[mi][2] = As[cur][r0][k0f + tg + 4];
                afr[mi][3] = As[cur][r0 + 8][k0f + tg + 4];
            }
            uint32_t bfr[4][2];
#pragma unroll
            for (int ni = 0; ni < 4; ni++) {
                const int c0 = wn * 32 + ni * 8 + g;
                bfr[ni][0] = Bs[cur][k0f + tg][c0];
                bfr[ni][1] = Bs[cur][k0f + tg + 4][c0];
            }
#pragma unroll
            for (int mi = 0; mi < 4; mi++)
#pragma unroll
                for (int ni = 0; ni < 4; ni++)
                    mma_tf32(acc[mi][ni], afr[mi], bfr[ni]);
        }

        if (more) {
            const int nxt = cur ^ 1;
            uint4 ca0 = {to_tf32(a0.x), to_tf32(a0.y), to_tf32(a0.z), to_tf32(a0.w)};
            uint4 ca1 = {to_tf32(a1.x), to_tf32(a1.y), to_tf32(a1.z), to_tf32(a1.w)};
            uint4 cb0 = {to_tf32(b0.x), to_tf32(b0.y), to_tf32(b0.z), to_tf32(b0.w)};
            uint4 cb1 = {to_tf32(b1.x), to_tf32(b1.y), to_tf32(b1.z), to_tf32(b1.w)};
            *(uint4*)(&As[nxt][aRow][aK])     = ca0;
            *(uint4*)(&As[nxt][aRow][aK + 4]) = ca1;
            *(uint4*)(&Bs[nxt][bK][bN])       = cb0;
            *(uint4*)(&Bs[nxt][bK][bN + 4])   = cb1;
            __syncthreads();
        }
    }

#pragma unroll
    for (int mi = 0; mi < 4; mi++) {
        const int r0 = blockIdx.y * 128 + wm * 64 + mi * 16 + g;
#pragma unroll
        for (int ni = 0; ni < 4; ni++) {
            const int c0 = blockIdx.x * 128 + wn * 32 + ni * 8 + tg * 2;
            const float bx0 = bias[c0], bx1 = bias[c0 + 1];
            float2 v0 = {acc[mi][ni][0] + bx0, acc[mi][ni][1] + bx1};
            float2 v1 = {acc[mi][ni][2] + bx0, acc[mi][ni][3] + bx1};
            *(float2*)(C + (size_t)r0 * N + c0)       = v0;
            *(float2*)(C + (size_t)(r0 + 8) * N + c0) = v1;
        }
    }
}

// ---------------------------------------------------------------------------
// Flash attention via tf32 mma.sync. Br=128/block (8 warps x 16 rows),
// Bc=64, HD=128. Q lives in registers as A-fragments; K/V in smem (stride 132);
// P round-trips through smem (stride 68) to form PV A-fragments.
// ---------------------------------------------------------------------------
#define FLDK 132            // K/V smem word stride (=4 mod 32 -> conflict-free frags)
#define FLDP 68             // P smem word stride
#define KS_OFF 0
#define VS_OFF (64 * FLDK)
#define PS_OFF (2 * 64 * FLDK)
#define FLASH_SMEM ((2 * 64 * FLDK + 128 * FLDP) * 4)

__global__ void __launch_bounds__(256, 1)
flash_mma(const float* __restrict__ q, const float* __restrict__ kv,
          float* __restrict__ y)
{
    extern __shared__ uint32_t smw[];
    uint32_t* Ks = smw + KS_OFF;   // [64][FLDK] tf32
    uint32_t* Vs = smw + VS_OFF;   // [64][FLDK] tf32
    uint32_t* Ps = smw + PS_OFF;   // [128][FLDP] tf32

    const int qt = blockIdx.x;        // q tile of 128 rows
    const int h  = blockIdx.y;
    const int b  = blockIdx.z;
    const int kvh = h & (HKV_ - 1);

    const int tid  = threadIdx.x;
    const int w    = tid >> 5;
    const int lane = tid & 31;
    const int g    = lane >> 2;
    const int tg   = lane & 3;
    const float scale = 0.08838834764831843f;  // 1/sqrt(128)

    const int rloc0 = w * 16 + g;       // local q row (frag rows rloc0, rloc0+8)
    const int grow0 = qt * 128 + rloc0; // global q row
    const int grow1 = grow0 + 8;

    // ---- load Q once into registers as tf32 A-fragments ----
    uint32_t qf[16][4];
    {
        const float* qb = q + ((size_t)(b * Tt_) + qt * 128 + w * 16) * Cc_
                            + h * HDv_;
#pragma unroll
        for (int kc = 0; kc < 16; kc++) {
            const int d0 = kc * 8 + tg;
            qf[kc][0] = to_tf32(qb[(size_t)g * Cc_ + d0] * scale);
            qf[kc][1] = to_tf32(qb[(size_t)(g + 8) * Cc_ + d0] * scale);
            qf[kc][2] = to_tf32(qb[(size_t)g * Cc_ + d0 + 4] * scale);
            qf[kc][3] = to_tf32(qb[(size_t)(g + 8) * Cc_ + d0 + 4] * scale);
        }
    }

    float of[16][4];
#pragma unroll
    for (int ni = 0; ni < 16; ni++)
#pragma unroll
        for (int r = 0; r < 4; r++) of[ni][r] = 0.f;
    float m0 = -INFINITY, m1 = -INFINITY, l0 = 0.f, l1 = 0.f;

    const int ktmax = 2 * qt + 1;
    for (int kt = 0; kt <= ktmax; ++kt) {
        __syncthreads();   // previous iter's Ks/Vs reads complete

        // ---- cooperative K/V load -> tf32 smem ----
        for (int i = tid; i < 64 * 32; i += 256) {
            const int r = i >> 5;
            const int c = (i & 31) << 2;
            const float* base =
                kv + ((size_t)(b * Tt_ + kt * 64 + r)) * KVN_ + kvh * HDv_ + c;
            const float4 kx = *(const float4*)(base);
            const float4 vx = *(const float4*)(base + 512);
            uint4 ck = {to_tf32(kx.x), to_tf32(kx.y), to_tf32(kx.z), to_tf32(kx.w)};
            uint4 cv = {to_tf32(vx.x), to_tf32(vx.y), to_tf32(vx.z), to_tf32(vx.w)};
            *(uint4*)(&Ks[r * FLDK + c]) = ck;
            *(uint4*)(&Vs[r * FLDK + c]) = cv;
        }
        __syncthreads();

        // per-warp causal activity: any col in this kv tile <= warp's max row?
        const bool act = (kt * 64) <= (qt * 128 + w * 16 + 15);
        if (!act) continue;

        // ---- S = Q K^T : 8 n-tiles x 16 k-chunks ----
        float sf[8][4];
#pragma unroll
        for (int ni = 0; ni < 8; ni++)
#pragma unroll
            for (int r = 0; r < 4; r++) sf[ni][r] = 0.f;

#pragma unroll
        for (int kc = 0; kc < 16; kc++) {
            uint32_t bfr[8][2];
#pragma unroll
            for (int ni = 0; ni < 8; ni++) {
                bfr[ni][0] = Ks[(ni * 8 + g) * FLDK + kc * 8 + tg];
                bfr[ni][1] = Ks[(ni * 8 + g) * FLDK + kc * 8 + tg + 4];
            }
#pragma unroll
            for (int ni = 0; ni < 8; ni++)
                mma_tf32(sf[ni], qf[kc], bfr[ni]);
        }

        // ---- causal mask (only tiles overlapping the diagonal) ----
        if (kt * 64 + 63 > qt * 128 + w * 16) {
            const int cb = kt * 64;
#pragma unroll
            for (int ni = 0; ni < 8; ni++) {
                const int c0 = cb + ni * 8 + tg * 2;
                if (c0 > grow0)     sf[ni][0] = -1e30f;
                if (c0 + 1 > grow0) sf[ni][1] = -1e30f;
                if (c0 > grow1)     sf[ni][2] = -1e30f;
                if (c0 + 1 > grow1) sf[ni][3] = -1e30f;
            }
        }

        // ---- online softmax (rows g and g+8), quad reductions ----
        float mx0 = -1e30f, mx1 = -1e30f;
#pragma unroll
        for (int ni = 0; ni < 8; ni++) {
            mx0 = fmaxf(mx0, fmaxf(sf[ni][0], sf[ni][1]));
            mx1 = fmaxf(mx1, fmaxf(sf[ni][2], sf[ni][3]));
        }
        mx0 = fmaxf(mx0, __shfl_xor_sync(0xffffffffu, mx0, 1));
        mx0 = fmaxf(mx0, __shfl_xor_sync(0xffffffffu, mx0, 2));
        mx1 = fmaxf(mx1, __shfl_xor_sync(0xffffffffu, mx1, 1));
        mx1 = fmaxf(mx1, __shfl_xor_sync(0xffffffffu, mx1, 2));

        const float nm0 = fmaxf(m0, mx0);
        const float nm1 = fmaxf(m1, mx1);
        float sum0 = 0.f, sum1 = 0.f;
#pragma unroll
        for (int ni = 0; ni < 8; ni++) {
            sf[ni][0] = __expf(sf[ni][0] - nm0);
            sf[ni][1] = __expf(sf[ni][1] - nm0);
            sf[ni][2] = __expf(sf[ni][2] - nm1);
            sf[ni][3] = __expf(sf[ni][3] - nm1);
            sum0 += sf[ni][0] + sf[ni][1];
            sum1 += sf[ni][2] + sf[ni][3];
        }
        sum0 += __shfl_xor_sync(0xffffffffu, sum0, 1);
        sum0 += __shfl_xor_sync(0xffffffffu, sum0, 2);
        sum1 += __shfl_xor_sync(0xffffffffu, sum1, 1);
        sum1 += __shfl_xor_sync(0xffffffffu, sum1, 2);

        const float al0 = __expf(m0 - nm0);
        const float al1 = __expf(m1 - nm1);
        m0 = nm0; m1 = nm1;
        l0 = l0 * al0 + sum0;
        l1 = l1 * al1 + sum1;

        // ---- write P (tf32) to warp-private smem strip ----
#pragma unroll
        for (int ni = 0; ni < 8; ni++) {
            uint2 p01 = {to_tf32(sf[ni][0]), to_tf32(sf[ni][1])};
            uint2 p23 = {to_tf32(sf[ni][2]), to_tf32(sf[ni][3])};
            *(uint2*)(&Ps[(w * 16 + g) * FLDP + ni * 8 + tg * 2])     = p01;
            *(uint2*)(&Ps[(w * 16 + 8 + g) * FLDP + ni * 8 + tg * 2]) = p23;
        }
        __syncwarp();

        // ---- rescale O ----
        {
            const u64t a0p = pk2(al0, al0);
            const u64t a1p = pk2(al1, al1);
#pragma unroll
            for (int ni = 0; ni < 16; ni++) {
                u64t v01 = pk2(of[ni][0], of[ni][1]);
                u64t v23 = pk2(of[ni][2], of[ni][3]);
                mul2(v01, v01, a0p);
                mul2(v23, v23, a1p);
                const float2 f01 = upk(v01), f23 = upk(v23);
                of[ni][0] = f01.x; of[ni][1] = f01.y;
                of[ni][2] = f23.x; of[ni][3] = f23.y;
            }
        }

        // ---- O += P V : 16 n-tiles x 8 k-chunks ----
#pragma unroll
        for (int kc = 0; kc < 8; kc++) {
            uint32_t pa[4];
            pa[0] = Ps[(w * 16 + g) * FLDP + kc * 8 + tg];
            pa[1] = Ps[(w * 16 + 8 + g) * FLDP + kc * 8 + tg];
            pa[2] = Ps[(w * 16 + g) * FLDP + kc * 8 + tg + 4];
            pa[3] = Ps[(w * 16 + 8 + g) * FLDP + kc * 8 + tg + 4];
#pragma unroll
            for (int ni = 0; ni < 16; ni++) {
                uint32_t vb[2];
                vb[0] = Vs[(kc * 8 + tg) * FLDK + ni * 8 + g];
                vb[1] = Vs[(kc * 8 + tg + 4) * FLDK + ni * 8 + g];
                mma_tf32(of[ni], pa, vb);
            }
        }
    }

    // ---- normalize + store ----
    const float inv0 = 1.f / l0;
    const float inv1 = 1.f / l1;
    float* y0 = y + ((size_t)(b * Tt_) + grow0) * Cc_ + h * HDv_;
    float* y1 = y + ((size_t)(b * Tt_) + grow1) * Cc_ + h * HDv_;
#pragma unroll
    for (int ni = 0; ni < 16; ni++) {
        const int c0 = ni * 8 + tg * 2;
        float2 v0 = {of[ni][0] * inv0, of[ni][1] * inv0};
        float2 v1 = {of[ni][2] * inv1, of[ni][3] * inv1};
        *(float2*)(y0 + c0) = v0;
        *(float2*)(y1 + c0) = v1;
    }
}

// ---------------------------------------------------------------------------
extern "C" void kernel_launch(void* const* d_in, const int* in_sizes, int n_in,
                              void* d_out, int out_size)
{
    const float* x   = (const float*)d_in[0];
    const float* Wkv = (const float*)d_in[1];
    const float* bkv = (const float*)d_in[2];
    const float* Wq  = (const float*)d_in[3];
    const float* bq  = (const float*)d_in[4];
    const float* Wp  = (const float*)d_in[5];
    const float* bp  = (const float*)d_in[6];
    float* out = (float*)d_out;

    float *qp, *kvp, *yp;
    cudaGetSymbolAddress((void**)&qp,  g_q);
    cudaGetSymbolAddress((void**)&kvp, g_kv);
    cudaGetSymbolAddress((void**)&yp,  g_y);

    cudaFuncSetAttribute(flash_mma,
                         cudaFuncAttributeMaxDynamicSharedMemorySize,
                         FLASH_SMEM);

    // q = x @ Wq + bq        (4096 x 2048 x 2048)
    tgemm_bias<<<dim3(Cc_ / 128, Mm_ / 128), 256>>>(Mm_, Cc_, Cc_, x, Wq, bq, qp);
    // kv = x @ Wkv + bkv     (4096 x 1024 x 2048)
    tgemm_bias<<<dim3(KVN_ / 128, Mm_ / 128), 256>>>(Mm_, KVN_, Cc_, x, Wkv, bkv, kvp);
    // attention (tf32 mma flash)
    flash_mma<<<dim3(Tt_ / 128, Hh_, Bb_), 256, FLASH_SMEM>>>(qp, kvp, yp);
    // out = y @ Wp + bp      (4096 x 2048 x 2048)
    tgemm_bias<<<dim3(Cc_ / 128, Mm_ / 128), 256>>>(Mm_, Cc_, Cc_, yp, Wp, bp, out);
}

// round 7
// speedup vs baseline: 2.6617x; 1.0117x over previous
#include <cuda_runtime.h>
#include <math.h>
#include <stdint.h>

// Problem constants
#define Bb_ 2
#define Tt_ 2048
#define Cc_ 2048
#define Hh_ 16
#define HKV_ 4
#define HDv_ 128
#define Mm_ (Bb_ * Tt_)
#define KVN_ 1024

// Scratch (device globals; no allocation allowed)
__device__ float g_q[(size_t)Mm_ * Cc_];
__device__ float g_kv[(size_t)Mm_ * KVN_];
__device__ float g_y[(size_t)Mm_ * Cc_];

// ---- helpers ----------------------------------------------------------------
typedef unsigned long long u64t;

__device__ __forceinline__ u64t pk2(float lo, float hi) {
    u64t r;
    asm("mov.b64 %0, {%1, %2};" : "=l"(r) : "f"(lo), "f"(hi));
    return r;
}
__device__ __forceinline__ void mul2(u64t& d, u64t a, u64t b) {
    asm("mul.rn.f32x2 %0, %1, %2;" : "=l"(d) : "l"(a), "l"(b));
}
__device__ __forceinline__ float2 upk(u64t v) {
    float2 f;
    asm("mov.b64 {%0, %1}, %2;" : "=f"(f.x), "=f"(f.y) : "l"(v));
    return f;
}
__device__ __forceinline__ uint32_t to_tf32(float f) {
    uint32_t r;
    asm("cvt.rna.tf32.f32 %0, %1;" : "=r"(r) : "f"(f));
    return r;
}
__device__ __forceinline__ void mma_tf32(float (&d)[4],
                                         const uint32_t (&a)[4],
                                         const uint32_t (&b)[2]) {
    asm volatile(
        "mma.sync.aligned.m16n8k8.row.col.f32.tf32.tf32.f32 "
        "{%0,%1,%2,%3}, {%4,%5,%6,%7}, {%8,%9}, {%0,%1,%2,%3};\n"
        : "+f"(d[0]), "+f"(d[1]), "+f"(d[2]), "+f"(d[3])
        : "r"(a[0]), "r"(a[1]), "r"(a[2]), "r"(a[3]), "r"(b[0]), "r"(b[1]));
}
// lane rotate-left-2 within 5 bits (bijective): mixes m-bits into STS banks
__device__ __forceinline__ int rot2(int l) {
    return ((l << 2) | (l >> 3)) & 31;
}

// ---------------------------------------------------------------------------
// tf32 tensor-core GEMM, fragment-ordered smem.
// CTA: 128 threads (4 warps), tile 128x128, BK=16, double-buffered.
// Warp tile 64x64 (wm = wid&1 in M, wn = wid>>1 in N): 4x8 m16n8k8 per k-step.
// A frags: uint4 per lane (LDS.128), lane-permuted by rot2.
// B frags: uint2 per lane (LDS.64).
// ---------------------------------------------------------------------------
#define AFRAGS 16   // 8 mt x 2 kc
#define BFRAGS 32   // 16 nt x 2 kc
#define AFSTR 33    // uint4 stride per fragment (pad)
#define BFSTR 33    // uint2 stride per fragment (pad)

__global__ void __launch_bounds__(128, 2)
fgemm(int M, int N, int K,
      const float* __restrict__ A, const float* __restrict__ B,
      const float* __restrict__ bias, float* __restrict__ C)
{
    __shared__ uint4 AF[2][AFRAGS * AFSTR];
    __shared__ uint2 BF[2][BFRAGS * BFSTR];

    const int tid  = threadIdx.x;
    const int wid  = tid >> 5;
    const int lane = tid & 31;
    const int g    = lane >> 2;
    const int tg   = lane & 3;
    const int wm   = wid & 1;
    const int wn   = wid >> 1;
    const int rl2  = rot2(lane);

    const float* Ab = A + (size_t)blockIdx.y * 128 * K;
    const float* Bb = B + blockIdx.x * 128;

    float acc[4][8][4];
#pragma unroll
    for (int mi = 0; mi < 4; mi++)
#pragma unroll
        for (int ni = 0; ni < 8; ni++)
#pragma unroll
            for (int r = 0; r < 4; r++) acc[mi][ni][r] = 0.f;

    const int nt = K / 16;
    float4 pfA[4], pfB[4];

    // ---- load k-tile 0 into prefetch regs ----
#pragma unroll
    for (int u = 0; u < 4; u++) {
        const int ia = tid + u * 128;
        pfA[u] = *(const float4*)(Ab + (size_t)(ia >> 2) * K + (ia & 3) * 4);
        const int ib = tid + u * 128;
        pfB[u] = *(const float4*)(Bb + (size_t)(ib >> 5) * N + ((ib & 31) << 2));
    }

    // scatter-store prefetch regs into buffer `buf` for k-tile (local k 0..15)
#define STAGE(buf)                                                            \
    do {                                                                      \
        uint32_t* AFw = (uint32_t*)AF[buf];                                   \
        uint32_t* BFw = (uint32_t*)BF[buf];                                   \
        _Pragma("unroll")                                                     \
        for (int u = 0; u < 4; u++) {                                         \
            const int ia = tid + u * 128;                                     \
            const int m  = ia >> 2;                                           \
            const int c  = ia & 3;                                            \
            const int fra  = (m >> 4) * 2 + (c >> 1);                         \
            const int widx = ((m >> 3) & 1) + ((c & 1) << 1);                 \
            const int lb   = (m & 7) << 2;                                    \
            const float* av = (const float*)&pfA[u];                          \
            _Pragma("unroll")                                                 \
            for (int e = 0; e < 4; e++)                                       \
                AFw[(fra * AFSTR + rot2(lb + e)) * 4 + widx] = to_tf32(av[e]);\
            const int ib = tid + u * 128;                                     \
            const int k  = ib >> 5;                                           \
            const int n0 = (ib & 31) << 2;                                    \
            const int tgb = k & 3;                                            \
            const int wb  = (k >> 2) & 1;                                     \
            const int kcb = k >> 3;                                           \
            const float* bv = (const float*)&pfB[u];                          \
            _Pragma("unroll")                                                 \
            for (int e = 0; e < 4; e++) {                                     \
                const int n = n0 + e;                                         \
                BFw[(((n >> 3) * 2 + kcb) * BFSTR + (n & 7) * 4 + tgb) * 2    \
                    + wb] = to_tf32(bv[e]);                                   \
            }                                                                 \
        }                                                                     \
    } while (0)

    STAGE(0);
    __syncthreads();

    for (int t = 0; t < nt; ++t) {
        const int cur = t & 1;
        const bool more = (t + 1 < nt);
        if (more) {
            const int k0 = (t + 1) * 16;
#pragma unroll
            for (int u = 0; u < 4; u++) {
                const int ia = tid + u * 128;
                pfA[u] = *(const float4*)(Ab + (size_t)(ia >> 2) * K + k0 +
                                          (ia & 3) * 4);
                const int ib = tid + u * 128;
                pfB[u] = *(const float4*)(Bb + (size_t)(k0 + (ib >> 5)) * N +
                                          ((ib & 31) << 2));
            }
        }

#pragma unroll
        for (int kc = 0; kc < 2; kc++) {
            uint32_t afr[4][4];
#pragma unroll
            for (int mi = 0; mi < 4; mi++) {
                const uint4 a4 =
                    AF[cur][((wm * 4 + mi) * 2 + kc) * AFSTR + rl2];
                afr[mi][0] = a4.x; afr[mi][1] = a4.y;
                afr[mi][2] = a4.z; afr[mi][3] = a4.w;
            }
            uint32_t bfr[8][2];
#pragma unroll
            for (int ni = 0; ni < 8; ni++) {
                const uint2 b2 =
                    BF[cur][((wn * 8 + ni) * 2 + kc) * BFSTR + lane];
                bfr[ni][0] = b2.x; bfr[ni][1] = b2.y;
            }
#pragma unroll
            for (int mi = 0; mi < 4; mi++)
#pragma unroll
                for (int ni = 0; ni < 8; ni++)
                    mma_tf32(acc[mi][ni], afr[mi], bfr[ni]);
        }

        if (more) {
            const int nxt = cur ^ 1;
            STAGE(nxt);
        }
        __syncthreads();
    }

    // ---- epilogue: fused bias ----
#pragma unroll
    for (int mi = 0; mi < 4; mi++) {
        const int r0 = blockIdx.y * 128 + wm * 64 + mi * 16 + g;
#pragma unroll
        for (int ni = 0; ni < 8; ni++) {
            const int c0 = blockIdx.x * 128 + wn * 64 + ni * 8 + tg * 2;
            const float bx0 = bias[c0], bx1 = bias[c0 + 1];
            float2 v0 = {acc[mi][ni][0] + bx0, acc[mi][ni][1] + bx1};
            float2 v1 = {acc[mi][ni][2] + bx0, acc[mi][ni][3] + bx1};
            *(float2*)(C + (size_t)r0 * N + c0)       = v0;
            *(float2*)(C + (size_t)(r0 + 8) * N + c0) = v1;
        }
    }
#undef STAGE
}

// ---------------------------------------------------------------------------
// Flash attention via tf32 mma.sync, fragment-ordered K/V smem (uint2 LDS.64).
// Br=128 (8 warps x 16 rows), Bc=64, HD=128.
// ---------------------------------------------------------------------------
#define KFRAGS 128           // 8 nt x 16 kc
#define VFRAGS 128           // 8 kc x 16 ni
#define KFo 0                            // words
#define VFo (KFRAGS * 33 * 2)            // 8448 words
#define PSo (2 * KFRAGS * 33 * 2)        // 16896 words
#define FLDP 68
#define FLASH_SMEM ((PSo + 128 * FLDP) * 4)

__global__ void __launch_bounds__(256, 1)
flash_mma(const float* __restrict__ q, const float* __restrict__ kv,
          float* __restrict__ y)
{
    extern __shared__ uint32_t smw[];
    uint32_t* KFw = smw + KFo;
    uint32_t* VFw = smw + VFo;
    uint32_t* Ps  = smw + PSo;
    const uint2* KF2 = (const uint2*)KFw;
    const uint2* VF2 = (const uint2*)VFw;

    const int qt = blockIdx.x;
    const int h  = blockIdx.y;
    const int b  = blockIdx.z;
    const int kvh = h & (HKV_ - 1);

    const int tid  = threadIdx.x;
    const int w    = tid >> 5;
    const int lane = tid & 31;
    const int g    = lane >> 2;
    const int tg   = lane & 3;
    const float scale = 0.08838834764831843f;

    const int rloc0 = w * 16 + g;
    const int grow0 = qt * 128 + rloc0;
    const int grow1 = grow0 + 8;

    uint32_t qf[16][4];
    {
        const float* qb = q + ((size_t)(b * Tt_) + qt * 128 + w * 16) * Cc_
                            + h * HDv_;
#pragma unroll
        for (int kc = 0; kc < 16; kc++) {
            const int d0 = kc * 8 + tg;
            qf[kc][0] = to_tf32(qb[(size_t)g * Cc_ + d0] * scale);
            qf[kc][1] = to_tf32(qb[(size_t)(g + 8) * Cc_ + d0] * scale);
            qf[kc][2] = to_tf32(qb[(size_t)g * Cc_ + d0 + 4] * scale);
            qf[kc][3] = to_tf32(qb[(size_t)(g + 8) * Cc_ + d0 + 4] * scale);
        }
    }

    float of[16][4];
#pragma unroll
    for (int ni = 0; ni < 16; ni++)
#pragma unroll
        for (int r = 0; r < 4; r++) of[ni][r] = 0.f;
    float m0 = -INFINITY, m1 = -INFINITY, l0 = 0.f, l1 = 0.f;

    const int ktmax = 2 * qt + 1;
    for (int kt = 0; kt <= ktmax; ++kt) {
        __syncthreads();

        // ---- cooperative K/V load -> fragment-ordered tf32 smem ----
        for (int i = tid; i < 64 * 32; i += 256) {
            const int r  = i >> 5;
            const int c4 = (i & 31) << 2;
            const float* base =
                kv + ((size_t)(b * Tt_ + kt * 64 + r)) * KVN_ + kvh * HDv_ + c4;
            const float4 kx = *(const float4*)(base);
            const float4 vx = *(const float4*)(base + 512);
            const float* ke = (const float*)&kx;
            const float* ve = (const float*)&vx;
            const int frb = (r >> 3) * 16;
            const int lkb = (r & 7) << 2;
            const int tgv = r & 3;
            const int wv  = (r >> 2) & 1;
#pragma unroll
            for (int e = 0; e < 4; e++) {
                const int c = c4 + e;
                // K: B-frag (seq=n, d=k)
                KFw[((frb + (c >> 3)) * 33 + lkb + (c & 3)) * 2 +
                    ((c >> 2) & 1)] = to_tf32(ke[e]);
                // V: B-frag (seq=k, hd=n)
                VFw[((frb + (c >> 3)) * 33 + (c & 7) * 4 + tgv) * 2 + wv] =
                    to_tf32(ve[e]);
            }
        }
        __syncthreads();

        const bool act = (kt * 64) <= (qt * 128 + w * 16 + 15);
        if (!act) continue;

        // ---- S = Q K^T ----
        float sf[8][4];
#pragma unroll
        for (int ni = 0; ni < 8; ni++)
#pragma unroll
            for (int r = 0; r < 4; r++) sf[ni][r] = 0.f;

#pragma unroll
        for (int kc = 0; kc < 16; kc++) {
#pragma unroll
            for (int ni = 0; ni < 8; ni++) {
                const uint2 b2 = KF2[(ni * 16 + kc) * 33 + lane];
                const uint32_t bfr[2] = {b2.x, b2.y};
                mma_tf32(sf[ni], qf[kc], bfr);
            }
        }

        if (kt * 64 + 63 > qt * 128 + w * 16) {
            const int cb = kt * 64;
#pragma unroll
            for (int ni = 0; ni < 8; ni++) {
                const int c0 = cb + ni * 8 + tg * 2;
                if (c0 > grow0)     sf[ni][0] = -1e30f;
                if (c0 + 1 > grow0) sf[ni][1] = -1e30f;
                if (c0 > grow1)     sf[ni][2] = -1e30f;
                if (c0 + 1 > grow1) sf[ni][3] = -1e30f;
            }
        }

        // ---- online softmax ----
        float mx0 = -1e30f, mx1 = -1e30f;
#pragma unroll
        for (int ni = 0; ni < 8; ni++) {
            mx0 = fmaxf(mx0, fmaxf(sf[ni][0], sf[ni][1]));
            mx1 = fmaxf(mx1, fmaxf(sf[ni][2], sf[ni][3]));
        }
        mx0 = fmaxf(mx0, __shfl_xor_sync(0xffffffffu, mx0, 1));
        mx0 = fmaxf(mx0, __shfl_xor_sync(0xffffffffu, mx0, 2));
        mx1 = fmaxf(mx1, __shfl_xor_sync(0xffffffffu, mx1, 1));
        mx1 = fmaxf(mx1, __shfl_xor_sync(0xffffffffu, mx1, 2));

        const float nm0 = fmaxf(m0, mx0);
        const float nm1 = fmaxf(m1, mx1);
        float sum0 = 0.f, sum1 = 0.f;
#pragma unroll
        for (int ni = 0; ni < 8; ni++) {
            sf[ni][0] = __expf(sf[ni][0] - nm0);
            sf[ni][1] = __expf(sf[ni][1] - nm0);
            sf[ni][2] = __expf(sf[ni][2] - nm1);
            sf[ni][3] = __expf(sf[ni][3] - nm1);
            sum0 += sf[ni][0] + sf[ni][1];
            sum1 += sf[ni][2] + sf[ni][3];
        }
        sum0 += __shfl_xor_sync(0xffffffffu, sum0, 1);
        sum0 += __shfl_xor_sync(0xffffffffu, sum0, 2);
        sum1 += __shfl_xor_sync(0xffffffffu, sum1, 1);
        sum1 += __shfl_xor_sync(0xffffffffu, sum1, 2);

        const float al0 = __expf(m0 - nm0);
        const float al1 = __expf(m1 - nm1);
        m0 = nm0; m1 = nm1;
        l0 = l0 * al0 + sum0;
        l1 = l1 * al1 + sum1;

        // ---- write P (tf32) to warp-private strip ----
#pragma unroll
        for (int ni = 0; ni < 8; ni++) {
            uint2 p01 = {to_tf32(sf[ni][0]), to_tf32(sf[ni][1])};
            uint2 p23 = {to_tf32(sf[ni][2]), to_tf32(sf[ni][3])};
            *(uint2*)(&Ps[(w * 16 + g) * FLDP + ni * 8 + tg * 2])     = p01;
            *(uint2*)(&Ps[(w * 16 + 8 + g) * FLDP + ni * 8 + tg * 2]) = p23;
        }
        __syncwarp();

        // ---- rescale O ----
        {
            const u64t a0p = pk2(al0, al0);
            const u64t a1p = pk2(al1, al1);
#pragma unroll
            for (int ni = 0; ni < 16; ni++) {
                u64t v01 = pk2(of[ni][0], of[ni][1]);
                u64t v23 = pk2(of[ni][2], of[ni][3]);
                mul2(v01, v01, a0p);
                mul2(v23, v23, a1p);
                const float2 f01 = upk(v01), f23 = upk(v23);
                of[ni][0] = f01.x; of[ni][1] = f01.y;
                of[ni][2] = f23.x; of[ni][3] = f23.y;
            }
        }

        // ---- O += P V ----
#pragma unroll
        for (int kc = 0; kc < 8; kc++) {
            uint32_t pa[4];
            pa[0] = Ps[(w * 16 + g) * FLDP + kc * 8 + tg];
            pa[1] = Ps[(w * 16 + 8 + g) * FLDP + kc * 8 + tg];
            pa[2] = Ps[(w * 16 + g) * FLDP + kc * 8 + tg + 4];
            pa[3] = Ps[(w * 16 + 8 + g) * FLDP + kc * 8 + tg + 4];
#pragma unroll
            for (int ni = 0; ni < 16; ni++) {
                const uint2 v2 = VF2[(kc * 16 + ni) * 33 + lane];
                const uint32_t vb[2] = {v2.x, v2.y};
                mma_tf32(of[ni], pa, vb);
            }
        }
    }

    const float inv0 = 1.f / l0;
    const float inv1 = 1.f / l1;
    float* y0 = y + ((size_t)(b * Tt_) + grow0) * Cc_ + h * HDv_;
    float* y1 = y + ((size_t)(b * Tt_) + grow1) * Cc_ + h * HDv_;
#pragma unroll
    for (int ni = 0; ni < 16; ni++) {
        const int c0 = ni * 8 + tg * 2;
        float2 v0 = {of[ni][0] * inv0, of[ni][1] * inv0};
        float2 v1 = {of[ni][2] * inv1, of[ni][3] * inv1};
        *(float2*)(y0 + c0) = v0;
        *(float2*)(y1 + c0) = v1;
    }
}

// ---------------------------------------------------------------------------
extern "C" void kernel_launch(void* const* d_in, const int* in_sizes, int n_in,
                              void* d_out, int out_size)
{
    const float* x   = (const float*)d_in[0];
    const float* Wkv = (const float*)d_in[1];
    const float* bkv = (const float*)d_in[2];
    const float* Wq  = (const float*)d_in[3];
    const float* bq  = (const float*)d_in[4];
    const float* Wp  = (const float*)d_in[5];
    const float* bp  = (const float*)d_in[6];
    float* out = (float*)d_out;

    float *qp, *kvp, *yp;
    cudaGetSymbolAddress((void**)&qp,  g_q);
    cudaGetSymbolAddress((void**)&kvp, g_kv);
    cudaGetSymbolAddress((void**)&yp,  g_y);

    cudaFuncSetAttribute(flash_mma,
                         cudaFuncAttributeMaxDynamicSharedMemorySize,
                         FLASH_SMEM);

    // q = x @ Wq + bq        (4096 x 2048 x 2048)
    fgemm<<<dim3(Cc_ / 128, Mm_ / 128), 128>>>(Mm_, Cc_, Cc_, x, Wq, bq, qp);
    // kv = x @ Wkv + bkv     (4096 x 1024 x 2048)
    fgemm<<<dim3(KVN_ / 128, Mm_ / 128), 128>>>(Mm_, KVN_, Cc_, x, Wkv, bkv, kvp);
    // attention
    flash_mma<<<dim3(Tt_ / 128, Hh_, Bb_), 256, FLASH_SMEM>>>(qp, kvp, yp);
    // out = y @ Wp + bp      (4096 x 2048 x 2048)
    fgemm<<<dim3(Cc_ / 128, Mm_ / 128), 128>>>(Mm_, Cc_, Cc_, yp, Wp, bp, out);
}

// round 8
// speedup vs baseline: 3.0793x; 1.1569x over previous
#include <cuda_runtime.h>
#include <math.h>
#include <stdint.h>

// Problem constants
#define Bb_ 2
#define Tt_ 2048
#define Cc_ 2048
#define Hh_ 16
#define HKV_ 4
#define HDv_ 128
#define Mm_ (Bb_ * Tt_)
#define KVN_ 1024

// Scratch (device globals; no allocation allowed)
__device__ float g_q[(size_t)Mm_ * Cc_];
__device__ float g_kv[(size_t)Mm_ * KVN_];
__device__ float g_y[(size_t)Mm_ * Cc_];

// ---- helpers ----------------------------------------------------------------
typedef unsigned long long u64t;

__device__ __forceinline__ u64t pk2(float lo, float hi) {
    u64t r;
    asm("mov.b64 %0, {%1, %2};" : "=l"(r) : "f"(lo), "f"(hi));
    return r;
}
__device__ __forceinline__ void mul2(u64t& d, u64t a, u64t b) {
    asm("mul.rn.f32x2 %0, %1, %2;" : "=l"(d) : "l"(a), "l"(b));
}
__device__ __forceinline__ float2 upk(u64t v) {
    float2 f;
    asm("mov.b64 {%0, %1}, %2;" : "=f"(f.x), "=f"(f.y) : "l"(v));
    return f;
}
__device__ __forceinline__ uint32_t to_tf32(float f) {
    uint32_t r;
    asm("cvt.rna.tf32.f32 %0, %1;" : "=r"(r) : "f"(f));
    return r;
}
__device__ __forceinline__ void mma_tf32(float (&d)[4],
                                         const uint32_t (&a)[4],
                                         const uint32_t (&b)[2]) {
    asm volatile(
        "mma.sync.aligned.m16n8k8.row.col.f32.tf32.tf32.f32 "
        "{%0,%1,%2,%3}, {%4,%5,%6,%7}, {%8,%9}, {%0,%1,%2,%3};\n"
        : "+f"(d[0]), "+f"(d[1]), "+f"(d[2]), "+f"(d[3])
        : "r"(a[0]), "r"(a[1]), "r"(a[2]), "r"(a[3]), "r"(b[0]), "r"(b[1]));
}
__device__ __forceinline__ uint32_t smem_u32(const void* p) {
    uint32_t a;
    asm("{ .reg .u64 t; cvta.to.shared.u64 t, %1; cvt.u32.u64 %0, t; }"
        : "=r"(a) : "l"(p));
    return a;
}
__device__ __forceinline__ void cp16(uint32_t dst, const void* src) {
    asm volatile("cp.async.cg.shared.global [%0], [%1], 16;"
                 :: "r"(dst), "l"(src));
}
#define CP_COMMIT() asm volatile("cp.async.commit_group;" ::: "memory")
#define CP_WAIT(n)  asm volatile("cp.async.wait_group %0;" :: "n"(n) : "memory")

// ---------------------------------------------------------------------------
// tf32 mma.sync GEMM with 4-stage cp.async pipeline.
// C[M,N] = A[M,K] @ B[K,N] + bias[N], row-major fp32.
// 128x128 CTA tile, BK=16, 8 warps (warp tile 64x32).
// Stage layout: A [128][20] raw fp32, B [16][132] raw fp32.
// cvt.rna to tf32 at fragment-load time.
// ---------------------------------------------------------------------------
#define GSTG 4
#define LDA_S 20
#define LDB_S 132
#define A_WORDS (128 * LDA_S)            // 2560
#define B_WORDS (16 * LDB_S)             // 2112
#define STG_WORDS (A_WORDS + B_WORDS)    // 4672
#define GEMM_SMEM (GSTG * STG_WORDS * 4) // 74752 B

__device__ __forceinline__ void gemm_issue(uint32_t sb, int buf,
                                           const float* Ab, const float* Bb,
                                           int K, int N, int k0, int tid)
{
    const uint32_t base = sb + buf * (STG_WORDS * 4);
#pragma unroll
    for (int u = 0; u < 2; u++) {
        const int ia = tid + u * 256;          // 0..511
        const int m  = ia >> 2;
        const int c4 = (ia & 3) << 2;          // word offset in k
        cp16(base + (m * LDA_S + c4) * 4, Ab + (size_t)m * K + k0 + c4);
        const int ib = tid + u * 256;
        const int k  = ib >> 5;
        const int n4 = (ib & 31) << 2;
        cp16(base + (A_WORDS + k * LDB_S + n4) * 4,
             Bb + (size_t)(k0 + k) * N + n4);
    }
}

__global__ void __launch_bounds__(256, 2)
pgemm(int M, int N, int K,
      const float* __restrict__ A, const float* __restrict__ B,
      const float* __restrict__ bias, float* __restrict__ C)
{
    extern __shared__ uint32_t smw[];
    const uint32_t sb = smem_u32(smw);
    const float* smf = (const float*)smw;

    const int tid  = threadIdx.x;
    const int wid  = tid >> 5;
    const int lane = tid & 31;
    const int g    = lane >> 2;
    const int tg   = lane & 3;
    const int wm   = wid & 1;
    const int wn   = wid >> 1;

    const float* Ab = A + (size_t)blockIdx.y * 128 * K;
    const float* Bb = B + blockIdx.x * 128;

    float acc[4][4][4];
#pragma unroll
    for (int mi = 0; mi < 4; mi++)
#pragma unroll
        for (int ni = 0; ni < 4; ni++)
#pragma unroll
            for (int r = 0; r < 4; r++) acc[mi][ni][r] = 0.f;

    const int nt = K / 16;

    // prologue: issue tiles 0..2
#pragma unroll
    for (int s = 0; s < GSTG - 1; s++) {
        if (s < nt) gemm_issue(sb, s, Ab, Bb, K, N, s * 16, tid);
        CP_COMMIT();
    }

    for (int t = 0; t < nt; ++t) {
        CP_WAIT(2);          // tile t resident (commits so far: t+3)
        __syncthreads();
        if (t + 3 < nt)
            gemm_issue(sb, (t + 3) & 3, Ab, Bb, K, N, (t + 3) * 16, tid);
        CP_COMMIT();

        const float* As = smf + (t & 3) * STG_WORDS;
        const float* Bs = As + A_WORDS;
#pragma unroll
        for (int kc = 0; kc < 2; kc++) {
            uint32_t afr[4][4];
#pragma unroll
            for (int mi = 0; mi < 4; mi++) {
                const int r0 = wm * 64 + mi * 16 + g;
                afr[mi][0] = to_tf32(As[r0 * LDA_S + kc * 8 + tg]);
                afr[mi][1] = to_tf32(As[(r0 + 8) * LDA_S + kc * 8 + tg]);
                afr[mi][2] = to_tf32(As[r0 * LDA_S + kc * 8 + tg + 4]);
                afr[mi][3] = to_tf32(As[(r0 + 8) * LDA_S + kc * 8 + tg + 4]);
            }
            uint32_t bfr[4][2];
#pragma unroll
            for (int ni = 0; ni < 4; ni++) {
                const int c0 = wn * 32 + ni * 8 + g;
                bfr[ni][0] = to_tf32(Bs[(kc * 8 + tg) * LDB_S + c0]);
                bfr[ni][1] = to_tf32(Bs[(kc * 8 + tg + 4) * LDB_S + c0]);
            }
#pragma unroll
            for (int mi = 0; mi < 4; mi++)
#pragma unroll
                for (int ni = 0; ni < 4; ni++)
                    mma_tf32(acc[mi][ni], afr[mi], bfr[ni]);
        }
        // next iter's sync guards buffer reuse (issue targets buf computed 1 iter ago)
    }

    // ---- epilogue: fused bias ----
#pragma unroll
    for (int mi = 0; mi < 4; mi++) {
        const int r0 = blockIdx.y * 128 + wm * 64 + mi * 16 + g;
#pragma unroll
        for (int ni = 0; ni < 4; ni++) {
            const int c0 = blockIdx.x * 128 + wn * 32 + ni * 8 + tg * 2;
            const float bx0 = bias[c0], bx1 = bias[c0 + 1];
            float2 v0 = {acc[mi][ni][0] + bx0, acc[mi][ni][1] + bx1};
            float2 v1 = {acc[mi][ni][2] + bx0, acc[mi][ni][3] + bx1};
            *(float2*)(C + (size_t)r0 * N + c0)       = v0;
            *(float2*)(C + (size_t)(r0 + 8) * N + c0) = v1;
        }
    }
}

// ---------------------------------------------------------------------------
// Flash attention, tf32 mma.sync, double-buffered cp.async K/V (raw fp32;
// HW-truncated tf32 operands). Br=128 (8 warps x 16 rows), Bc=64, HD=128.
// ---------------------------------------------------------------------------
#define FLDK 132
#define KV_WORDS (64 * FLDK)             // per K or V buffer: 8448 words
#define STG_F (2 * KV_WORDS)             // K+V per stage: 16896 words
#define PSo (2 * STG_F)                  // 33792 words
#define FLDP 68
#define FLASH_SMEM ((PSo + 128 * FLDP) * 4)   // 169984 B

__device__ __forceinline__ void flash_issue(uint32_t sb, int buf,
                                            const float* kvbase, int tid)
{
    const uint32_t kb = sb + buf * (STG_F * 4);
    const uint32_t vb = kb + KV_WORDS * 4;
#pragma unroll
    for (int u = 0; u < 8; u++) {
        const int i  = tid + u * 256;     // 0..2047
        const int r  = i >> 5;
        const int c4 = (i & 31) << 2;
        const float* src = kvbase + (size_t)r * KVN_ + c4;
        cp16(kb + (r * FLDK + c4) * 4, src);
        cp16(vb + (r * FLDK + c4) * 4, src + 512);
    }
}

__global__ void __launch_bounds__(256, 1)
flash_cp(const float* __restrict__ q, const float* __restrict__ kv,
         float* __restrict__ y)
{
    extern __shared__ uint32_t smw[];
    const uint32_t sb = smem_u32(smw);
    uint32_t* Ps = smw + PSo;

    const int qt = blockIdx.x;
    const int h  = blockIdx.y;
    const int b  = blockIdx.z;
    const int kvh = h & (HKV_ - 1);

    const int tid  = threadIdx.x;
    const int w    = tid >> 5;
    const int lane = tid & 31;
    const int g    = lane >> 2;
    const int tg   = lane & 3;
    const float scale = 0.08838834764831843f;

    const int rloc0 = w * 16 + g;
    const int grow0 = qt * 128 + rloc0;
    const int grow1 = grow0 + 8;

    // ---- Q in registers as tf32 A-fragments (rounded) ----
    uint32_t qf[16][4];
    {
        const float* qb = q + ((size_t)(b * Tt_) + qt * 128 + w * 16) * Cc_
                            + h * HDv_;
#pragma unroll
        for (int kc = 0; kc < 16; kc++) {
            const int d0 = kc * 8 + tg;
            qf[kc][0] = to_tf32(qb[(size_t)g * Cc_ + d0] * scale);
            qf[kc][1] = to_tf32(qb[(size_t)(g + 8) * Cc_ + d0] * scale);
            qf[kc][2] = to_tf32(qb[(size_t)g * Cc_ + d0 + 4] * scale);
            qf[kc][3] = to_tf32(qb[(size_t)(g + 8) * Cc_ + d0 + 4] * scale);
        }
    }

    float of[16][4];
#pragma unroll
    for (int ni = 0; ni < 16; ni++)
#pragma unroll
        for (int r = 0; r < 4; r++) of[ni][r] = 0.f;
    float m0 = -INFINITY, m1 = -INFINITY, l0 = 0.f, l1 = 0.f;

    const int ktmax = 2 * qt + 1;
    const float* kvb0 = kv + (size_t)(b * Tt_) * KVN_ + kvh * HDv_;

    // prologue: tile 0 -> buf 0
    flash_issue(sb, 0, kvb0, tid);
    CP_COMMIT();

    for (int kt = 0; kt <= ktmax; ++kt) {
        const int cur = kt & 1;
        if (kt < ktmax)
            flash_issue(sb, cur ^ 1, kvb0 + (size_t)(kt + 1) * 64 * KVN_, tid);
        CP_COMMIT();
        CP_WAIT(1);          // commits = kt+2 -> tiles 0..kt resident
        __syncthreads();

        const uint32_t* Kb = smw + cur * STG_F;
        const uint32_t* Vb = Kb + KV_WORDS;

        const bool act = (kt * 64) <= (qt * 128 + w * 16 + 15);
        if (act) {
            // ---- S = Q K^T ----
            float sf[8][4];
#pragma unroll
            for (int ni = 0; ni < 8; ni++)
#pragma unroll
                for (int r = 0; r < 4; r++) sf[ni][r] = 0.f;

#pragma unroll
            for (int kc = 0; kc < 16; kc++) {
#pragma unroll
                for (int ni = 0; ni < 8; ni++) {
                    uint32_t bfr[2];
                    bfr[0] = Kb[(ni * 8 + g) * FLDK + kc * 8 + tg];
                    bfr[1] = Kb[(ni * 8 + g) * FLDK + kc * 8 + tg + 4];
                    mma_tf32(sf[ni], qf[kc], bfr);
                }
            }

            if (kt * 64 + 63 > qt * 128 + w * 16) {
                const int cb = kt * 64;
#pragma unroll
                for (int ni = 0; ni < 8; ni++) {
                    const int c0 = cb + ni * 8 + tg * 2;
                    if (c0 > grow0)     sf[ni][0] = -1e30f;
                    if (c0 + 1 > grow0) sf[ni][1] = -1e30f;
                    if (c0 > grow1)     sf[ni][2] = -1e30f;
                    if (c0 + 1 > grow1) sf[ni][3] = -1e30f;
                }
            }

            // ---- online softmax ----
            float mx0 = -1e30f, mx1 = -1e30f;
#pragma unroll
            for (int ni = 0; ni < 8; ni++) {
                mx0 = fmaxf(mx0, fmaxf(sf[ni][0], sf[ni][1]));
                mx1 = fmaxf(mx1, fmaxf(sf[ni][2], sf[ni][3]));
            }
            mx0 = fmaxf(mx0, __shfl_xor_sync(0xffffffffu, mx0, 1));
            mx0 = fmaxf(mx0, __shfl_xor_sync(0xffffffffu, mx0, 2));
            mx1 = fmaxf(mx1, __shfl_xor_sync(0xffffffffu, mx1, 1));
            mx1 = fmaxf(mx1, __shfl_xor_sync(0xffffffffu, mx1, 2));

            const float nm0 = fmaxf(m0, mx0);
            const float nm1 = fmaxf(m1, mx1);
            float sum0 = 0.f, sum1 = 0.f;
#pragma unroll
            for (int ni = 0; ni < 8; ni++) {
                sf[ni][0] = __expf(sf[ni][0] - nm0);
                sf[ni][1] = __expf(sf[ni][1] - nm0);
                sf[ni][2] = __expf(sf[ni][2] - nm1);
                sf[ni][3] = __expf(sf[ni][3] - nm1);
                sum0 += sf[ni][0] + sf[ni][1];
                sum1 += sf[ni][2] + sf[ni][3];
            }
            sum0 += __shfl_xor_sync(0xffffffffu, sum0, 1);
            sum0 += __shfl_xor_sync(0xffffffffu, sum0, 2);
            sum1 += __shfl_xor_sync(0xffffffffu, sum1, 1);
            sum1 += __shfl_xor_sync(0xffffffffu, sum1, 2);

            const float al0 = __expf(m0 - nm0);
            const float al1 = __expf(m1 - nm1);
            m0 = nm0; m1 = nm1;
            l0 = l0 * al0 + sum0;
            l1 = l1 * al1 + sum1;

            // ---- P -> warp-private smem strip (rounded tf32) ----
#pragma unroll
            for (int ni = 0; ni < 8; ni++) {
                uint2 p01 = {to_tf32(sf[ni][0]), to_tf32(sf[ni][1])};
                uint2 p23 = {to_tf32(sf[ni][2]), to_tf32(sf[ni][3])};
                *(uint2*)(&Ps[(w * 16 + g) * FLDP + ni * 8 + tg * 2])     = p01;
                *(uint2*)(&Ps[(w * 16 + 8 + g) * FLDP + ni * 8 + tg * 2]) = p23;
            }
            __syncwarp();

            // ---- rescale O ----
            {
                const u64t a0p = pk2(al0, al0);
                const u64t a1p = pk2(al1, al1);
#pragma unroll
                for (int ni = 0; ni < 16; ni++) {
                    u64t v01 = pk2(of[ni][0], of[ni][1]);
                    u64t v23 = pk2(of[ni][2], of[ni][3]);
                    mul2(v01, v01, a0p);
                    mul2(v23, v23, a1p);
                    const float2 f01 = upk(v01), f23 = upk(v23);
                    of[ni][0] = f01.x; of[ni][1] = f01.y;
                    of[ni][2] = f23.x; of[ni][3] = f23.y;
                }
            }

            // ---- O += P V ----
#pragma unroll
            for (int kc = 0; kc < 8; kc++) {
                uint32_t pa[4];
                pa[0] = Ps[(w * 16 + g) * FLDP + kc * 8 + tg];
                pa[1] = Ps[(w * 16 + 8 + g) * FLDP + kc * 8 + tg];
                pa[2] = Ps[(w * 16 + g) * FLDP + kc * 8 + tg + 4];
                pa[3] = Ps[(w * 16 + 8 + g) * FLDP + kc * 8 + tg + 4];
#pragma unroll
                for (int ni = 0; ni < 16; ni++) {
                    uint32_t vb2[2];
                    vb2[0] = Vb[(kc * 8 + tg) * FLDK + ni * 8 + g];
                    vb2[1] = Vb[(kc * 8 + tg + 4) * FLDK + ni * 8 + g];
                    mma_tf32(of[ni], pa, vb2);
                }
            }
        }
        __syncthreads();   // all reads of buf cur done before next iter's issue
    }

    // ---- normalize + store ----
    const float inv0 = 1.f / l0;
    const float inv1 = 1.f / l1;
    float* y0 = y + ((size_t)(b * Tt_) + grow0) * Cc_ + h * HDv_;
    float* y1 = y + ((size_t)(b * Tt_) + grow1) * Cc_ + h * HDv_;
#pragma unroll
    for (int ni = 0; ni < 16; ni++) {
        const int c0 = ni * 8 + tg * 2;
        float2 v0 = {of[ni][0] * inv0, of[ni][1] * inv0};
        float2 v1 = {of[ni][2] * inv1, of[ni][3] * inv1};
        *(float2*)(y0 + c0) = v0;
        *(float2*)(y1 + c0) = v1;
    }
}

// ---------------------------------------------------------------------------
extern "C" void kernel_launch(void* const* d_in, const int* in_sizes, int n_in,
                              void* d_out, int out_size)
{
    const float* x   = (const float*)d_in[0];
    const float* Wkv = (const float*)d_in[1];
    const float* bkv = (const float*)d_in[2];
    const float* Wq  = (const float*)d_in[3];
    const float* bq  = (const float*)d_in[4];
    const float* Wp  = (const float*)d_in[5];
    const float* bp  = (const float*)d_in[6];
    float* out = (float*)d_out;

    float *qp, *kvp, *yp;
    cudaGetSymbolAddress((void**)&qp,  g_q);
    cudaGetSymbolAddress((void**)&kvp, g_kv);
    cudaGetSymbolAddress((void**)&yp,  g_y);

    cudaFuncSetAttribute(pgemm,
                         cudaFuncAttributeMaxDynamicSharedMemorySize,
                         GEMM_SMEM);
    cudaFuncSetAttribute(flash_cp,
                         cudaFuncAttributeMaxDynamicSharedMemorySize,
                         FLASH_SMEM);

    // q = x @ Wq + bq        (4096 x 2048 x 2048)
    pgemm<<<dim3(Cc_ / 128, Mm_ / 128), 256, GEMM_SMEM>>>(
        Mm_, Cc_, Cc_, x, Wq, bq, qp);
    // kv = x @ Wkv + bkv     (4096 x 1024 x 2048)
    pgemm<<<dim3(KVN_ / 128, Mm_ / 128), 256, GEMM_SMEM>>>(
        Mm_, KVN_, Cc_, x, Wkv, bkv, kvp);
    // attention
    flash_cp<<<dim3(Tt_ / 128, Hh_, Bb_), 256, FLASH_SMEM>>>(qp, kvp, yp);
    // out = y @ Wp + bp      (4096 x 2048 x 2048)
    pgemm<<<dim3(Cc_ / 128, Mm_ / 128), 256, GEMM_SMEM>>>(
        Mm_, Cc_, Cc_, yp, Wp, bp, out);
}

// round 9
// speedup vs baseline: 3.1535x; 1.0241x over previous
#include <cuda_runtime.h>
#include <math.h>
#include <stdint.h>

// Problem constants
#define Bb_ 2
#define Tt_ 2048
#define Cc_ 2048
#define Hh_ 16
#define HKV_ 4
#define HDv_ 128
#define Mm_ (Bb_ * Tt_)
#define KVN_ 1024

// Scratch (device globals; no allocation allowed)
__device__ float g_q[(size_t)Mm_ * Cc_];
__device__ float g_kv[(size_t)Mm_ * KVN_];
__device__ float g_y[(size_t)Mm_ * Cc_];
__device__ float g_xr[(size_t)Mm_ * Cc_];        // tf32-rounded x
__device__ float g_wq[(size_t)Cc_ * Cc_];        // tf32-rounded Wq
__device__ float g_wkv[(size_t)Cc_ * KVN_];      // tf32-rounded Wkv
__device__ float g_wp[(size_t)Cc_ * Cc_];        // tf32-rounded Wp

// ---- helpers ----------------------------------------------------------------
typedef unsigned long long u64t;

__device__ __forceinline__ u64t pk2(float lo, float hi) {
    u64t r;
    asm("mov.b64 %0, {%1, %2};" : "=l"(r) : "f"(lo), "f"(hi));
    return r;
}
__device__ __forceinline__ void mul2(u64t& d, u64t a, u64t b) {
    asm("mul.rn.f32x2 %0, %1, %2;" : "=l"(d) : "l"(a), "l"(b));
}
__device__ __forceinline__ float2 upk(u64t v) {
    float2 f;
    asm("mov.b64 {%0, %1}, %2;" : "=f"(f.x), "=f"(f.y) : "l"(v));
    return f;
}
__device__ __forceinline__ uint32_t to_tf32(float f) {
    uint32_t r;
    asm("cvt.rna.tf32.f32 %0, %1;" : "=r"(r) : "f"(f));
    return r;
}
__device__ __forceinline__ float round_tf32(float f) {
    return __uint_as_float(to_tf32(f));
}
__device__ __forceinline__ void mma_tf32(float (&d)[4],
                                         const uint32_t (&a)[4],
                                         const uint32_t (&b)[2]) {
    asm volatile(
        "mma.sync.aligned.m16n8k8.row.col.f32.tf32.tf32.f32 "
        "{%0,%1,%2,%3}, {%4,%5,%6,%7}, {%8,%9}, {%0,%1,%2,%3};\n"
        : "+f"(d[0]), "+f"(d[1]), "+f"(d[2]), "+f"(d[3])
        : "r"(a[0]), "r"(a[1]), "r"(a[2]), "r"(a[3]), "r"(b[0]), "r"(b[1]));
}
__device__ __forceinline__ uint32_t smem_u32(const void* p) {
    uint32_t a;
    asm("{ .reg .u64 t; cvta.to.shared.u64 t, %1; cvt.u32.u64 %0, t; }"
        : "=r"(a) : "l"(p));
    return a;
}
__device__ __forceinline__ void cp16(uint32_t dst, const void* src) {
    asm volatile("cp.async.cg.shared.global [%0], [%1], 16;"
                 :: "r"(dst), "l"(src));
}
#define CP_COMMIT() asm volatile("cp.async.commit_group;" ::: "memory")
#define CP_WAIT(n)  asm volatile("cp.async.wait_group %0;" :: "n"(n) : "memory")

// ---------------------------------------------------------------------------
// One-time tf32 rounding pass: out[i] = round_tf32(in[i]). n % 1024 == 0.
// ---------------------------------------------------------------------------
__global__ void __launch_bounds__(256)
round_pass(const float* __restrict__ in, float* __restrict__ out)
{
    const size_t i = ((size_t)blockIdx.x * 256 + threadIdx.x) * 4;
    const float4 v = *(const float4*)(in + i);
    float4 o;
    o.x = round_tf32(v.x);
    o.y = round_tf32(v.y);
    o.z = round_tf32(v.z);
    o.w = round_tf32(v.w);
    *(float4*)(out + i) = o;
}

// ---------------------------------------------------------------------------
// tf32 mma.sync GEMM, 4-stage cp.async pipeline, NO inner-loop cvt
// (all operands pre-rounded tf32 in fp32 containers).
// C[M,N] = A[M,K] @ B[K,N] + bias[N]. 128x128 CTA, BK=16, 8 warps (64x32).
// roundOut: 1 -> store tf32-rounded outputs (for downstream MMA consumers).
// ---------------------------------------------------------------------------
#define GSTG 4
#define LDA_S 20
#define LDB_S 132
#define A_WORDS (128 * LDA_S)
#define B_WORDS (16 * LDB_S)
#define STG_WORDS (A_WORDS + B_WORDS)
#define GEMM_SMEM (GSTG * STG_WORDS * 4)

__device__ __forceinline__ void gemm_issue(uint32_t sb, int buf,
                                           const float* Ab, const float* Bb,
                                           int K, int N, int k0, int tid)
{
    const uint32_t base = sb + buf * (STG_WORDS * 4);
#pragma unroll
    for (int u = 0; u < 2; u++) {
        const int ia = tid + u * 256;
        const int m  = ia >> 2;
        const int c4 = (ia & 3) << 2;
        cp16(base + (m * LDA_S + c4) * 4, Ab + (size_t)m * K + k0 + c4);
        const int ib = tid + u * 256;
        const int k  = ib >> 5;
        const int n4 = (ib & 31) << 2;
        cp16(base + (A_WORDS + k * LDB_S + n4) * 4,
             Bb + (size_t)(k0 + k) * N + n4);
    }
}

__global__ void __launch_bounds__(256, 2)
pgemm(int M, int N, int K,
      const float* __restrict__ A, const float* __restrict__ B,
      const float* __restrict__ bias, float* __restrict__ C, int roundOut)
{
    extern __shared__ uint32_t smw[];
    const uint32_t sb = smem_u32(smw);

    const int tid  = threadIdx.x;
    const int wid  = tid >> 5;
    const int lane = tid & 31;
    const int g    = lane >> 2;
    const int tg   = lane & 3;
    const int wm   = wid & 1;
    const int wn   = wid >> 1;

    const float* Ab = A + (size_t)blockIdx.y * 128 * K;
    const float* Bb = B + blockIdx.x * 128;

    float acc[4][4][4];
#pragma unroll
    for (int mi = 0; mi < 4; mi++)
#pragma unroll
        for (int ni = 0; ni < 4; ni++)
#pragma unroll
            for (int r = 0; r < 4; r++) acc[mi][ni][r] = 0.f;

    const int nt = K / 16;

#pragma unroll
    for (int s = 0; s < GSTG - 1; s++) {
        if (s < nt) gemm_issue(sb, s, Ab, Bb, K, N, s * 16, tid);
        CP_COMMIT();
    }

    for (int t = 0; t < nt; ++t) {
        CP_WAIT(2);
        __syncthreads();
        if (t + 3 < nt)
            gemm_issue(sb, (t + 3) & 3, Ab, Bb, K, N, (t + 3) * 16, tid);
        CP_COMMIT();

        const uint32_t* As = smw + (t & 3) * STG_WORDS;
        const uint32_t* Bs = As + A_WORDS;
#pragma unroll
        for (int kc = 0; kc < 2; kc++) {
            uint32_t afr[4][4];
#pragma unroll
            for (int mi = 0; mi < 4; mi++) {
                const int r0 = wm * 64 + mi * 16 + g;
                afr[mi][0] = As[r0 * LDA_S + kc * 8 + tg];
                afr[mi][1] = As[(r0 + 8) * LDA_S + kc * 8 + tg];
                afr[mi][2] = As[r0 * LDA_S + kc * 8 + tg + 4];
                afr[mi][3] = As[(r0 + 8) * LDA_S + kc * 8 + tg + 4];
            }
            uint32_t bfr[4][2];
#pragma unroll
            for (int ni = 0; ni < 4; ni++) {
                const int c0 = wn * 32 + ni * 8 + g;
                bfr[ni][0] = Bs[(kc * 8 + tg) * LDB_S + c0];
                bfr[ni][1] = Bs[(kc * 8 + tg + 4) * LDB_S + c0];
            }
#pragma unroll
            for (int mi = 0; mi < 4; mi++)
#pragma unroll
                for (int ni = 0; ni < 4; ni++)
                    mma_tf32(acc[mi][ni], afr[mi], bfr[ni]);
        }
    }

    // ---- epilogue: fused bias (+ optional tf32 rounding of outputs) ----
#pragma unroll
    for (int mi = 0; mi < 4; mi++) {
        const int r0 = blockIdx.y * 128 + wm * 64 + mi * 16 + g;
#pragma unroll
        for (int ni = 0; ni < 4; ni++) {
            const int c0 = blockIdx.x * 128 + wn * 32 + ni * 8 + tg * 2;
            const float bx0 = bias[c0], bx1 = bias[c0 + 1];
            float2 v0 = {acc[mi][ni][0] + bx0, acc[mi][ni][1] + bx1};
            float2 v1 = {acc[mi][ni][2] + bx0, acc[mi][ni][3] + bx1};
            if (roundOut) {
                v0.x = round_tf32(v0.x); v0.y = round_tf32(v0.y);
                v1.x = round_tf32(v1.x); v1.y = round_tf32(v1.y);
            }
            *(float2*)(C + (size_t)r0 * N + c0)       = v0;
            *(float2*)(C + (size_t)(r0 + 8) * N + c0) = v1;
        }
    }
}

// ---------------------------------------------------------------------------
// Flash attention, tf32 mma.sync, double-buffered cp.async K/V.
// K/V/q are pre-rounded tf32 -> raw operands are lossless.
// Br=128 (8 warps x 16 rows), Bc=64, HD=128. Output tf32-rounded.
// ---------------------------------------------------------------------------
#define FLDK 132
#define KV_WORDS (64 * FLDK)
#define STG_F (2 * KV_WORDS)
#define PSo (2 * STG_F)
#define FLDP 68
#define FLASH_SMEM ((PSo + 128 * FLDP) * 4)

__device__ __forceinline__ void flash_issue(uint32_t sb, int buf,
                                            const float* kvbase, int tid)
{
    const uint32_t kb = sb + buf * (STG_F * 4);
    const uint32_t vb = kb + KV_WORDS * 4;
#pragma unroll
    for (int u = 0; u < 8; u++) {
        const int i  = tid + u * 256;
        const int r  = i >> 5;
        const int c4 = (i & 31) << 2;
        const float* src = kvbase + (size_t)r * KVN_ + c4;
        cp16(kb + (r * FLDK + c4) * 4, src);
        cp16(vb + (r * FLDK + c4) * 4, src + 512);
    }
}

__global__ void __launch_bounds__(256, 1)
flash_cp(const float* __restrict__ q, const float* __restrict__ kv,
         float* __restrict__ y)
{
    extern __shared__ uint32_t smw[];
    const uint32_t sb = smem_u32(smw);
    uint32_t* Ps = smw + PSo;

    const int qt = blockIdx.x;
    const int h  = blockIdx.y;
    const int b  = blockIdx.z;
    const int kvh = h & (HKV_ - 1);

    const int tid  = threadIdx.x;
    const int w    = tid >> 5;
    const int lane = tid & 31;
    const int g    = lane >> 2;
    const int tg   = lane & 3;
    const float scale = 0.08838834764831843f;

    const int rloc0 = w * 16 + g;
    const int grow0 = qt * 128 + rloc0;
    const int grow1 = grow0 + 8;

    // Q (pre-rounded) * scale, re-rounded to tf32 fragments
    uint32_t qf[16][4];
    {
        const float* qb = q + ((size_t)(b * Tt_) + qt * 128 + w * 16) * Cc_
                            + h * HDv_;
#pragma unroll
        for (int kc = 0; kc < 16; kc++) {
            const int d0 = kc * 8 + tg;
            qf[kc][0] = to_tf32(qb[(size_t)g * Cc_ + d0] * scale);
            qf[kc][1] = to_tf32(qb[(size_t)(g + 8) * Cc_ + d0] * scale);
            qf[kc][2] = to_tf32(qb[(size_t)g * Cc_ + d0 + 4] * scale);
            qf[kc][3] = to_tf32(qb[(size_t)(g + 8) * Cc_ + d0 + 4] * scale);
        }
    }

    float of[16][4];
#pragma unroll
    for (int ni = 0; ni < 16; ni++)
#pragma unroll
        for (int r = 0; r < 4; r++) of[ni][r] = 0.f;
    float m0 = -INFINITY, m1 = -INFINITY, l0 = 0.f, l1 = 0.f;

    const int ktmax = 2 * qt + 1;
    const float* kvb0 = kv + (size_t)(b * Tt_) * KVN_ + kvh * HDv_;

    flash_issue(sb, 0, kvb0, tid);
    CP_COMMIT();

    for (int kt = 0; kt <= ktmax; ++kt) {
        const int cur = kt & 1;
        if (kt < ktmax)
            flash_issue(sb, cur ^ 1, kvb0 + (size_t)(kt + 1) * 64 * KVN_, tid);
        CP_COMMIT();
        CP_WAIT(1);
        __syncthreads();

        const uint32_t* Kb = smw + cur * STG_F;
        const uint32_t* Vb = Kb + KV_WORDS;

        const bool act = (kt * 64) <= (qt * 128 + w * 16 + 15);
        if (act) {
            float sf[8][4];
#pragma unroll
            for (int ni = 0; ni < 8; ni++)
#pragma unroll
                for (int r = 0; r < 4; r++) sf[ni][r] = 0.f;

#pragma unroll
            for (int kc = 0; kc < 16; kc++) {
#pragma unroll
                for (int ni = 0; ni < 8; ni++) {
                    uint32_t bfr[2];
                    bfr[0] = Kb[(ni * 8 + g) * FLDK + kc * 8 + tg];
                    bfr[1] = Kb[(ni * 8 + g) * FLDK + kc * 8 + tg + 4];
                    mma_tf32(sf[ni], qf[kc], bfr);
                }
            }

            if (kt * 64 + 63 > qt * 128 + w * 16) {
                const int cb = kt * 64;
#pragma unroll
                for (int ni = 0; ni < 8; ni++) {
                    const int c0 = cb + ni * 8 + tg * 2;
                    if (c0 > grow0)     sf[ni][0] = -1e30f;
                    if (c0 + 1 > grow0) sf[ni][1] = -1e30f;
                    if (c0 > grow1)     sf[ni][2] = -1e30f;
                    if (c0 + 1 > grow1) sf[ni][3] = -1e30f;
                }
            }

            float mx0 = -1e30f, mx1 = -1e30f;
#pragma unroll
            for (int ni = 0; ni < 8; ni++) {
                mx0 = fmaxf(mx0, fmaxf(sf[ni][0], sf[ni][1]));
                mx1 = fmaxf(mx1, fmaxf(sf[ni][2], sf[ni][3]));
            }
            mx0 = fmaxf(mx0, __shfl_xor_sync(0xffffffffu, mx0, 1));
            mx0 = fmaxf(mx0, __shfl_xor_sync(0xffffffffu, mx0, 2));
            mx1 = fmaxf(mx1, __shfl_xor_sync(0xffffffffu, mx1, 1));
            mx1 = fmaxf(mx1, __shfl_xor_sync(0xffffffffu, mx1, 2));

            const float nm0 = fmaxf(m0, mx0);
            const float nm1 = fmaxf(m1, mx1);
            float sum0 = 0.f, sum1 = 0.f;
#pragma unroll
            for (int ni = 0; ni < 8; ni++) {
                sf[ni][0] = __expf(sf[ni][0] - nm0);
                sf[ni][1] = __expf(sf[ni][1] - nm0);
                sf[ni][2] = __expf(sf[ni][2] - nm1);
                sf[ni][3] = __expf(sf[ni][3] - nm1);
                sum0 += sf[ni][0] + sf[ni][1];
                sum1 += sf[ni][2] + sf[ni][3];
            }
            sum0 += __shfl_xor_sync(0xffffffffu, sum0, 1);
            sum0 += __shfl_xor_sync(0xffffffffu, sum0, 2);
            sum1 += __shfl_xor_sync(0xffffffffu, sum1, 1);
            sum1 += __shfl_xor_sync(0xffffffffu, sum1, 2);

            const float al0 = __expf(m0 - nm0);
            const float al1 = __expf(m1 - nm1);
            m0 = nm0; m1 = nm1;
            l0 = l0 * al0 + sum0;
            l1 = l1 * al1 + sum1;

#pragma unroll
            for (int ni = 0; ni < 8; ni++) {
                uint2 p01 = {to_tf32(sf[ni][0]), to_tf32(sf[ni][1])};
                uint2 p23 = {to_tf32(sf[ni][2]), to_tf32(sf[ni][3])};
                *(uint2*)(&Ps[(w * 16 + g) * FLDP + ni * 8 + tg * 2])     = p01;
                *(uint2*)(&Ps[(w * 16 + 8 + g) * FLDP + ni * 8 + tg * 2]) = p23;
            }
            __syncwarp();

            {
                const u64t a0p = pk2(al0, al0);
                const u64t a1p = pk2(al1, al1);
#pragma unroll
                for (int ni = 0; ni < 16; ni++) {
                    u64t v01 = pk2(of[ni][0], of[ni][1]);
                    u64t v23 = pk2(of[ni][2], of[ni][3]);
                    mul2(v01, v01, a0p);
                    mul2(v23, v23, a1p);
                    const float2 f01 = upk(v01), f23 = upk(v23);
                    of[ni][0] = f01.x; of[ni][1] = f01.y;
                    of[ni][2] = f23.x; of[ni][3] = f23.y;
                }
            }

#pragma unroll
            for (int kc = 0; kc < 8; kc++) {
                uint32_t pa[4];
                pa[0] = Ps[(w * 16 + g) * FLDP + kc * 8 + tg];
                pa[1] = Ps[(w * 16 + 8 + g) * FLDP + kc * 8 + tg];
                pa[2] = Ps[(w * 16 + g) * FLDP + kc * 8 + tg + 4];
                pa[3] = Ps[(w * 16 + 8 + g) * FLDP + kc * 8 + tg + 4];
#pragma unroll
                for (int ni = 0; ni < 16; ni++) {
                    uint32_t vb2[2];
                    vb2[0] = Vb[(kc * 8 + tg) * FLDK + ni * 8 + g];
                    vb2[1] = Vb[(kc * 8 + tg + 4) * FLDK + ni * 8 + g];
                    mma_tf32(of[ni], pa, vb2);
                }
            }
        }
        __syncthreads();
    }

    // ---- normalize + tf32-round + store (y feeds final GEMM as A) ----
    const float inv0 = 1.f / l0;
    const float inv1 = 1.f / l1;
    float* y0 = y + ((size_t)(b * Tt_) + grow0) * Cc_ + h * HDv_;
    float* y1 = y + ((size_t)(b * Tt_) + grow1) * Cc_ + h * HDv_;
#pragma unroll
    for (int ni = 0; ni < 16; ni++) {
        const int c0 = ni * 8 + tg * 2;
        float2 v0 = {round_tf32(of[ni][0] * inv0), round_tf32(of[ni][1] * inv0)};
        float2 v1 = {round_tf32(of[ni][2] * inv1), round_tf32(of[ni][3] * inv1)};
        *(float2*)(y0 + c0) = v0;
        *(float2*)(y1 + c0) = v1;
    }
}

// ---------------------------------------------------------------------------
extern "C" void kernel_launch(void* const* d_in, const int* in_sizes, int n_in,
                              void* d_out, int out_size)
{
    const float* x   = (const float*)d_in[0];
    const float* Wkv = (const float*)d_in[1];
    const float* bkv = (const float*)d_in[2];
    const float* Wq  = (const float*)d_in[3];
    const float* bq  = (const float*)d_in[4];
    const float* Wp  = (const float*)d_in[5];
    const float* bp  = (const float*)d_in[6];
    float* out = (float*)d_out;

    float *qp, *kvp, *yp, *xr, *wq, *wkv, *wp;
    cudaGetSymbolAddress((void**)&qp,  g_q);
    cudaGetSymbolAddress((void**)&kvp, g_kv);
    cudaGetSymbolAddress((void**)&yp,  g_y);
    cudaGetSymbolAddress((void**)&xr,  g_xr);
    cudaGetSymbolAddress((void**)&wq,  g_wq);
    cudaGetSymbolAddress((void**)&wkv, g_wkv);
    cudaGetSymbolAddress((void**)&wp,  g_wp);

    cudaFuncSetAttribute(pgemm,
                         cudaFuncAttributeMaxDynamicSharedMemorySize,
                         GEMM_SMEM);
    cudaFuncSetAttribute(flash_cp,
                         cudaFuncAttributeMaxDynamicSharedMemorySize,
                         FLASH_SMEM);

    // one-time tf32 rounding of all GEMM inputs
    round_pass<<<(Mm_ * Cc_) / 1024, 256>>>(x, xr);
    round_pass<<<(Cc_ * Cc_) / 1024, 256>>>(Wq, wq);
    round_pass<<<(Cc_ * KVN_) / 1024, 256>>>(Wkv, wkv);
    round_pass<<<(Cc_ * Cc_) / 1024, 256>>>(Wp, wp);

    // q = x @ Wq + bq   (rounded output -> flash operand)
    pgemm<<<dim3(Cc_ / 128, Mm_ / 128), 256, GEMM_SMEM>>>(
        Mm_, Cc_, Cc_, xr, wq, bq, qp, 1);
    // kv = x @ Wkv + bkv (rounded output -> flash operand)
    pgemm<<<dim3(KVN_ / 128, Mm_ / 128), 256, GEMM_SMEM>>>(
        Mm_, KVN_, Cc_, xr, wkv, bkv, kvp, 1);
    // attention (y rounded inside)
    flash_cp<<<dim3(Tt_ / 128, Hh_, Bb_), 256, FLASH_SMEM>>>(qp, kvp, yp);
    // out = y @ Wp + bp (exact fp32 output)
    pgemm<<<dim3(Cc_ / 128, Mm_ / 128), 256, GEMM_SMEM>>>(
        Mm_, Cc_, Cc_, yp, wp, bp, out, 0);
}

// round 10
// speedup vs baseline: 3.3598x; 1.0654x over previous
#include <cuda_runtime.h>
#include <math.h>
#include <stdint.h>

// Problem constants
#define Bb_ 2
#define Tt_ 2048
#define Cc_ 2048
#define Hh_ 16
#define HKV_ 4
#define HDv_ 128
#define Mm_ (Bb_ * Tt_)
#define KVN_ 1024

// Scratch (device globals; no allocation allowed)
__device__ float g_q[(size_t)Mm_ * Cc_];
__device__ float g_kv[(size_t)Mm_ * KVN_];
__device__ float g_y[(size_t)Mm_ * Cc_];
__device__ float g_xr[(size_t)Mm_ * Cc_];        // tf32-rounded x
__device__ float g_wq[(size_t)Cc_ * Cc_];        // tf32-rounded Wq
__device__ float g_wkv[(size_t)Cc_ * KVN_];      // tf32-rounded Wkv
__device__ float g_wp[(size_t)Cc_ * Cc_];        // tf32-rounded Wp

// ---- helpers ----------------------------------------------------------------
typedef unsigned long long u64t;

__device__ __forceinline__ u64t pk2(float lo, float hi) {
    u64t r;
    asm("mov.b64 %0, {%1, %2};" : "=l"(r) : "f"(lo), "f"(hi));
    return r;
}
__device__ __forceinline__ void mul2(u64t& d, u64t a, u64t b) {
    asm("mul.rn.f32x2 %0, %1, %2;" : "=l"(d) : "l"(a), "l"(b));
}
__device__ __forceinline__ float2 upk(u64t v) {
    float2 f;
    asm("mov.b64 {%0, %1}, %2;" : "=f"(f.x), "=f"(f.y) : "l"(v));
    return f;
}
__device__ __forceinline__ uint32_t to_tf32(float f) {
    uint32_t r;
    asm("cvt.rna.tf32.f32 %0, %1;" : "=r"(r) : "f"(f));
    return r;
}
__device__ __forceinline__ float round_tf32(float f) {
    return __uint_as_float(to_tf32(f));
}
__device__ __forceinline__ void mma_tf32(float (&d)[4],
                                         const uint32_t (&a)[4],
                                         const uint32_t (&b)[2]) {
    asm volatile(
        "mma.sync.aligned.m16n8k8.row.col.f32.tf32.tf32.f32 "
        "{%0,%1,%2,%3}, {%4,%5,%6,%7}, {%8,%9}, {%0,%1,%2,%3};\n"
        : "+f"(d[0]), "+f"(d[1]), "+f"(d[2]), "+f"(d[3])
        : "r"(a[0]), "r"(a[1]), "r"(a[2]), "r"(a[3]), "r"(b[0]), "r"(b[1]));
}
__device__ __forceinline__ uint32_t smem_u32(const void* p) {
    uint32_t a;
    asm("{ .reg .u64 t; cvta.to.shared.u64 t, %1; cvt.u32.u64 %0, t; }"
        : "=r"(a) : "l"(p));
    return a;
}
__device__ __forceinline__ void cp16(uint32_t dst, const void* src) {
    asm volatile("cp.async.cg.shared.global [%0], [%1], 16;"
                 :: "r"(dst), "l"(src));
}
#define CP_COMMIT() asm volatile("cp.async.commit_group;" ::: "memory")
#define CP_WAIT(n)  asm volatile("cp.async.wait_group %0;" :: "n"(n) : "memory")

// ---------------------------------------------------------------------------
// One-time tf32 rounding pass.
// ---------------------------------------------------------------------------
__global__ void __launch_bounds__(256)
round_pass(const float* __restrict__ in, float* __restrict__ out)
{
    const size_t i = ((size_t)blockIdx.x * 256 + threadIdx.x) * 4;
    const float4 v = *(const float4*)(in + i);
    float4 o;
    o.x = round_tf32(v.x);
    o.y = round_tf32(v.y);
    o.z = round_tf32(v.z);
    o.w = round_tf32(v.w);
    *(float4*)(out + i) = o;
}

// ---------------------------------------------------------------------------
// tf32 mma.sync GEMM, BK=32 stages, 3-stage cp.async pipeline, no inner cvt.
// C[M,N] = A[M,K] @ B[K,N] + bias[N]. 128x128 CTA, 8 warps (64x32 warp tile).
// Stage: A [128][36] raw fp32 (pre-rounded tf32), B [32][132].
// One __syncthreads + one wait per 32 K (half of R9's barrier count).
// ---------------------------------------------------------------------------
#define GSTG 3
#define LDA_S 36
#define LDB_S 132
#define A_WORDS (128 * LDA_S)            // 4608
#define B_WORDS (32 * LDB_S)             // 4224
#define STG_WORDS (A_WORDS + B_WORDS)    // 8832
#define GEMM_SMEM (GSTG * STG_WORDS * 4) // 105984 B

__device__ __forceinline__ void gemm_issue(uint32_t sb, int buf,
                                           const float* Ab, const float* Bb,
                                           int K, int N, int k0, int tid)
{
    const uint32_t base = sb + buf * (STG_WORDS * 4);
#pragma unroll
    for (int u = 0; u < 4; u++) {
        const int ia = tid + u * 256;          // 0..1023
        const int m  = ia >> 3;
        const int c4 = (ia & 7) << 2;
        cp16(base + (m * LDA_S + c4) * 4, Ab + (size_t)m * K + k0 + c4);
        const int ib = tid + u * 256;
        const int k  = ib >> 5;
        const int n4 = (ib & 31) << 2;
        cp16(base + (A_WORDS + k * LDB_S + n4) * 4,
             Bb + (size_t)(k0 + k) * N + n4);
    }
}

__global__ void __launch_bounds__(256, 2)
pgemm(int M, int N, int K,
      const float* __restrict__ A, const float* __restrict__ B,
      const float* __restrict__ bias, float* __restrict__ C, int roundOut)
{
    extern __shared__ uint32_t smw[];
    const uint32_t sb = smem_u32(smw);

    const int tid  = threadIdx.x;
    const int wid  = tid >> 5;
    const int lane = tid & 31;
    const int g    = lane >> 2;
    const int tg   = lane & 3;
    const int wm   = wid & 1;
    const int wn   = wid >> 1;

    const float* Ab = A + (size_t)blockIdx.y * 128 * K;
    const float* Bb = B + blockIdx.x * 128;

    float acc[4][4][4];
#pragma unroll
    for (int mi = 0; mi < 4; mi++)
#pragma unroll
        for (int ni = 0; ni < 4; ni++)
#pragma unroll
            for (int r = 0; r < 4; r++) acc[mi][ni][r] = 0.f;

    const int nt = K / 32;

    // prologue: issue tiles 0,1
#pragma unroll
    for (int s = 0; s < GSTG - 1; s++) {
        if (s < nt) gemm_issue(sb, s, Ab, Bb, K, N, s * 32, tid);
        CP_COMMIT();
    }

    int buf = 0;
    for (int t = 0; t < nt; ++t) {
        CP_WAIT(1);          // outstanding {t, t+1} -> tile t resident
        __syncthreads();     // also guards reuse of buffer (t+2)%3
        if (t + 2 < nt)
            gemm_issue(sb, (t + 2) % GSTG, Ab, Bb, K, N, (t + 2) * 32, tid);
        CP_COMMIT();

        const uint32_t* As = smw + buf * STG_WORDS;
        const uint32_t* Bs = As + A_WORDS;
#pragma unroll
        for (int kc = 0; kc < 4; kc++) {
            uint32_t afr[4][4];
#pragma unroll
            for (int mi = 0; mi < 4; mi++) {
                const int r0 = wm * 64 + mi * 16 + g;
                afr[mi][0] = As[r0 * LDA_S + kc * 8 + tg];
                afr[mi][1] = As[(r0 + 8) * LDA_S + kc * 8 + tg];
                afr[mi][2] = As[r0 * LDA_S + kc * 8 + tg + 4];
                afr[mi][3] = As[(r0 + 8) * LDA_S + kc * 8 + tg + 4];
            }
            uint32_t bfr[4][2];
#pragma unroll
            for (int ni = 0; ni < 4; ni++) {
                const int c0 = wn * 32 + ni * 8 + g;
                bfr[ni][0] = Bs[(kc * 8 + tg) * LDB_S + c0];
                bfr[ni][1] = Bs[(kc * 8 + tg + 4) * LDB_S + c0];
            }
#pragma unroll
            for (int mi = 0; mi < 4; mi++)
#pragma unroll
                for (int ni = 0; ni < 4; ni++)
                    mma_tf32(acc[mi][ni], afr[mi], bfr[ni]);
        }
        buf = (buf + 1 == GSTG) ? 0 : buf + 1;
    }

    // ---- epilogue: fused bias (+ optional tf32 rounding) ----
#pragma unroll
    for (int mi = 0; mi < 4; mi++) {
        const int r0 = blockIdx.y * 128 + wm * 64 + mi * 16 + g;
#pragma unroll
        for (int ni = 0; ni < 4; ni++) {
            const int c0 = blockIdx.x * 128 + wn * 32 + ni * 8 + tg * 2;
            const float bx0 = bias[c0], bx1 = bias[c0 + 1];
            float2 v0 = {acc[mi][ni][0] + bx0, acc[mi][ni][1] + bx1};
            float2 v1 = {acc[mi][ni][2] + bx0, acc[mi][ni][3] + bx1};
            if (roundOut) {
                v0.x = round_tf32(v0.x); v0.y = round_tf32(v0.y);
                v1.x = round_tf32(v1.x); v1.y = round_tf32(v1.y);
            }
            *(float2*)(C + (size_t)r0 * N + c0)       = v0;
            *(float2*)(C + (size_t)(r0 + 8) * N + c0) = v1;
        }
    }
}

// ---------------------------------------------------------------------------
// Flash attention, tf32 mma.sync, double-buffered cp.async K/V (operands
// pre-rounded tf32 -> raw loads lossless). Br=128, Bc=64, HD=128.
// ---------------------------------------------------------------------------
#define FLDK 132
#define KV_WORDS (64 * FLDK)
#define STG_F (2 * KV_WORDS)
#define PSo (2 * STG_F)
#define FLDP 68
#define FLASH_SMEM ((PSo + 128 * FLDP) * 4)

__device__ __forceinline__ void flash_issue(uint32_t sb, int buf,
                                            const float* kvbase, int tid)
{
    const uint32_t kb = sb + buf * (STG_F * 4);
    const uint32_t vb = kb + KV_WORDS * 4;
#pragma unroll
    for (int u = 0; u < 8; u++) {
        const int i  = tid + u * 256;
        const int r  = i >> 5;
        const int c4 = (i & 31) << 2;
        const float* src = kvbase + (size_t)r * KVN_ + c4;
        cp16(kb + (r * FLDK + c4) * 4, src);
        cp16(vb + (r * FLDK + c4) * 4, src + 512);
    }
}

__global__ void __launch_bounds__(256, 1)
flash_cp(const float* __restrict__ q, const float* __restrict__ kv,
         float* __restrict__ y)
{
    extern __shared__ uint32_t smw[];
    const uint32_t sb = smem_u32(smw);
    uint32_t* Ps = smw + PSo;

    const int qt = blockIdx.x;
    const int h  = blockIdx.y;
    const int b  = blockIdx.z;
    const int kvh = h & (HKV_ - 1);

    const int tid  = threadIdx.x;
    const int w    = tid >> 5;
    const int lane = tid & 31;
    const int g    = lane >> 2;
    const int tg   = lane & 3;
    const float scale = 0.08838834764831843f;

    const int rloc0 = w * 16 + g;
    const int grow0 = qt * 128 + rloc0;
    const int grow1 = grow0 + 8;

    uint32_t qf[16][4];
    {
        const float* qb = q + ((size_t)(b * Tt_) + qt * 128 + w * 16) * Cc_
                            + h * HDv_;
#pragma unroll
        for (int kc = 0; kc < 16; kc++) {
            const int d0 = kc * 8 + tg;
            qf[kc][0] = to_tf32(qb[(size_t)g * Cc_ + d0] * scale);
            qf[kc][1] = to_tf32(qb[(size_t)(g + 8) * Cc_ + d0] * scale);
            qf[kc][2] = to_tf32(qb[(size_t)g * Cc_ + d0 + 4] * scale);
            qf[kc][3] = to_tf32(qb[(size_t)(g + 8) * Cc_ + d0 + 4] * scale);
        }
    }

    float of[16][4];
#pragma unroll
    for (int ni = 0; ni < 16; ni++)
#pragma unroll
        for (int r = 0; r < 4; r++) of[ni][r] = 0.f;
    float m0 = -INFINITY, m1 = -INFINITY, l0 = 0.f, l1 = 0.f;

    const int ktmax = 2 * qt + 1;
    const float* kvb0 = kv + (size_t)(b * Tt_) * KVN_ + kvh * HDv_;

    flash_issue(sb, 0, kvb0, tid);
    CP_COMMIT();

    for (int kt = 0; kt <= ktmax; ++kt) {
        const int cur = kt & 1;
        if (kt < ktmax)
            flash_issue(sb, cur ^ 1, kvb0 + (size_t)(kt + 1) * 64 * KVN_, tid);
        CP_COMMIT();
        CP_WAIT(1);
        __syncthreads();

        const uint32_t* Kb = smw + cur * STG_F;
        const uint32_t* Vb = Kb + KV_WORDS;

        const bool act = (kt * 64) <= (qt * 128 + w * 16 + 15);
        if (act) {
            float sf[8][4];
#pragma unroll
            for (int ni = 0; ni < 8; ni++)
#pragma unroll
                for (int r = 0; r < 4; r++) sf[ni][r] = 0.f;

#pragma unroll
            for (int kc = 0; kc < 16; kc++) {
#pragma unroll
                for (int ni = 0; ni < 8; ni++) {
                    uint32_t bfr[2];
                    bfr[0] = Kb[(ni * 8 + g) * FLDK + kc * 8 + tg];
                    bfr[1] = Kb[(ni * 8 + g) * FLDK + kc * 8 + tg + 4];
                    mma_tf32(sf[ni], qf[kc], bfr);
                }
            }

            if (kt * 64 + 63 > qt * 128 + w * 16) {
                const int cb = kt * 64;
#pragma unroll
                for (int ni = 0; ni < 8; ni++) {
                    const int c0 = cb + ni * 8 + tg * 2;
                    if (c0 > grow0)     sf[ni][0] = -1e30f;
                    if (c0 + 1 > grow0) sf[ni][1] = -1e30f;
                    if (c0 > grow1)     sf[ni][2] = -1e30f;
                    if (c0 + 1 > grow1) sf[ni][3] = -1e30f;
                }
            }

            float mx0 = -1e30f, mx1 = -1e30f;
#pragma unroll
            for (int ni = 0; ni < 8; ni++) {
                mx0 = fmaxf(mx0, fmaxf(sf[ni][0], sf[ni][1]));
                mx1 = fmaxf(mx1, fmaxf(sf[ni][2], sf[ni][3]));
            }
            mx0 = fmaxf(mx0, __shfl_xor_sync(0xffffffffu, mx0, 1));
            mx0 = fmaxf(mx0, __shfl_xor_sync(0xffffffffu, mx0, 2));
            mx1 = fmaxf(mx1, __shfl_xor_sync(0xffffffffu, mx1, 1));
            mx1 = fmaxf(mx1, __shfl_xor_sync(0xffffffffu, mx1, 2));

            const float nm0 = fmaxf(m0, mx0);
            const float nm1 = fmaxf(m1, mx1);
            float sum0 = 0.f, sum1 = 0.f;
#pragma unroll
            for (int ni = 0; ni < 8; ni++) {
                sf[ni][0] = __expf(sf[ni][0] - nm0);
                sf[ni][1] = __expf(sf[ni][1] - nm0);
                sf[ni][2] = __expf(sf[ni][2] - nm1);
                sf[ni][3] = __expf(sf[ni][3] - nm1);
                sum0 += sf[ni][0] + sf[ni][1];
                sum1 += sf[ni][2] + sf[ni][3];
            }
            sum0 += __shfl_xor_sync(0xffffffffu, sum0, 1);
            sum0 += __shfl_xor_sync(0xffffffffu, sum0, 2);
            sum1 += __shfl_xor_sync(0xffffffffu, sum1, 1);
            sum1 += __shfl_xor_sync(0xffffffffu, sum1, 2);

            const float al0 = __expf(m0 - nm0);
            const float al1 = __expf(m1 - nm1);
            m0 = nm0; m1 = nm1;
            l0 = l0 * al0 + sum0;
            l1 = l1 * al1 + sum1;

#pragma unroll
            for (int ni = 0; ni < 8; ni++) {
                uint2 p01 = {to_tf32(sf[ni][0]), to_tf32(sf[ni][1])};
                uint2 p23 = {to_tf32(sf[ni][2]), to_tf32(sf[ni][3])};
                *(uint2*)(&Ps[(w * 16 + g) * FLDP + ni * 8 + tg * 2])     = p01;
                *(uint2*)(&Ps[(w * 16 + 8 + g) * FLDP + ni * 8 + tg * 2]) = p23;
            }
            __syncwarp();

            {
                const u64t a0p = pk2(al0, al0);
                const u64t a1p = pk2(al1, al1);
#pragma unroll
                for (int ni = 0; ni < 16; ni++) {
                    u64t v01 = pk2(of[ni][0], of[ni][1]);
                    u64t v23 = pk2(of[ni][2], of[ni][3]);
                    mul2(v01, v01, a0p);
                    mul2(v23, v23, a1p);
                    const float2 f01 = upk(v01), f23 = upk(v23);
                    of[ni][0] = f01.x; of[ni][1] = f01.y;
                    of[ni][2] = f23.x; of[ni][3] = f23.y;
                }
            }

#pragma unroll
            for (int kc = 0; kc < 8; kc++) {
                uint32_t pa[4];
                pa[0] = Ps[(w * 16 + g) * FLDP + kc * 8 + tg];
                pa[1] = Ps[(w * 16 + 8 + g) * FLDP + kc * 8 + tg];
                pa[2] = Ps[(w * 16 + g) * FLDP + kc * 8 + tg + 4];
                pa[3] = Ps[(w * 16 + 8 + g) * FLDP + kc * 8 + tg + 4];
#pragma unroll
                for (int ni = 0; ni < 16; ni++) {
                    uint32_t vb2[2];
                    vb2[0] = Vb[(kc * 8 + tg) * FLDK + ni * 8 + g];
                    vb2[1] = Vb[(kc * 8 + tg + 4) * FLDK + ni * 8 + g];
                    mma_tf32(of[ni], pa, vb2);
                }
            }
        }
        __syncthreads();
    }

    const float inv0 = 1.f / l0;
    const float inv1 = 1.f / l1;
    float* y0 = y + ((size_t)(b * Tt_) + grow0) * Cc_ + h * HDv_;
    float* y1 = y + ((size_t)(b * Tt_) + grow1) * Cc_ + h * HDv_;
#pragma unroll
    for (int ni = 0; ni < 16; ni++) {
        const int c0 = ni * 8 + tg * 2;
        float2 v0 = {round_tf32(of[ni][0] * inv0), round_tf32(of[ni][1] * inv0)};
        float2 v1 = {round_tf32(of[ni][2] * inv1), round_tf32(of[ni][3] * inv1)};
        *(float2*)(y0 + c0) = v0;
        *(float2*)(y1 + c0) = v1;
    }
}

// ---------------------------------------------------------------------------
extern "C" void kernel_launch(void* const* d_in, const int* in_sizes, int n_in,
                              void* d_out, int out_size)
{
    const float* x   = (const float*)d_in[0];
    const float* Wkv = (const float*)d_in[1];
    const float* bkv = (const float*)d_in[2];
    const float* Wq  = (const float*)d_in[3];
    const float* bq  = (const float*)d_in[4];
    const float* Wp  = (const float*)d_in[5];
    const float* bp  = (const float*)d_in[6];
    float* out = (float*)d_out;

    float *qp, *kvp, *yp, *xr, *wq, *wkv, *wp;
    cudaGetSymbolAddress((void**)&qp,  g_q);
    cudaGetSymbolAddress((void**)&kvp, g_kv);
    cudaGetSymbolAddress((void**)&yp,  g_y);
    cudaGetSymbolAddress((void**)&xr,  g_xr);
    cudaGetSymbolAddress((void**)&wq,  g_wq);
    cudaGetSymbolAddress((void**)&wkv, g_wkv);
    cudaGetSymbolAddress((void**)&wp,  g_wp);

    cudaFuncSetAttribute(pgemm,
                         cudaFuncAttributeMaxDynamicSharedMemorySize,
                         GEMM_SMEM);
    cudaFuncSetAttribute(flash_cp,
                         cudaFuncAttributeMaxDynamicSharedMemorySize,
                         FLASH_SMEM);

    // one-time tf32 rounding of all GEMM inputs
    round_pass<<<(Mm_ * Cc_) / 1024, 256>>>(x, xr);
    round_pass<<<(Cc_ * Cc_) / 1024, 256>>>(Wq, wq);
    round_pass<<<(Cc_ * KVN_) / 1024, 256>>>(Wkv, wkv);
    round_pass<<<(Cc_ * Cc_) / 1024, 256>>>(Wp, wp);

    // q = x @ Wq + bq   (rounded output -> flash operand)
    pgemm<<<dim3(Cc_ / 128, Mm_ / 128), 256, GEMM_SMEM>>>(
        Mm_, Cc_, Cc_, xr, wq, bq, qp, 1);
    // kv = x @ Wkv + bkv (rounded output -> flash operand)
    pgemm<<<dim3(KVN_ / 128, Mm_ / 128), 256, GEMM_SMEM>>>(
        Mm_, KVN_, Cc_, xr, wkv, bkv, kvp, 1);
    // attention (y rounded inside)
    flash_cp<<<dim3(Tt_ / 128, Hh_, Bb_), 256, FLASH_SMEM>>>(qp, kvp, yp);
    // out = y @ Wp + bp (exact fp32 output)
    pgemm<<<dim3(Cc_ / 128, Mm_ / 128), 256, GEMM_SMEM>>>(
        Mm_, Cc_, Cc_, yp, wp, bp, out, 0);
}

// round 11
// speedup vs baseline: 3.4391x; 1.0236x over previous
#include <cuda_runtime.h>
#include <math.h>
#include <stdint.h>

// Problem constants
#define Bb_ 2
#define Tt_ 2048
#define Cc_ 2048
#define Hh_ 16
#define HKV_ 4
#define HDv_ 128
#define Mm_ (Bb_ * Tt_)
#define KVN_ 1024

// Scratch (device globals; no allocation allowed)
__device__ float g_q[(size_t)Mm_ * Cc_];
__device__ float g_kv[(size_t)Mm_ * KVN_];
__device__ float g_y[(size_t)Mm_ * Cc_];
__device__ float g_xr[(size_t)Mm_ * Cc_];        // tf32-rounded x
__device__ float g_wq[(size_t)Cc_ * Cc_];        // tf32-rounded Wq
__device__ float g_wkv[(size_t)Cc_ * KVN_];      // tf32-rounded Wkv
__device__ float g_wp[(size_t)Cc_ * Cc_];        // tf32-rounded Wp

// ---- helpers ----------------------------------------------------------------
typedef unsigned long long u64t;

__device__ __forceinline__ u64t pk2(float lo, float hi) {
    u64t r;
    asm("mov.b64 %0, {%1, %2};" : "=l"(r) : "f"(lo), "f"(hi));
    return r;
}
__device__ __forceinline__ void mul2(u64t& d, u64t a, u64t b) {
    asm("mul.rn.f32x2 %0, %1, %2;" : "=l"(d) : "l"(a), "l"(b));
}
__device__ __forceinline__ float2 upk(u64t v) {
    float2 f;
    asm("mov.b64 {%0, %1}, %2;" : "=f"(f.x), "=f"(f.y) : "l"(v));
    return f;
}
__device__ __forceinline__ uint32_t to_tf32(float f) {
    uint32_t r;
    asm("cvt.rna.tf32.f32 %0, %1;" : "=r"(r) : "f"(f));
    return r;
}
__device__ __forceinline__ float round_tf32(float f) {
    return __uint_as_float(to_tf32(f));
}
__device__ __forceinline__ void mma_tf32(float (&d)[4],
                                         const uint32_t (&a)[4],
                                         const uint32_t (&b)[2]) {
    asm volatile(
        "mma.sync.aligned.m16n8k8.row.col.f32.tf32.tf32.f32 "
        "{%0,%1,%2,%3}, {%4,%5,%6,%7}, {%8,%9}, {%0,%1,%2,%3};\n"
        : "+f"(d[0]), "+f"(d[1]), "+f"(d[2]), "+f"(d[3])
        : "r"(a[0]), "r"(a[1]), "r"(a[2]), "r"(a[3]), "r"(b[0]), "r"(b[1]));
}
__device__ __forceinline__ uint32_t smem_u32(const void* p) {
    uint32_t a;
    asm("{ .reg .u64 t; cvta.to.shared.u64 t, %1; cvt.u32.u64 %0, t; }"
        : "=r"(a) : "l"(p));
    return a;
}
__device__ __forceinline__ void cp16(uint32_t dst, const void* src) {
    asm volatile("cp.async.cg.shared.global [%0], [%1], 16;"
                 :: "r"(dst), "l"(src));
}
#define CP_COMMIT() asm volatile("cp.async.commit_group;" ::: "memory")
#define CP_WAIT(n)  asm volatile("cp.async.wait_group %0;" :: "n"(n) : "memory")

// ---------------------------------------------------------------------------
// One-time tf32 rounding pass.
// ---------------------------------------------------------------------------
__global__ void __launch_bounds__(256)
round_pass(const float* __restrict__ in, float* __restrict__ out)
{
    const size_t i = ((size_t)blockIdx.x * 256 + threadIdx.x) * 4;
    const float4 v = *(const float4*)(in + i);
    float4 o;
    o.x = round_tf32(v.x);
    o.y = round_tf32(v.y);
    o.z = round_tf32(v.z);
    o.w = round_tf32(v.w);
    *(float4*)(out + i) = o;
}

// ---------------------------------------------------------------------------
// tf32 mma.sync GEMM core, BK=32, 3-stage cp.async pipeline, no inner cvt.
// Ab: A offset to this CTA's 128 rows. Bb/biasb/Cb: offset to CTA's 128 cols.
// ---------------------------------------------------------------------------
#define GSTG 3
#define LDA_S 36
#define LDB_S 132
#define A_WORDS (128 * LDA_S)
#define B_WORDS (32 * LDB_S)
#define STG_WORDS (A_WORDS + B_WORDS)
#define GEMM_SMEM (GSTG * STG_WORDS * 4)

__device__ __forceinline__ void gemm_issue(uint32_t sb, int buf,
                                           const float* Ab, const float* Bb,
                                           int K, int N, int k0, int tid)
{
    const uint32_t base = sb + buf * (STG_WORDS * 4);
#pragma unroll
    for (int u = 0; u < 4; u++) {
        const int ia = tid + u * 256;
        const int m  = ia >> 3;
        const int c4 = (ia & 7) << 2;
        cp16(base + (m * LDA_S + c4) * 4, Ab + (size_t)m * K + k0 + c4);
        const int ib = tid + u * 256;
        const int k  = ib >> 5;
        const int n4 = (ib & 31) << 2;
        cp16(base + (A_WORDS + k * LDB_S + n4) * 4,
             Bb + (size_t)(k0 + k) * N + n4);
    }
}

__device__ __forceinline__ void gemm_core(const float* Ab, const float* Bb,
                                          const float* biasb, float* Cb,
                                          int K, int N, int roundOut,
                                          uint32_t* smw, uint32_t sb)
{
    const int tid  = threadIdx.x;
    const int wid  = tid >> 5;
    const int lane = tid & 31;
    const int g    = lane >> 2;
    const int tg   = lane & 3;
    const int wm   = wid & 1;
    const int wn   = wid >> 1;

    float acc[4][4][4];
#pragma unroll
    for (int mi = 0; mi < 4; mi++)
#pragma unroll
        for (int ni = 0; ni < 4; ni++)
#pragma unroll
            for (int r = 0; r < 4; r++) acc[mi][ni][r] = 0.f;

    const int nt = K / 32;

#pragma unroll
    for (int s = 0; s < GSTG - 1; s++) {
        if (s < nt) gemm_issue(sb, s, Ab, Bb, K, N, s * 32, tid);
        CP_COMMIT();
    }

    int buf = 0;
    for (int t = 0; t < nt; ++t) {
        CP_WAIT(1);
        __syncthreads();
        if (t + 2 < nt)
            gemm_issue(sb, (t + 2) % GSTG, Ab, Bb, K, N, (t + 2) * 32, tid);
        CP_COMMIT();

        const uint32_t* As = smw + buf * STG_WORDS;
        const uint32_t* Bs = As + A_WORDS;
#pragma unroll
        for (int kc = 0; kc < 4; kc++) {
            uint32_t afr[4][4];
#pragma unroll
            for (int mi = 0; mi < 4; mi++) {
                const int r0 = wm * 64 + mi * 16 + g;
                afr[mi][0] = As[r0 * LDA_S + kc * 8 + tg];
                afr[mi][1] = As[(r0 + 8) * LDA_S + kc * 8 + tg];
                afr[mi][2] = As[r0 * LDA_S + kc * 8 + tg + 4];
                afr[mi][3] = As[(r0 + 8) * LDA_S + kc * 8 + tg + 4];
            }
            uint32_t bfr[4][2];
#pragma unroll
            for (int ni = 0; ni < 4; ni++) {
                const int c0 = wn * 32 + ni * 8 + g;
                bfr[ni][0] = Bs[(kc * 8 + tg) * LDB_S + c0];
                bfr[ni][1] = Bs[(kc * 8 + tg + 4) * LDB_S + c0];
            }
#pragma unroll
            for (int mi = 0; mi < 4; mi++)
#pragma unroll
                for (int ni = 0; ni < 4; ni++)
                    mma_tf32(acc[mi][ni], afr[mi], bfr[ni]);
        }
        buf = (buf + 1 == GSTG) ? 0 : buf + 1;
    }

    // ---- epilogue: fused bias (+ optional tf32 rounding) ----
#pragma unroll
    for (int mi = 0; mi < 4; mi++) {
        const int r0 = wm * 64 + mi * 16 + g;
#pragma unroll
        for (int ni = 0; ni < 4; ni++) {
            const int c0 = wn * 32 + ni * 8 + tg * 2;
            const float bx0 = biasb[c0], bx1 = biasb[c0 + 1];
            float2 v0 = {acc[mi][ni][0] + bx0, acc[mi][ni][1] + bx1};
            float2 v1 = {acc[mi][ni][2] + bx0, acc[mi][ni][3] + bx1};
            if (roundOut) {
                v0.x = round_tf32(v0.x); v0.y = round_tf32(v0.y);
                v1.x = round_tf32(v1.x); v1.y = round_tf32(v1.y);
            }
            *(float2*)(Cb + (size_t)r0 * N + c0)       = v0;
            *(float2*)(Cb + (size_t)(r0 + 8) * N + c0) = v1;
        }
    }
}

// Fused q+kv projection: grid.x in [0,24). bx<16 -> q columns, else kv.
__global__ void __launch_bounds__(256, 2)
qkv_gemm(const float* __restrict__ x,
         const float* __restrict__ wq, const float* __restrict__ bq,
         const float* __restrict__ wkv, const float* __restrict__ bkv,
         float* __restrict__ q, float* __restrict__ kvo)
{
    extern __shared__ uint32_t smw[];
    const uint32_t sb = smem_u32(smw);
    const int bx = blockIdx.x;
    const float* Ab = x + (size_t)blockIdx.y * 128 * Cc_;

    if (bx < 16) {
        const int cb = bx * 128;
        gemm_core(Ab, wq + cb, bq + cb,
                  q + (size_t)blockIdx.y * 128 * Cc_ + cb,
                  Cc_, Cc_, 1, smw, sb);
    } else {
        const int cb = (bx - 16) * 128;
        gemm_core(Ab, wkv + cb, bkv + cb,
                  kvo + (size_t)blockIdx.y * 128 * KVN_ + cb,
                  Cc_, KVN_, 1, smw, sb);
    }
}

// Plain GEMM (final projection)
__global__ void __launch_bounds__(256, 2)
pgemm(int M, int N, int K,
      const float* __restrict__ A, const float* __restrict__ B,
      const float* __restrict__ bias, float* __restrict__ C, int roundOut)
{
    extern __shared__ uint32_t smw[];
    const uint32_t sb = smem_u32(smw);
    const int cb = blockIdx.x * 128;
    gemm_core(A + (size_t)blockIdx.y * 128 * K, B + cb, bias + cb,
              C + (size_t)blockIdx.y * 128 * N + cb,
              K, N, roundOut, smw, sb);
}

// ---------------------------------------------------------------------------
// Flash attention, tf32 mma.sync, double-buffered cp.async K/V.
// Longest-first: qt = 15 - blockIdx.x. Br=128, Bc=64, HD=128.
// ---------------------------------------------------------------------------
#define FLDK 132
#define KV_WORDS (64 * FLDK)
#define STG_F (2 * KV_WORDS)
#define PSo (2 * STG_F)
#define FLDP 68
#define FLASH_SMEM ((PSo + 128 * FLDP) * 4)

__device__ __forceinline__ void flash_issue(uint32_t sb, int buf,
                                            const float* kvbase, int tid)
{
    const uint32_t kb = sb + buf * (STG_F * 4);
    const uint32_t vb = kb + KV_WORDS * 4;
#pragma unroll
    for (int u = 0; u < 8; u++) {
        const int i  = tid + u * 256;
        const int r  = i >> 5;
        const int c4 = (i & 31) << 2;
        const float* src = kvbase + (size_t)r * KVN_ + c4;
        cp16(kb + (r * FLDK + c4) * 4, src);
        cp16(vb + (r * FLDK + c4) * 4, src + 512);
    }
}

__global__ void __launch_bounds__(256, 1)
flash_cp(const float* __restrict__ q, const float* __restrict__ kv,
         float* __restrict__ y)
{
    extern __shared__ uint32_t smw[];
    const uint32_t sb = smem_u32(smw);
    uint32_t* Ps = smw + PSo;

    const int qt = (int)gridDim.x - 1 - (int)blockIdx.x;  // longest-first
    const int h  = blockIdx.y;
    const int b  = blockIdx.z;
    const int kvh = h & (HKV_ - 1);

    const int tid  = threadIdx.x;
    const int w    = tid >> 5;
    const int lane = tid & 31;
    const int g    = lane >> 2;
    const int tg   = lane & 3;
    const float scale = 0.08838834764831843f;

    const int rloc0 = w * 16 + g;
    const int grow0 = qt * 128 + rloc0;
    const int grow1 = grow0 + 8;

    uint32_t qf[16][4];
    {
        const float* qb = q + ((size_t)(b * Tt_) + qt * 128 + w * 16) * Cc_
                            + h * HDv_;
#pragma unroll
        for (int kc = 0; kc < 16; kc++) {
            const int d0 = kc * 8 + tg;
            qf[kc][0] = to_tf32(qb[(size_t)g * Cc_ + d0] * scale);
            qf[kc][1] = to_tf32(qb[(size_t)(g + 8) * Cc_ + d0] * scale);
            qf[kc][2] = to_tf32(qb[(size_t)g * Cc_ + d0 + 4] * scale);
            qf[kc][3] = to_tf32(qb[(size_t)(g + 8) * Cc_ + d0 + 4] * scale);
        }
    }

    float of[16][4];
#pragma unroll
    for (int ni = 0; ni < 16; ni++)
#pragma unroll
        for (int r = 0; r < 4; r++) of[ni][r] = 0.f;
    float m0 = -INFINITY, m1 = -INFINITY, l0 = 0.f, l1 = 0.f;

    const int ktmax = 2 * qt + 1;
    const float* kvb0 = kv + (size_t)(b * Tt_) * KVN_ + kvh * HDv_;

    flash_issue(sb, 0, kvb0, tid);
    CP_COMMIT();

    for (int kt = 0; kt <= ktmax; ++kt) {
        const int cur = kt & 1;
        if (kt < ktmax)
            flash_issue(sb, cur ^ 1, kvb0 + (size_t)(kt + 1) * 64 * KVN_, tid);
        CP_COMMIT();
        CP_WAIT(1);
        __syncthreads();

        const uint32_t* Kb = smw + cur * STG_F;
        const uint32_t* Vb = Kb + KV_WORDS;

        const bool act = (kt * 64) <= (qt * 128 + w * 16 + 15);
        if (act) {
            float sf[8][4];
#pragma unroll
            for (int ni = 0; ni < 8; ni++)
#pragma unroll
                for (int r = 0; r < 4; r++) sf[ni][r] = 0.f;

#pragma unroll
            for (int kc = 0; kc < 16; kc++) {
#pragma unroll
                for (int ni = 0; ni < 8; ni++) {
                    uint32_t bfr[2];
                    bfr[0] = Kb[(ni * 8 + g) * FLDK + kc * 8 + tg];
                    bfr[1] = Kb[(ni * 8 + g) * FLDK + kc * 8 + tg + 4];
                    mma_tf32(sf[ni], qf[kc], bfr);
                }
            }

            if (kt * 64 + 63 > qt * 128 + w * 16) {
                const int cb = kt * 64;
#pragma unroll
                for (int ni = 0; ni < 8; ni++) {
                    const int c0 = cb + ni * 8 + tg * 2;
                    if (c0 > grow0)     sf[ni][0] = -1e30f;
                    if (c0 + 1 > grow0) sf[ni][1] = -1e30f;
                    if (c0 > grow1)     sf[ni][2] = -1e30f;
                    if (c0 + 1 > grow1) sf[ni][3] = -1e30f;
                }
            }

            float mx0 = -1e30f, mx1 = -1e30f;
#pragma unroll
            for (int ni = 0; ni < 8; ni++) {
                mx0 = fmaxf(mx0, fmaxf(sf[ni][0], sf[ni][1]));
                mx1 = fmaxf(mx1, fmaxf(sf[ni][2], sf[ni][3]));
            }
            mx0 = fmaxf(mx0, __shfl_xor_sync(0xffffffffu, mx0, 1));
            mx0 = fmaxf(mx0, __shfl_xor_sync(0xffffffffu, mx0, 2));
            mx1 = fmaxf(mx1, __shfl_xor_sync(0xffffffffu, mx1, 1));
            mx1 = fmaxf(mx1, __shfl_xor_sync(0xffffffffu, mx1, 2));

            const float nm0 = fmaxf(m0, mx0);
            const float nm1 = fmaxf(m1, mx1);
            float sum0 = 0.f, sum1 = 0.f;
#pragma unroll
            for (int ni = 0; ni < 8; ni++) {
                sf[ni][0] = __expf(sf[ni][0] - nm0);
                sf[ni][1] = __expf(sf[ni][1] - nm0);
                sf[ni][2] = __expf(sf[ni][2] - nm1);
                sf[ni][3] = __expf(sf[ni][3] - nm1);
                sum0 += sf[ni][0] + sf[ni][1];
                sum1 += sf[ni][2] + sf[ni][3];
            }
            sum0 += __shfl_xor_sync(0xffffffffu, sum0, 1);
            sum0 += __shfl_xor_sync(0xffffffffu, sum0, 2);
            sum1 += __shfl_xor_sync(0xffffffffu, sum1, 1);
            sum1 += __shfl_xor_sync(0xffffffffu, sum1, 2);

            const float al0 = __expf(m0 - nm0);
            const float al1 = __expf(m1 - nm1);
            m0 = nm0; m1 = nm1;
            l0 = l0 * al0 + sum0;
            l1 = l1 * al1 + sum1;

#pragma unroll
            for (int ni = 0; ni < 8; ni++) {
                uint2 p01 = {to_tf32(sf[ni][0]), to_tf32(sf[ni][1])};
                uint2 p23 = {to_tf32(sf[ni][2]), to_tf32(sf[ni][3])};
                *(uint2*)(&Ps[(w * 16 + g) * FLDP + ni * 8 + tg * 2])     = p01;
                *(uint2*)(&Ps[(w * 16 + 8 + g) * FLDP + ni * 8 + tg * 2]) = p23;
            }
            __syncwarp();

            {
                const u64t a0p = pk2(al0, al0);
                const u64t a1p = pk2(al1, al1);
#pragma unroll
                for (int ni = 0; ni < 16; ni++) {
                    u64t v01 = pk2(of[ni][0], of[ni][1]);
                    u64t v23 = pk2(of[ni][2], of[ni][3]);
                    mul2(v01, v01, a0p);
                    mul2(v23, v23, a1p);
                    const float2 f01 = upk(v01), f23 = upk(v23);
                    of[ni][0] = f01.x; of[ni][1] = f01.y;
                    of[ni][2] = f23.x; of[ni][3] = f23.y;
                }
            }

#pragma unroll
            for (int kc = 0; kc < 8; kc++) {
                uint32_t pa[4];
                pa[0] = Ps[(w * 16 + g) * FLDP + kc * 8 + tg];
                pa[1] = Ps[(w * 16 + 8 + g) * FLDP + kc * 8 + tg];
                pa[2] = Ps[(w * 16 + g) * FLDP + kc * 8 + tg + 4];
                pa[3] = Ps[(w * 16 + 8 + g) * FLDP + kc * 8 + tg + 4];
#pragma unroll
                for (int ni = 0; ni < 16; ni++) {
                    uint32_t vb2[2];
                    vb2[0] = Vb[(kc * 8 + tg) * FLDK + ni * 8 + g];
                    vb2[1] = Vb[(kc * 8 + tg + 4) * FLDK + ni * 8 + g];
                    mma_tf32(of[ni], pa, vb2);
                }
            }
        }
        __syncthreads();
    }

    const float inv0 = 1.f / l0;
    const float inv1 = 1.f / l1;
    float* y0 = y + ((size_t)(b * Tt_) + grow0) * Cc_ + h * HDv_;
    float* y1 = y + ((size_t)(b * Tt_) + grow1) * Cc_ + h * HDv_;
#pragma unroll
    for (int ni = 0; ni < 16; ni++) {
        const int c0 = ni * 8 + tg * 2;
        float2 v0 = {round_tf32(of[ni][0] * inv0), round_tf32(of[ni][1] * inv0)};
        float2 v1 = {round_tf32(of[ni][2] * inv1), round_tf32(of[ni][3] * inv1)};
        *(float2*)(y0 + c0) = v0;
        *(float2*)(y1 + c0) = v1;
    }
}

// ---------------------------------------------------------------------------
extern "C" void kernel_launch(void* const* d_in, const int* in_sizes, int n_in,
                              void* d_out, int out_size)
{
    const float* x   = (const float*)d_in[0];
    const float* Wkv = (const float*)d_in[1];
    const float* bkv = (const float*)d_in[2];
    const float* Wq  = (const float*)d_in[3];
    const float* bq  = (const float*)d_in[4];
    const float* Wp  = (const float*)d_in[5];
    const float* bp  = (const float*)d_in[6];
    float* out = (float*)d_out;

    float *qp, *kvp, *yp, *xr, *wq, *wkv, *wp;
    cudaGetSymbolAddress((void**)&qp,  g_q);
    cudaGetSymbolAddress((void**)&kvp, g_kv);
    cudaGetSymbolAddress((void**)&yp,  g_y);
    cudaGetSymbolAddress((void**)&xr,  g_xr);
    cudaGetSymbolAddress((void**)&wq,  g_wq);
    cudaGetSymbolAddress((void**)&wkv, g_wkv);
    cudaGetSymbolAddress((void**)&wp,  g_wp);

    cudaFuncSetAttribute(qkv_gemm,
                         cudaFuncAttributeMaxDynamicSharedMemorySize,
                         GEMM_SMEM);
    cudaFuncSetAttribute(pgemm,
                         cudaFuncAttributeMaxDynamicSharedMemorySize,
                         GEMM_SMEM);
    cudaFuncSetAttribute(flash_cp,
                         cudaFuncAttributeMaxDynamicSharedMemorySize,
                         FLASH_SMEM);

    // one-time tf32 rounding of all GEMM inputs
    round_pass<<<(Mm_ * Cc_) / 1024, 256>>>(x, xr);
    round_pass<<<(Cc_ * Cc_) / 1024, 256>>>(Wq, wq);
    round_pass<<<(Cc_ * KVN_) / 1024, 256>>>(Wkv, wkv);
    round_pass<<<(Cc_ * Cc_) / 1024, 256>>>(Wp, wp);

    // fused q + kv projections (768 CTAs, one tail)
    qkv_gemm<<<dim3(24, Mm_ / 128), 256, GEMM_SMEM>>>(
        xr, wq, bq, wkv, bkv, qp, kvp);
    // attention (longest-first qt order)
    flash_cp<<<dim3(Tt_ / 128, Hh_, Bb_), 256, FLASH_SMEM>>>(qp, kvp, yp);
    // out = y @ Wp + bp (exact fp32 output)
    pgemm<<<dim3(Cc_ / 128, Mm_ / 128), 256, GEMM_SMEM>>>(
        Mm_, Cc_, Cc_, yp, wp, bp, out, 0);
}

// round 12
// speedup vs baseline: 4.9158x; 1.4294x over previous
#include <cuda_runtime.h>
#include <cuda_fp16.h>
#include <math.h>
#include <stdint.h>

// Problem constants
#define Bb_ 2
#define Tt_ 2048
#define Cc_ 2048
#define Hh_ 16
#define HKV_ 4
#define HDv_ 128
#define Mm_ (Bb_ * Tt_)
#define KVN_ 1024

// Scratch (device globals; no allocation allowed)
__device__ float  g_q[(size_t)Mm_ * Cc_];      // fp32 (tf32-rounded) for flash
__device__ float  g_kv[(size_t)Mm_ * KVN_];    // fp32 (tf32-rounded) for flash
__device__ __half g_yh[(size_t)Mm_ * Cc_];     // fp16 attention output
__device__ __half g_xh[(size_t)Mm_ * Cc_];     // fp16 x
__device__ __half g_wqh[(size_t)Cc_ * Cc_];    // fp16 Wq
__device__ __half g_wkvh[(size_t)Cc_ * KVN_];  // fp16 Wkv
__device__ __half g_wph[(size_t)Cc_ * Cc_];    // fp16 Wp

// ---- helpers ----------------------------------------------------------------
typedef unsigned long long u64t;

__device__ __forceinline__ u64t pk2(float lo, float hi) {
    u64t r;
    asm("mov.b64 %0, {%1, %2};" : "=l"(r) : "f"(lo), "f"(hi));
    return r;
}
__device__ __forceinline__ void mul2(u64t& d, u64t a, u64t b) {
    asm("mul.rn.f32x2 %0, %1, %2;" : "=l"(d) : "l"(a), "l"(b));
}
__device__ __forceinline__ float2 upk(u64t v) {
    float2 f;
    asm("mov.b64 {%0, %1}, %2;" : "=f"(f.x), "=f"(f.y) : "l"(v));
    return f;
}
__device__ __forceinline__ uint32_t to_tf32(float f) {
    uint32_t r;
    asm("cvt.rna.tf32.f32 %0, %1;" : "=r"(r) : "f"(f));
    return r;
}
__device__ __forceinline__ float round_tf32(float f) {
    return __uint_as_float(to_tf32(f));
}
__device__ __forceinline__ void mma_tf32(float (&d)[4],
                                         const uint32_t (&a)[4],
                                         const uint32_t (&b)[2]) {
    asm volatile(
        "mma.sync.aligned.m16n8k8.row.col.f32.tf32.tf32.f32 "
        "{%0,%1,%2,%3}, {%4,%5,%6,%7}, {%8,%9}, {%0,%1,%2,%3};\n"
        : "+f"(d[0]), "+f"(d[1]), "+f"(d[2]), "+f"(d[3])
        : "r"(a[0]), "r"(a[1]), "r"(a[2]), "r"(a[3]), "r"(b[0]), "r"(b[1]));
}
__device__ __forceinline__ void mma_f16(float (&d)[4],
                                        const uint32_t (&a)[4],
                                        const uint32_t (&b)[2]) {
    asm volatile(
        "mma.sync.aligned.m16n8k16.row.col.f32.f16.f16.f32 "
        "{%0,%1,%2,%3}, {%4,%5,%6,%7}, {%8,%9}, {%0,%1,%2,%3};\n"
        : "+f"(d[0]), "+f"(d[1]), "+f"(d[2]), "+f"(d[3])
        : "r"(a[0]), "r"(a[1]), "r"(a[2]), "r"(a[3]), "r"(b[0]), "r"(b[1]));
}
__device__ __forceinline__ void ldsm_x4(uint32_t (&r)[4], uint32_t addr) {
    asm volatile(
        "ldmatrix.sync.aligned.m8n8.x4.shared.b16 {%0,%1,%2,%3}, [%4];"
        : "=r"(r[0]), "=r"(r[1]), "=r"(r[2]), "=r"(r[3]) : "r"(addr));
}
__device__ __forceinline__ void ldsm_x2t(uint32_t (&r)[2], uint32_t addr) {
    asm volatile(
        "ldmatrix.sync.aligned.m8n8.x2.trans.shared.b16 {%0,%1}, [%2];"
        : "=r"(r[0]), "=r"(r[1]) : "r"(addr));
}
__device__ __forceinline__ uint32_t smem_u32(const void* p) {
    uint32_t a;
    asm("{ .reg .u64 t; cvta.to.shared.u64 t, %1; cvt.u32.u64 %0, t; }"
        : "=r"(a) : "l"(p));
    return a;
}
__device__ __forceinline__ void cp16(uint32_t dst, const void* src) {
    asm volatile("cp.async.cg.shared.global [%0], [%1], 16;"
                 :: "r"(dst), "l"(src));
}
#define CP_COMMIT() asm volatile("cp.async.commit_group;" ::: "memory")
#define CP_WAIT(n)  asm volatile("cp.async.wait_group %0;" :: "n"(n) : "memory")

// ---------------------------------------------------------------------------
// One-time fp32 -> fp16 conversion (rn).
// ---------------------------------------------------------------------------
__global__ void __launch_bounds__(256)
conv_pass(const float* __restrict__ in, __half* __restrict__ out)
{
    const size_t i = ((size_t)blockIdx.x * 256 + threadIdx.x) * 4;
    const float4 v = *(const float4*)(in + i);
    __half2 h0 = __floats2half2_rn(v.x, v.y);
    __half2 h1 = __floats2half2_rn(v.z, v.w);
    *(__half2*)(out + i)     = h0;
    *(__half2*)(out + i + 2) = h1;
}

// ---------------------------------------------------------------------------
// fp16 m16n8k16 GEMM core, BK=32, 3-stage cp.async, ldmatrix fragments.
// C[M,N](fp32) = Ah[M,K] @ Bh[K,N] + bias[N]. 128x128 CTA, 8 warps (64x32).
// ---------------------------------------------------------------------------
#define GSTG 3
#define LDAH 40                      // A row stride (halfs): conflict-free LDSM
#define LDBH 136                     // B row stride (halfs)
#define A_BYTES (128 * LDAH * 2)     // 10240
#define B_BYTES (32 * LDBH * 2)      // 8704
#define STG_BYTES (A_BYTES + B_BYTES)
#define GEMM_SMEM (GSTG * STG_BYTES) // 56832

__device__ __forceinline__ void gemm_issue_h(uint32_t sb, int buf,
                                             const __half* Ah, const __half* Bh,
                                             int K, int N, int k0, int tid)
{
    const uint32_t base = sb + buf * STG_BYTES;
#pragma unroll
    for (int u = 0; u < 2; u++) {
        const int ia = tid + u * 256;          // 0..511
        const int m  = ia >> 2;
        const int c8 = (ia & 3) * 8;
        cp16(base + (m * LDAH + c8) * 2, Ah + (size_t)m * K + k0 + c8);
        const int ib = tid + u * 256;
        const int k  = ib >> 4;
        const int n8 = (ib & 15) * 8;
        cp16(base + A_BYTES + (k * LDBH + n8) * 2,
             Bh + (size_t)(k0 + k) * N + n8);
    }
}

__device__ __forceinline__ void gemm_core_h(const __half* Ah, const __half* Bh,
                                            const float* biasb, float* Cb,
                                            int K, int N, int roundOut,
                                            uint32_t sb)
{
    const int tid  = threadIdx.x;
    const int wid  = tid >> 5;
    const int lane = tid & 31;
    const int g    = lane >> 2;
    const int tg   = lane & 3;
    const int wm   = wid & 1;
    const int wn   = wid >> 1;

    // ldmatrix lane addressing components
    const int arow_l = (lane & 7) + 8 * ((lane >> 3) & 1);  // 0..15
    const int acol_l = (lane >> 4) * 8;                     // 0 or 8

    float acc[4][4][4];
#pragma unroll
    for (int mi = 0; mi < 4; mi++)
#pragma unroll
        for (int ni = 0; ni < 4; ni++)
#pragma unroll
            for (int r = 0; r < 4; r++) acc[mi][ni][r] = 0.f;

    const int nt = K / 32;

#pragma unroll
    for (int s = 0; s < GSTG - 1; s++) {
        if (s < nt) gemm_issue_h(sb, s, Ah, Bh, K, N, s * 32, tid);
        CP_COMMIT();
    }

    int buf = 0;
    for (int t = 0; t < nt; ++t) {
        CP_WAIT(1);
        __syncthreads();
        if (t + 2 < nt)
            gemm_issue_h(sb, (t + 2) % GSTG, Ah, Bh, K, N, (t + 2) * 32, tid);
        CP_COMMIT();

        const uint32_t base = sb + buf * STG_BYTES;
#pragma unroll
        for (int kc = 0; kc < 2; kc++) {
            uint32_t afr[4][4];
#pragma unroll
            for (int mi = 0; mi < 4; mi++) {
                const int row = wm * 64 + mi * 16 + arow_l;
                const int col = kc * 16 + acol_l;
                ldsm_x4(afr[mi], base + (row * LDAH + col) * 2);
            }
            uint32_t bfr[4][2];
#pragma unroll
            for (int ni = 0; ni < 4; ni++) {
                const int krow = kc * 16 + arow_l;          // lanes 0-15 used
                const int ncol = wn * 32 + ni * 8;
                ldsm_x2t(bfr[ni], base + A_BYTES + (krow * LDBH + ncol) * 2);
            }
#pragma unroll
            for (int mi = 0; mi < 4; mi++)
#pragma unroll
                for (int ni = 0; ni < 4; ni++)
                    mma_f16(acc[mi][ni], afr[mi], bfr[ni]);
        }
        buf = (buf + 1 == GSTG) ? 0 : buf + 1;
    }

    // ---- epilogue: fused bias (+ optional tf32 rounding) ----
#pragma unroll
    for (int mi = 0; mi < 4; mi++) {
        const int r0 = wm * 64 + mi * 16 + g;
#pragma unroll
        for (int ni = 0; ni < 4; ni++) {
            const int c0 = wn * 32 + ni * 8 + tg * 2;
            const float bx0 = biasb[c0], bx1 = biasb[c0 + 1];
            float2 v0 = {acc[mi][ni][0] + bx0, acc[mi][ni][1] + bx1};
            float2 v1 = {acc[mi][ni][2] + bx0, acc[mi][ni][3] + bx1};
            if (roundOut) {
                v0.x = round_tf32(v0.x); v0.y = round_tf32(v0.y);
                v1.x = round_tf32(v1.x); v1.y = round_tf32(v1.y);
            }
            *(float2*)(Cb + (size_t)r0 * N + c0)       = v0;
            *(float2*)(Cb + (size_t)(r0 + 8) * N + c0) = v1;
        }
    }
}

// Fused q+kv projection: grid.x in [0,24). bx<16 -> q columns, else kv.
__global__ void __launch_bounds__(256, 2)
qkv_gemm(const __half* __restrict__ xh,
         const __half* __restrict__ wqh, const float* __restrict__ bq,
         const __half* __restrict__ wkvh, const float* __restrict__ bkv,
         float* __restrict__ q, float* __restrict__ kvo)
{
    extern __shared__ uint32_t smw[];
    const uint32_t sb = smem_u32(smw);
    const int bx = blockIdx.x;
    const __half* Ab = xh + (size_t)blockIdx.y * 128 * Cc_;

    if (bx < 16) {
        const int cb = bx * 128;
        gemm_core_h(Ab, wqh + cb, bq + cb,
                    q + (size_t)blockIdx.y * 128 * Cc_ + cb,
                    Cc_, Cc_, 1, sb);
    } else {
        const int cb = (bx - 16) * 128;
        gemm_core_h(Ab, wkvh + cb, bkv + cb,
                    kvo + (size_t)blockIdx.y * 128 * KVN_ + cb,
                    Cc_, KVN_, 1, sb);
    }
}

// Final projection: out = yh @ Wp + bp (fp32 exact output)
__global__ void __launch_bounds__(256, 2)
pgemm_h(const __half* __restrict__ A, const __half* __restrict__ B,
        const float* __restrict__ bias, float* __restrict__ C)
{
    extern __shared__ uint32_t smw[];
    const uint32_t sb = smem_u32(smw);
    const int cb = blockIdx.x * 128;
    gemm_core_h(A + (size_t)blockIdx.y * 128 * Cc_, B + cb, bias + cb,
                C + (size_t)blockIdx.y * 128 * Cc_ + cb,
                Cc_, Cc_, 0, sb);
}

// ---------------------------------------------------------------------------
// Flash attention, tf32 mma.sync, double-buffered cp.async K/V,
// single __syncthreads per kt (issue-after-wait). y output fp16.
// Longest-first qt. Br=128, Bc=64, HD=128.
// ---------------------------------------------------------------------------
#define FLDK 132
#define KV_WORDS (64 * FLDK)
#define STG_F (2 * KV_WORDS)
#define PSo (2 * STG_F)
#define FLDP 68
#define FLASH_SMEM ((PSo + 128 * FLDP) * 4)

__device__ __forceinline__ void flash_issue(uint32_t sb, int buf,
                                            const float* kvbase, int tid)
{
    const uint32_t kb = sb + buf * (STG_F * 4);
    const uint32_t vb = kb + KV_WORDS * 4;
#pragma unroll
    for (int u = 0; u < 8; u++) {
        const int i  = tid + u * 256;
        const int r  = i >> 5;
        const int c4 = (i & 31) << 2;
        const float* src = kvbase + (size_t)r * KVN_ + c4;
        cp16(kb + (r * FLDK + c4) * 4, src);
        cp16(vb + (r * FLDK + c4) * 4, src + 512);
    }
}

__global__ void __launch_bounds__(256, 1)
flash_cp(const float* __restrict__ q, const float* __restrict__ kv,
         __half* __restrict__ y)
{
    extern __shared__ uint32_t smw[];
    const uint32_t sb = smem_u32(smw);
    uint32_t* Ps = smw + PSo;

    const int qt = (int)gridDim.x - 1 - (int)blockIdx.x;  // longest-first
    const int h  = blockIdx.y;
    const int b  = blockIdx.z;
    const int kvh = h & (HKV_ - 1);

    const int tid  = threadIdx.x;
    const int w    = tid >> 5;
    const int lane = tid & 31;
    const int g    = lane >> 2;
    const int tg   = lane & 3;
    const float scale = 0.08838834764831843f;

    const int rloc0 = w * 16 + g;
    const int grow0 = qt * 128 + rloc0;
    const int grow1 = grow0 + 8;

    uint32_t qf[16][4];
    {
        const float* qb = q + ((size_t)(b * Tt_) + qt * 128 + w * 16) * Cc_
                            + h * HDv_;
#pragma unroll
        for (int kc = 0; kc < 16; kc++) {
            const int d0 = kc * 8 + tg;
            qf[kc][0] = to_tf32(qb[(size_t)g * Cc_ + d0] * scale);
            qf[kc][1] = to_tf32(qb[(size_t)(g + 8) * Cc_ + d0] * scale);
            qf[kc][2] = to_tf32(qb[(size_t)g * Cc_ + d0 + 4] * scale);
            qf[kc][3] = to_tf32(qb[(size_t)(g + 8) * Cc_ + d0 + 4] * scale);
        }
    }

    float of[16][4];
#pragma unroll
    for (int ni = 0; ni < 16; ni++)
#pragma unroll
        for (int r = 0; r < 4; r++) of[ni][r] = 0.f;
    float m0 = -INFINITY, m1 = -INFINITY, l0 = 0.f, l1 = 0.f;

    const int ktmax = 2 * qt + 1;
    const float* kvb0 = kv + (size_t)(b * Tt_) * KVN_ + kvh * HDv_;

    flash_issue(sb, 0, kvb0, tid);
    CP_COMMIT();

    for (int kt = 0; kt <= ktmax; ++kt) {
        const int cur = kt & 1;
        CP_WAIT(0);          // tile kt (only outstanding group) resident
        __syncthreads();     // all reads of buf cur^1 (iter kt-1) done
        if (kt < ktmax) {
            flash_issue(sb, cur ^ 1, kvb0 + (size_t)(kt + 1) * 64 * KVN_, tid);
            CP_COMMIT();
        }

        const uint32_t* Kb = smw + cur * STG_F;
        const uint32_t* Vb = Kb + KV_WORDS;

        const bool act = (kt * 64) <= (qt * 128 + w * 16 + 15);
        if (act) {
            float sf[8][4];
#pragma unroll
            for (int ni = 0; ni < 8; ni++)
#pragma unroll
                for (int r = 0; r < 4; r++) sf[ni][r] = 0.f;

#pragma unroll
            for (int kc = 0; kc < 16; kc++) {
#pragma unroll
                for (int ni = 0; ni < 8; ni++) {
                    uint32_t bfr[2];
                    bfr[0] = Kb[(ni * 8 + g) * FLDK + kc * 8 + tg];
                    bfr[1] = Kb[(ni * 8 + g) * FLDK + kc * 8 + tg + 4];
                    mma_tf32(sf[ni], qf[kc], bfr);
                }
            }

            if (kt * 64 + 63 > qt * 128 + w * 16) {
                const int cb = kt * 64;
#pragma unroll
                for (int ni = 0; ni < 8; ni++) {
                    const int c0 = cb + ni * 8 + tg * 2;
                    if (c0 > grow0)     sf[ni][0] = -1e30f;
                    if (c0 + 1 > grow0) sf[ni][1] = -1e30f;
                    if (c0 > grow1)     sf[ni][2] = -1e30f;
                    if (c0 + 1 > grow1) sf[ni][3] = -1e30f;
                }
            }

            float mx0 = -1e30f, mx1 = -1e30f;
#pragma unroll
            for (int ni = 0; ni < 8; ni++) {
                mx0 = fmaxf(mx0, fmaxf(sf[ni][0], sf[ni][1]));
                mx1 = fmaxf(mx1, fmaxf(sf[ni][2], sf[ni][3]));
            }
            mx0 = fmaxf(mx0, __shfl_xor_sync(0xffffffffu, mx0, 1));
            mx0 = fmaxf(mx0, __shfl_xor_sync(0xffffffffu, mx0, 2));
            mx1 = fmaxf(mx1, __shfl_xor_sync(0xffffffffu, mx1, 1));
            mx1 = fmaxf(mx1, __shfl_xor_sync(0xffffffffu, mx1, 2));

            const float nm0 = fmaxf(m0, mx0);
            const float nm1 = fmaxf(m1, mx1);
            float sum0 = 0.f, sum1 = 0.f;
#pragma unroll
            for (int ni = 0; ni < 8; ni++) {
                sf[ni][0] = __expf(sf[ni][0] - nm0);
                sf[ni][1] = __expf(sf[ni][1] - nm0);
                sf[ni][2] = __expf(sf[ni][2] - nm1);
                sf[ni][3] = __expf(sf[ni][3] - nm1);
                sum0 += sf[ni][0] + sf[ni][1];
                sum1 += sf[ni][2] + sf[ni][3];
            }
            sum0 += __shfl_xor_sync(0xffffffffu, sum0, 1);
            sum0 += __shfl_xor_sync(0xffffffffu, sum0, 2);
            sum1 += __shfl_xor_sync(0xffffffffu, sum1, 1);
            sum1 += __shfl_xor_sync(0xffffffffu, sum1, 2);

            const float al0 = __expf(m0 - nm0);
            const float al1 = __expf(m1 - nm1);
            m0 = nm0; m1 = nm1;
            l0 = l0 * al0 + sum0;
            l1 = l1 * al1 + sum1;

#pragma unroll
            for (int ni = 0; ni < 8; ni++) {
                uint2 p01 = {to_tf32(sf[ni][0]), to_tf32(sf[ni][1])};
                uint2 p23 = {to_tf32(sf[ni][2]), to_tf32(sf[ni][3])};
                *(uint2*)(&Ps[(w * 16 + g) * FLDP + ni * 8 + tg * 2])     = p01;
                *(uint2*)(&Ps[(w * 16 + 8 + g) * FLDP + ni * 8 + tg * 2]) = p23;
            }
            __syncwarp();

            {
                const u64t a0p = pk2(al0, al0);
                const u64t a1p = pk2(al1, al1);
#pragma unroll
                for (int ni = 0; ni < 16; ni++) {
                    u64t v01 = pk2(of[ni][0], of[ni][1]);
                    u64t v23 = pk2(of[ni][2], of[ni][3]);
                    mul2(v01, v01, a0p);
                    mul2(v23, v23, a1p);
                    const float2 f01 = upk(v01), f23 = upk(v23);
                    of[ni][0] = f01.x; of[ni][1] = f01.y;
                    of[ni][2] = f23.x; of[ni][3] = f23.y;
                }
            }

#pragma unroll
            for (int kc = 0; kc < 8; kc++) {
                uint32_t pa[4];
                pa[0] = Ps[(w * 16 + g) * FLDP + kc * 8 + tg];
                pa[1] = Ps[(w * 16 + 8 + g) * FLDP + kc * 8 + tg];
                pa[2] = Ps[(w * 16 + g) * FLDP + kc * 8 + tg + 4];
                pa[3] = Ps[(w * 16 + 8 + g) * FLDP + kc * 8 + tg + 4];
#pragma unroll
                for (int ni = 0; ni < 16; ni++) {
                    uint32_t vb2[2];
                    vb2[0] = Vb[(kc * 8 + tg) * FLDK + ni * 8 + g];
                    vb2[1] = Vb[(kc * 8 + tg + 4) * FLDK + ni * 8 + g];
                    mma_tf32(of[ni], pa, vb2);
                }
            }
        }
    }

    // ---- normalize + store fp16 (feeds final GEMM's A operand) ----
    const float inv0 = 1.f / l0;
    const float inv1 = 1.f / l1;
    __half* y0 = y + ((size_t)(b * Tt_) + grow0) * Cc_ + h * HDv_;
    __half* y1 = y + ((size_t)(b * Tt_) + grow1) * Cc_ + h * HDv_;
#pragma unroll
    for (int ni = 0; ni < 16; ni++) {
        const int c0 = ni * 8 + tg * 2;
        *(__half2*)(y0 + c0) =
            __floats2half2_rn(of[ni][0] * inv0, of[ni][1] * inv0);
        *(__half2*)(y1 + c0) =
            __floats2half2_rn(of[ni][2] * inv1, of[ni][3] * inv1);
    }
}

// ---------------------------------------------------------------------------
extern "C" void kernel_launch(void* const* d_in, const int* in_sizes, int n_in,
                              void* d_out, int out_size)
{
    const float* x   = (const float*)d_in[0];
    const float* Wkv = (const float*)d_in[1];
    const float* bkv = (const float*)d_in[2];
    const float* Wq  = (const float*)d_in[3];
    const float* bq  = (const float*)d_in[4];
    const float* Wp  = (const float*)d_in[5];
    const float* bp  = (const float*)d_in[6];
    float* out = (float*)d_out;

    float *qp, *kvp;
    __half *yh, *xh, *wqh, *wkvh, *wph;
    cudaGetSymbolAddress((void**)&qp,   g_q);
    cudaGetSymbolAddress((void**)&kvp,  g_kv);
    cudaGetSymbolAddress((void**)&yh,   g_yh);
    cudaGetSymbolAddress((void**)&xh,   g_xh);
    cudaGetSymbolAddress((void**)&wqh,  g_wqh);
    cudaGetSymbolAddress((void**)&wkvh, g_wkvh);
    cudaGetSymbolAddress((void**)&wph,  g_wph);

    cudaFuncSetAttribute(qkv_gemm,
                         cudaFuncAttributeMaxDynamicSharedMemorySize,
                         GEMM_SMEM);
    cudaFuncSetAttribute(pgemm_h,
                         cudaFuncAttributeMaxDynamicSharedMemorySize,
                         GEMM_SMEM);
    cudaFuncSetAttribute(flash_cp,
                         cudaFuncAttributeMaxDynamicSharedMemorySize,
                         FLASH_SMEM);

    // one-time fp16 conversion of GEMM inputs
    conv_pass<<<(Mm_ * Cc_) / 1024, 256>>>(x, xh);
    conv_pass<<<(Cc_ * Cc_) / 1024, 256>>>(Wq, wqh);
    conv_pass<<<(Cc_ * KVN_) / 1024, 256>>>(Wkv, wkvh);
    conv_pass<<<(Cc_ * Cc_) / 1024, 256>>>(Wp, wph);

    // fused q + kv projections (fp16 mma; fp32 tf32-rounded outputs)
    qkv_gemm<<<dim3(24, Mm_ / 128), 256, GEMM_SMEM>>>(
        xh, wqh, bq, wkvh, bkv, qp, kvp);
    // attention (tf32; writes y as fp16)
    flash_cp<<<dim3(Tt_ / 128, Hh_, Bb_), 256, FLASH_SMEM>>>(qp, kvp, yh);
    // out = y @ Wp + bp (fp16 mma, exact fp32 output)
    pgemm_h<<<dim3(Cc_ / 128, Mm_ / 128), 256, GEMM_SMEM>>>(yh, wph, bp, out);
}

// round 13
// speedup vs baseline: 6.9232x; 1.4083x over previous
#include <cuda_runtime.h>
#include <cuda_fp16.h>
#include <math.h>
#include <stdint.h>

// Problem constants
#define Bb_ 2
#define Tt_ 2048
#define Cc_ 2048
#define Hh_ 16
#define HKV_ 4
#define HDv_ 128
#define Mm_ (Bb_ * Tt_)
#define KVN_ 1024

// Scratch (device globals; no allocation allowed)
__device__ __half g_qh[(size_t)Mm_ * Cc_];     // fp16 q
__device__ __half g_kvh[(size_t)Mm_ * KVN_];   // fp16 kv
__device__ __half g_yh[(size_t)Mm_ * Cc_];     // fp16 attention output
__device__ __half g_xh[(size_t)Mm_ * Cc_];     // fp16 x
__device__ __half g_wqh[(size_t)Cc_ * Cc_];    // fp16 Wq
__device__ __half g_wkvh[(size_t)Cc_ * KVN_];  // fp16 Wkv
__device__ __half g_wph[(size_t)Cc_ * Cc_];    // fp16 Wp

// ---- helpers ----------------------------------------------------------------
typedef unsigned long long u64t;

__device__ __forceinline__ u64t pk2(float lo, float hi) {
    u64t r;
    asm("mov.b64 %0, {%1, %2};" : "=l"(r) : "f"(lo), "f"(hi));
    return r;
}
__device__ __forceinline__ void mul2(u64t& d, u64t a, u64t b) {
    asm("mul.rn.f32x2 %0, %1, %2;" : "=l"(d) : "l"(a), "l"(b));
}
__device__ __forceinline__ float2 upk(u64t v) {
    float2 f;
    asm("mov.b64 {%0, %1}, %2;" : "=f"(f.x), "=f"(f.y) : "l"(v));
    return f;
}
__device__ __forceinline__ void mma_f16(float (&d)[4],
                                        const uint32_t (&a)[4],
                                        const uint32_t (&b)[2]) {
    asm volatile(
        "mma.sync.aligned.m16n8k16.row.col.f32.f16.f16.f32 "
        "{%0,%1,%2,%3}, {%4,%5,%6,%7}, {%8,%9}, {%0,%1,%2,%3};\n"
        : "+f"(d[0]), "+f"(d[1]), "+f"(d[2]), "+f"(d[3])
        : "r"(a[0]), "r"(a[1]), "r"(a[2]), "r"(a[3]), "r"(b[0]), "r"(b[1]));
}
__device__ __forceinline__ void ldsm_x4(uint32_t (&r)[4], uint32_t addr) {
    asm volatile(
        "ldmatrix.sync.aligned.m8n8.x4.shared.b16 {%0,%1,%2,%3}, [%4];"
        : "=r"(r[0]), "=r"(r[1]), "=r"(r[2]), "=r"(r[3]) : "r"(addr));
}
__device__ __forceinline__ void ldsm_x2t(uint32_t (&r)[2], uint32_t addr) {
    asm volatile(
        "ldmatrix.sync.aligned.m8n8.x2.trans.shared.b16 {%0,%1}, [%2];"
        : "=r"(r[0]), "=r"(r[1]) : "r"(addr));
}
__device__ __forceinline__ uint32_t smem_u32(const void* p) {
    uint32_t a;
    asm("{ .reg .u64 t; cvta.to.shared.u64 t, %1; cvt.u32.u64 %0, t; }"
        : "=r"(a) : "l"(p));
    return a;
}
__device__ __forceinline__ void cp16(uint32_t dst, const void* src) {
    asm volatile("cp.async.cg.shared.global [%0], [%1], 16;"
                 :: "r"(dst), "l"(src));
}
#define CP_COMMIT() asm volatile("cp.async.commit_group;" ::: "memory")
#define CP_WAIT(n)  asm volatile("cp.async.wait_group %0;" :: "n"(n) : "memory")

// ---------------------------------------------------------------------------
// One-time fp32 -> fp16 conversion (rn).
// ---------------------------------------------------------------------------
__global__ void __launch_bounds__(256)
conv_pass(const float* __restrict__ in, __half* __restrict__ out)
{
    const size_t i = ((size_t)blockIdx.x * 256 + threadIdx.x) * 4;
    const float4 v = *(const float4*)(in + i);
    *(__half2*)(out + i)     = __floats2half2_rn(v.x, v.y);
    *(__half2*)(out + i + 2) = __floats2half2_rn(v.z, v.w);
}

// ---------------------------------------------------------------------------
// fp16 m16n8k16 GEMM core, BK=32, 3-stage cp.async, ldmatrix fragments.
// 128x128 CTA, 8 warps (64x32). Output either fp32 (+bias) or fp16 (+bias).
// ---------------------------------------------------------------------------
#define GSTG 3
#define LDAH 40
#define LDBH 136
#define A_BYTES (128 * LDAH * 2)
#define B_BYTES (32 * LDBH * 2)
#define STG_BYTES (A_BYTES + B_BYTES)
#define GEMM_SMEM (GSTG * STG_BYTES)

__device__ __forceinline__ void gemm_issue_h(uint32_t sb, int buf,
                                             const __half* Ah, const __half* Bh,
                                             int K, int N, int k0, int tid)
{
    const uint32_t base = sb + buf * STG_BYTES;
#pragma unroll
    for (int u = 0; u < 2; u++) {
        const int ia = tid + u * 256;
        const int m  = ia >> 2;
        const int c8 = (ia & 3) * 8;
        cp16(base + (m * LDAH + c8) * 2, Ah + (size_t)m * K + k0 + c8);
        const int ib = tid + u * 256;
        const int k  = ib >> 4;
        const int n8 = (ib & 15) * 8;
        cp16(base + A_BYTES + (k * LDBH + n8) * 2,
             Bh + (size_t)(k0 + k) * N + n8);
    }
}

// outMode: 0 -> fp32 C, 1 -> fp16 C
template <int outMode>
__device__ __forceinline__ void gemm_core_h(const __half* Ah, const __half* Bh,
                                            const float* biasb, void* Cb,
                                            int K, int N, uint32_t sb)
{
    const int tid  = threadIdx.x;
    const int wid  = tid >> 5;
    const int lane = tid & 31;
    const int g    = lane >> 2;
    const int tg   = lane & 3;
    const int wm   = wid & 1;
    const int wn   = wid >> 1;

    const int arow_l = (lane & 7) + 8 * ((lane >> 3) & 1);
    const int acol_l = (lane >> 4) * 8;

    float acc[4][4][4];
#pragma unroll
    for (int mi = 0; mi < 4; mi++)
#pragma unroll
        for (int ni = 0; ni < 4; ni++)
#pragma unroll
            for (int r = 0; r < 4; r++) acc[mi][ni][r] = 0.f;

    const int nt = K / 32;

#pragma unroll
    for (int s = 0; s < GSTG - 1; s++) {
        if (s < nt) gemm_issue_h(sb, s, Ah, Bh, K, N, s * 32, tid);
        CP_COMMIT();
    }

    int buf = 0;
    for (int t = 0; t < nt; ++t) {
        CP_WAIT(1);
        __syncthreads();
        if (t + 2 < nt)
            gemm_issue_h(sb, (t + 2) % GSTG, Ah, Bh, K, N, (t + 2) * 32, tid);
        CP_COMMIT();

        const uint32_t base = sb + buf * STG_BYTES;
#pragma unroll
        for (int kc = 0; kc < 2; kc++) {
            uint32_t afr[4][4];
#pragma unroll
            for (int mi = 0; mi < 4; mi++) {
                const int row = wm * 64 + mi * 16 + arow_l;
                const int col = kc * 16 + acol_l;
                ldsm_x4(afr[mi], base + (row * LDAH + col) * 2);
            }
            uint32_t bfr[4][2];
#pragma unroll
            for (int ni = 0; ni < 4; ni++) {
                const int krow = kc * 16 + arow_l;
                const int ncol = wn * 32 + ni * 8;
                ldsm_x2t(bfr[ni], base + A_BYTES + (krow * LDBH + ncol) * 2);
            }
#pragma unroll
            for (int mi = 0; mi < 4; mi++)
#pragma unroll
                for (int ni = 0; ni < 4; ni++)
                    mma_f16(acc[mi][ni], afr[mi], bfr[ni]);
        }
        buf = (buf + 1 == GSTG) ? 0 : buf + 1;
    }

    // ---- epilogue: fused bias ----
#pragma unroll
    for (int mi = 0; mi < 4; mi++) {
        const int r0 = wm * 64 + mi * 16 + g;
#pragma unroll
        for (int ni = 0; ni < 4; ni++) {
            const int c0 = wn * 32 + ni * 8 + tg * 2;
            const float bx0 = biasb[c0], bx1 = biasb[c0 + 1];
            const float a0 = acc[mi][ni][0] + bx0;
            const float a1 = acc[mi][ni][1] + bx1;
            const float a2 = acc[mi][ni][2] + bx0;
            const float a3 = acc[mi][ni][3] + bx1;
            if (outMode == 0) {
                float* Cf = (float*)Cb;
                *(float2*)(Cf + (size_t)r0 * N + c0)       = make_float2(a0, a1);
                *(float2*)(Cf + (size_t)(r0 + 8) * N + c0) = make_float2(a2, a3);
            } else {
                __half* Ch = (__half*)Cb;
                *(__half2*)(Ch + (size_t)r0 * N + c0)       = __floats2half2_rn(a0, a1);
                *(__half2*)(Ch + (size_t)(r0 + 8) * N + c0) = __floats2half2_rn(a2, a3);
            }
        }
    }
}

// Fused q+kv projection (fp16 outputs): grid.x in [0,24).
__global__ void __launch_bounds__(256, 2)
qkv_gemm(const __half* __restrict__ xh,
         const __half* __restrict__ wqh, const float* __restrict__ bq,
         const __half* __restrict__ wkvh, const float* __restrict__ bkv,
         __half* __restrict__ qh, __half* __restrict__ kvh)
{
    extern __shared__ uint32_t smw[];
    const uint32_t sb = smem_u32(smw);
    const int bx = blockIdx.x;
    const __half* Ab = xh + (size_t)blockIdx.y * 128 * Cc_;

    if (bx < 16) {
        const int cb = bx * 128;
        gemm_core_h<1>(Ab, wqh + cb, bq + cb,
                       qh + (size_t)blockIdx.y * 128 * Cc_ + cb,
                       Cc_, Cc_, sb);
    } else {
        const int cb = (bx - 16) * 128;
        gemm_core_h<1>(Ab, wkvh + cb, bkv + cb,
                       kvh + (size_t)blockIdx.y * 128 * KVN_ + cb,
                       Cc_, KVN_, sb);
    }
}

// Final projection: out = yh @ Wp + bp (fp32 output)
__global__ void __launch_bounds__(256, 2)
pgemm_h(const __half* __restrict__ A, const __half* __restrict__ B,
        const float* __restrict__ bias, float* __restrict__ C)
{
    extern __shared__ uint32_t smw[];
    const uint32_t sb = smem_u32(smw);
    const int cb = blockIdx.x * 128;
    gemm_core_h<0>(A + (size_t)blockIdx.y * 128 * Cc_, B + cb, bias + cb,
                   C + (size_t)blockIdx.y * 128 * Cc_ + cb,
                   Cc_, Cc_, sb);
}

// ---------------------------------------------------------------------------
// Flash attention, fp16 m16n8k16, double-buffered cp.async K/V,
// one __syncthreads per kt. Br=128 (8 warps x 16 rows), Bc=64, HD=128.
// ---------------------------------------------------------------------------
#define LDKH 136                         // K/V smem row stride (halfs)
#define KVB (64 * LDKH * 2)              // 17408 B per K or V buffer
#define STG_FB (2 * KVB)                 // K+V stage
#define PS_OFF (2 * STG_FB)              // 69632
#define LDPH 72                          // P smem row stride (halfs)
#define FLASH_SMEM (PS_OFF + 128 * LDPH * 2)   // 88064 B

__device__ __forceinline__ void flash_issue_h(uint32_t sb, int buf,
                                              const __half* kvbase, int tid)
{
    const uint32_t kb = sb + buf * STG_FB;
    const uint32_t vb = kb + KVB;
#pragma unroll
    for (int u = 0; u < 4; u++) {
        const int i  = tid + u * 256;     // 0..1023
        const int r  = i >> 4;
        const int c8 = (i & 15) * 8;
        const __half* src = kvbase + (size_t)r * KVN_ + c8;
        cp16(kb + (r * LDKH + c8) * 2, src);
        cp16(vb + (r * LDKH + c8) * 2, src + 512);
    }
}

__global__ void __launch_bounds__(256, 1)
flash_h(const __half* __restrict__ q, const __half* __restrict__ kv,
        __half* __restrict__ y)
{
    extern __shared__ char smc[];
    const uint32_t sb = smem_u32(smc);
    __half* Ps = (__half*)(smc + PS_OFF);
    const uint32_t psb = sb + PS_OFF;

    const int qt = (int)gridDim.x - 1 - (int)blockIdx.x;  // longest-first
    const int h  = blockIdx.y;
    const int b  = blockIdx.z;
    const int kvh = h & (HKV_ - 1);

    const int tid  = threadIdx.x;
    const int w    = tid >> 5;
    const int lane = tid & 31;
    const int g    = lane >> 2;
    const int tg   = lane & 3;
    const int arow_l = (lane & 7) + 8 * ((lane >> 3) & 1);
    const int acol_l = (lane >> 4) * 8;
    const float scale = 0.08838834764831843f;  // 1/sqrt(128)

    const int rloc0 = w * 16 + g;
    const int grow0 = qt * 128 + rloc0;
    const int grow1 = grow0 + 8;

    // ---- load Q once as fp16 A-fragments (8 k-chunks of 16) ----
    uint32_t qf[8][4];
    {
        const __half* qb = q + ((size_t)(b * Tt_) + qt * 128 + w * 16) * Cc_
                             + h * HDv_;
#pragma unroll
        for (int kc = 0; kc < 8; kc++) {
            const int d0 = kc * 16 + tg * 2;
            qf[kc][0] = *(const uint32_t*)(qb + (size_t)g * Cc_ + d0);
            qf[kc][1] = *(const uint32_t*)(qb + (size_t)(g + 8) * Cc_ + d0);
            qf[kc][2] = *(const uint32_t*)(qb + (size_t)g * Cc_ + d0 + 8);
            qf[kc][3] = *(const uint32_t*)(qb + (size_t)(g + 8) * Cc_ + d0 + 8);
        }
    }

    float of[16][4];
#pragma unroll
    for (int ni = 0; ni < 16; ni++)
#pragma unroll
        for (int r = 0; r < 4; r++) of[ni][r] = 0.f;
    float m0 = -INFINITY, m1 = -INFINITY, l0 = 0.f, l1 = 0.f;

    const int ktmax = 2 * qt + 1;
    const __half* kvb0 = kv + (size_t)(b * Tt_) * KVN_ + kvh * HDv_;

    flash_issue_h(sb, 0, kvb0, tid);
    CP_COMMIT();

    for (int kt = 0; kt <= ktmax; ++kt) {
        const int cur = kt & 1;
        CP_WAIT(0);
        __syncthreads();
        if (kt < ktmax) {
            flash_issue_h(sb, cur ^ 1, kvb0 + (size_t)(kt + 1) * 64 * KVN_, tid);
            CP_COMMIT();
        }

        const uint32_t kbase = sb + cur * STG_FB;
        const uint32_t vbase = kbase + KVB;
        const __half* Kb = (const __half*)(smc + cur * STG_FB);

        const bool act = (kt * 64) <= (qt * 128 + w * 16 + 15);
        if (act) {
            // ---- S = Q K^T : 8 kc x 8 ni fp16 MMAs ----
            float sf[8][4];
#pragma unroll
            for (int ni = 0; ni < 8; ni++)
#pragma unroll
                for (int r = 0; r < 4; r++) sf[ni][r] = 0.f;

#pragma unroll
            for (int kc = 0; kc < 8; kc++) {
#pragma unroll
                for (int ni = 0; ni < 8; ni++) {
                    uint32_t bfr[2];
                    const __half* krow = Kb + (ni * 8 + g) * LDKH + kc * 16 + tg * 2;
                    bfr[0] = *(const uint32_t*)(krow);
                    bfr[1] = *(const uint32_t*)(krow + 8);
                    mma_f16(sf[ni], qf[kc], bfr);
                }
            }

            // scale S (fp32)
#pragma unroll
            for (int ni = 0; ni < 8; ni++)
#pragma unroll
                for (int r = 0; r < 4; r++) sf[ni][r] *= scale;

            // ---- causal mask ----
            if (kt * 64 + 63 > qt * 128 + w * 16) {
                const int cb = kt * 64;
#pragma unroll
                for (int ni = 0; ni < 8; ni++) {
                    const int c0 = cb + ni * 8 + tg * 2;
                    if (c0 > grow0)     sf[ni][0] = -1e30f;
                    if (c0 + 1 > grow0) sf[ni][1] = -1e30f;
                    if (c0 > grow1)     sf[ni][2] = -1e30f;
                    if (c0 + 1 > grow1) sf[ni][3] = -1e30f;
                }
            }

            // ---- online softmax (rows g, g+8) ----
            float mx0 = -1e30f, mx1 = -1e30f;
#pragma unroll
            for (int ni = 0; ni < 8; ni++) {
                mx0 = fmaxf(mx0, fmaxf(sf[ni][0], sf[ni][1]));
                mx1 = fmaxf(mx1, fmaxf(sf[ni][2], sf[ni][3]));
            }
            mx0 = fmaxf(mx0, __shfl_xor_sync(0xffffffffu, mx0, 1));
            mx0 = fmaxf(mx0, __shfl_xor_sync(0xffffffffu, mx0, 2));
            mx1 = fmaxf(mx1, __shfl_xor_sync(0xffffffffu, mx1, 1));
            mx1 = fmaxf(mx1, __shfl_xor_sync(0xffffffffu, mx1, 2));

            const float nm0 = fmaxf(m0, mx0);
            const float nm1 = fmaxf(m1, mx1);
            float sum0 = 0.f, sum1 = 0.f;
#pragma unroll
            for (int ni = 0; ni < 8; ni++) {
                sf[ni][0] = __expf(sf[ni][0] - nm0);
                sf[ni][1] = __expf(sf[ni][1] - nm0);
                sf[ni][2] = __expf(sf[ni][2] - nm1);
                sf[ni][3] = __expf(sf[ni][3] - nm1);
                sum0 += sf[ni][0] + sf[ni][1];
                sum1 += sf[ni][2] + sf[ni][3];
            }
            sum0 += __shfl_xor_sync(0xffffffffu, sum0, 1);
            sum0 += __shfl_xor_sync(0xffffffffu, sum0, 2);
            sum1 += __shfl_xor_sync(0xffffffffu, sum1, 1);
            sum1 += __shfl_xor_sync(0xffffffffu, sum1, 2);

            const float al0 = __expf(m0 - nm0);
            const float al1 = __expf(m1 - nm1);
            m0 = nm0; m1 = nm1;
            l0 = l0 * al0 + sum0;
            l1 = l1 * al1 + sum1;

            // ---- P -> fp16 warp-private smem strip ----
#pragma unroll
            for (int ni = 0; ni < 8; ni++) {
                *(__half2*)(Ps + (w * 16 + g) * LDPH + ni * 8 + tg * 2) =
                    __floats2half2_rn(sf[ni][0], sf[ni][1]);
                *(__half2*)(Ps + (w * 16 + 8 + g) * LDPH + ni * 8 + tg * 2) =
                    __floats2half2_rn(sf[ni][2], sf[ni][3]);
            }
            __syncwarp();

            // ---- rescale O ----
            {
                const u64t a0p = pk2(al0, al0);
                const u64t a1p = pk2(al1, al1);
#pragma unroll
                for (int ni = 0; ni < 16; ni++) {
                    u64t v01 = pk2(of[ni][0], of[ni][1]);
                    u64t v23 = pk2(of[ni][2], of[ni][3]);
                    mul2(v01, v01, a0p);
                    mul2(v23, v23, a1p);
                    const float2 f01 = upk(v01), f23 = upk(v23);
                    of[ni][0] = f01.x; of[ni][1] = f01.y;
                    of[ni][2] = f23.x; of[ni][3] = f23.y;
                }
            }

            // ---- O += P V : 4 kc x 16 ni fp16 MMAs ----
#pragma unroll
            for (int kc = 0; kc < 4; kc++) {
                uint32_t pa[4];
                ldsm_x4(pa, psb + ((w * 16 + arow_l) * LDPH + kc * 16 + acol_l) * 2);
#pragma unroll
                for (int ni = 0; ni < 16; ni++) {
                    uint32_t vb2[2];
                    ldsm_x2t(vb2, vbase + ((kc * 16 + arow_l) * LDKH + ni * 8) * 2);
                    mma_f16(of[ni], pa, vb2);
                }
            }
        }
    }

    // ---- normalize + store fp16 ----
    const float inv0 = 1.f / l0;
    const float inv1 = 1.f / l1;
    __half* y0 = y + ((size_t)(b * Tt_) + grow0) * Cc_ + h * HDv_;
    __half* y1 = y + ((size_t)(b * Tt_) + grow1) * Cc_ + h * HDv_;
#pragma unroll
    for (int ni = 0; ni < 16; ni++) {
        const int c0 = ni * 8 + tg * 2;
        *(__half2*)(y0 + c0) =
            __floats2half2_rn(of[ni][0] * inv0, of[ni][1] * inv0);
        *(__half2*)(y1 + c0) =
            __floats2half2_rn(of[ni][2] * inv1, of[ni][3] * inv1);
    }
}

// ---------------------------------------------------------------------------
extern "C" void kernel_launch(void* const* d_in, const int* in_sizes, int n_in,
                              void* d_out, int out_size)
{
    const float* x   = (const float*)d_in[0];
    const float* Wkv = (const float*)d_in[1];
    const float* bkv = (const float*)d_in[2];
    const float* Wq  = (const float*)d_in[3];
    const float* bq  = (const float*)d_in[4];
    const float* Wp  = (const float*)d_in[5];
    const float* bp  = (const float*)d_in[6];
    float* out = (float*)d_out;

    __half *qh, *kvh, *yh, *xh, *wqh, *wkvh, *wph;
    cudaGetSymbolAddress((void**)&qh,   g_qh);
    cudaGetSymbolAddress((void**)&kvh,  g_kvh);
    cudaGetSymbolAddress((void**)&yh,   g_yh);
    cudaGetSymbolAddress((void**)&xh,   g_xh);
    cudaGetSymbolAddress((void**)&wqh,  g_wqh);
    cudaGetSymbolAddress((void**)&wkvh, g_wkvh);
    cudaGetSymbolAddress((void**)&wph,  g_wph);

    cudaFuncSetAttribute(qkv_gemm,
                         cudaFuncAttributeMaxDynamicSharedMemorySize,
                         GEMM_SMEM);
    cudaFuncSetAttribute(pgemm_h,
                         cudaFuncAttributeMaxDynamicSharedMemorySize,
                         GEMM_SMEM);
    cudaFuncSetAttribute(flash_h,
                         cudaFuncAttributeMaxDynamicSharedMemorySize,
                         FLASH_SMEM);

    // one-time fp16 conversion of GEMM inputs
    conv_pass<<<(Mm_ * Cc_) / 1024, 256>>>(x, xh);
    conv_pass<<<(Cc_ * Cc_) / 1024, 256>>>(Wq, wqh);
    conv_pass<<<(Cc_ * KVN_) / 1024, 256>>>(Wkv, wkvh);
    conv_pass<<<(Cc_ * Cc_) / 1024, 256>>>(Wp, wph);

    // fused q + kv projections (fp16 outputs)
    qkv_gemm<<<dim3(24, Mm_ / 128), 256, GEMM_SMEM>>>(
        xh, wqh, bq, wkvh, bkv, qh, kvh);
    // attention (fp16 mma, fp32 softmax)
    flash_h<<<dim3(Tt_ / 128, Hh_, Bb_), 256, FLASH_SMEM>>>(qh, kvh, yh);
    // out = y @ Wp + bp
    pgemm_h<<<dim3(Cc_ / 128, Mm_ / 128), 256, GEMM_SMEM>>>(yh, wph, bp, out);
}

// round 14
// speedup vs baseline: 7.4430x; 1.0751x over previous
#include <cuda_runtime.h>
#include <cuda_fp16.h>
#include <math.h>
#include <stdint.h>

// Problem constants
#define Bb_ 2
#define Tt_ 2048
#define Cc_ 2048
#define Hh_ 16
#define HKV_ 4
#define HDv_ 128
#define Mm_ (Bb_ * Tt_)
#define KVN_ 1024

// Scratch (device globals; no allocation allowed)
__device__ __half g_qh[(size_t)Mm_ * Cc_];
__device__ __half g_kvh[(size_t)Mm_ * KVN_];
__device__ __half g_yh[(size_t)Mm_ * Cc_];
__device__ __half g_xh[(size_t)Mm_ * Cc_];
__device__ __half g_wqh[(size_t)Cc_ * Cc_];
__device__ __half g_wkvh[(size_t)Cc_ * KVN_];
__device__ __half g_wph[(size_t)Cc_ * Cc_];

// ---- helpers ----------------------------------------------------------------
typedef unsigned long long u64t;

__device__ __forceinline__ u64t pk2(float lo, float hi) {
    u64t r;
    asm("mov.b64 %0, {%1, %2};" : "=l"(r) : "f"(lo), "f"(hi));
    return r;
}
__device__ __forceinline__ void mul2(u64t& d, u64t a, u64t b) {
    asm("mul.rn.f32x2 %0, %1, %2;" : "=l"(d) : "l"(a), "l"(b));
}
__device__ __forceinline__ float2 upk(u64t v) {
    float2 f;
    asm("mov.b64 {%0, %1}, %2;" : "=f"(f.x), "=f"(f.y) : "l"(v));
    return f;
}
__device__ __forceinline__ void mma_f16(float (&d)[4],
                                        const uint32_t (&a)[4],
                                        const uint32_t (&b)[2]) {
    asm volatile(
        "mma.sync.aligned.m16n8k16.row.col.f32.f16.f16.f32 "
        "{%0,%1,%2,%3}, {%4,%5,%6,%7}, {%8,%9}, {%0,%1,%2,%3};\n"
        : "+f"(d[0]), "+f"(d[1]), "+f"(d[2]), "+f"(d[3])
        : "r"(a[0]), "r"(a[1]), "r"(a[2]), "r"(a[3]), "r"(b[0]), "r"(b[1]));
}
__device__ __forceinline__ void ldsm_x4(uint32_t (&r)[4], uint32_t addr) {
    asm volatile(
        "ldmatrix.sync.aligned.m8n8.x4.shared.b16 {%0,%1,%2,%3}, [%4];"
        : "=r"(r[0]), "=r"(r[1]), "=r"(r[2]), "=r"(r[3]) : "r"(addr));
}
__device__ __forceinline__ void ldsm_x2t(uint32_t (&r)[2], uint32_t addr) {
    asm volatile(
        "ldmatrix.sync.aligned.m8n8.x2.trans.shared.b16 {%0,%1}, [%2];"
        : "=r"(r[0]), "=r"(r[1]) : "r"(addr));
}
__device__ __forceinline__ uint32_t smem_u32(const void* p) {
    uint32_t a;
    asm("{ .reg .u64 t; cvta.to.shared.u64 t, %1; cvt.u32.u64 %0, t; }"
        : "=r"(a) : "l"(p));
    return a;
}
__device__ __forceinline__ void cp16(uint32_t dst, const void* src) {
    asm volatile("cp.async.cg.shared.global [%0], [%1], 16;"
                 :: "r"(dst), "l"(src));
}
#define CP_COMMIT() asm volatile("cp.async.commit_group;" ::: "memory")
#define CP_WAIT(n)  asm volatile("cp.async.wait_group %0;" :: "n"(n) : "memory")

// ---------------------------------------------------------------------------
// One-time fp32 -> fp16 conversion (rn).
// ---------------------------------------------------------------------------
__global__ void __launch_bounds__(256)
conv_pass(const float* __restrict__ in, __half* __restrict__ out)
{
    const size_t i = ((size_t)blockIdx.x * 256 + threadIdx.x) * 4;
    const float4 v = *(const float4*)(in + i);
    *(__half2*)(out + i)     = __floats2half2_rn(v.x, v.y);
    *(__half2*)(out + i + 2) = __floats2half2_rn(v.z, v.w);
}

// ---------------------------------------------------------------------------
// fp16 m16n8k16 GEMM core, BK=64, 3-stage cp.async, ldmatrix fragments.
// 128x128 CTA, 8 warps (64x32). One barrier per 64 K.
// ---------------------------------------------------------------------------
#define GSTG 3
#define LDAH 72                      // A row stride (halfs), BK=64 + pad 8
#define LDBH 136                     // B row stride (halfs)
#define A_BYTES (128 * LDAH * 2)     // 18432
#define B_BYTES (64 * LDBH * 2)      // 17408
#define STG_BYTES (A_BYTES + B_BYTES)
#define GEMM_SMEM (GSTG * STG_BYTES) // 107520

__device__ __forceinline__ void gemm_issue_h(uint32_t sb, int buf,
                                             const __half* Ah, const __half* Bh,
                                             int K, int N, int k0, int tid)
{
    const uint32_t base = sb + buf * STG_BYTES;
#pragma unroll
    for (int u = 0; u < 4; u++) {
        const int ia = tid + u * 256;          // 0..1023
        const int m  = ia >> 3;
        const int c8 = (ia & 7) * 8;
        cp16(base + (m * LDAH + c8) * 2, Ah + (size_t)m * K + k0 + c8);
        const int ib = tid + u * 256;
        const int k  = ib >> 4;
        const int n8 = (ib & 15) * 8;
        cp16(base + A_BYTES + (k * LDBH + n8) * 2,
             Bh + (size_t)(k0 + k) * N + n8);
    }
}

// outMode: 0 -> fp32 C, 1 -> fp16 C
template <int outMode>
__device__ __forceinline__ void gemm_core_h(const __half* Ah, const __half* Bh,
                                            const float* biasb, void* Cb,
                                            int K, int N, uint32_t sb)
{
    const int tid  = threadIdx.x;
    const int wid  = tid >> 5;
    const int lane = tid & 31;
    const int g    = lane >> 2;
    const int tg   = lane & 3;
    const int wm   = wid & 1;
    const int wn   = wid >> 1;

    const int arow_l = (lane & 7) + 8 * ((lane >> 3) & 1);
    const int acol_l = (lane >> 4) * 8;

    float acc[4][4][4];
#pragma unroll
    for (int mi = 0; mi < 4; mi++)
#pragma unroll
        for (int ni = 0; ni < 4; ni++)
#pragma unroll
            for (int r = 0; r < 4; r++) acc[mi][ni][r] = 0.f;

    const int nt = K / 64;

#pragma unroll
    for (int s = 0; s < GSTG - 1; s++) {
        if (s < nt) gemm_issue_h(sb, s, Ah, Bh, K, N, s * 64, tid);
        CP_COMMIT();
    }

    int buf = 0;
    for (int t = 0; t < nt; ++t) {
        CP_WAIT(1);
        __syncthreads();
        if (t + 2 < nt)
            gemm_issue_h(sb, (t + 2) % GSTG, Ah, Bh, K, N, (t + 2) * 64, tid);
        CP_COMMIT();

        const uint32_t base = sb + buf * STG_BYTES;
#pragma unroll
        for (int kc = 0; kc < 4; kc++) {
            uint32_t afr[4][4];
#pragma unroll
            for (int mi = 0; mi < 4; mi++) {
                const int row = wm * 64 + mi * 16 + arow_l;
                const int col = kc * 16 + acol_l;
                ldsm_x4(afr[mi], base + (row * LDAH + col) * 2);
            }
            uint32_t bfr[4][2];
#pragma unroll
            for (int ni = 0; ni < 4; ni++) {
                const int krow = kc * 16 + arow_l;
                const int ncol = wn * 32 + ni * 8;
                ldsm_x2t(bfr[ni], base + A_BYTES + (krow * LDBH + ncol) * 2);
            }
#pragma unroll
            for (int mi = 0; mi < 4; mi++)
#pragma unroll
                for (int ni = 0; ni < 4; ni++)
                    mma_f16(acc[mi][ni], afr[mi], bfr[ni]);
        }
        buf = (buf + 1 == GSTG) ? 0 : buf + 1;
    }

    // ---- epilogue: fused bias ----
#pragma unroll
    for (int mi = 0; mi < 4; mi++) {
        const int r0 = wm * 64 + mi * 16 + g;
#pragma unroll
        for (int ni = 0; ni < 4; ni++) {
            const int c0 = wn * 32 + ni * 8 + tg * 2;
            const float bx0 = biasb[c0], bx1 = biasb[c0 + 1];
            const float a0 = acc[mi][ni][0] + bx0;
            const float a1 = acc[mi][ni][1] + bx1;
            const float a2 = acc[mi][ni][2] + bx0;
            const float a3 = acc[mi][ni][3] + bx1;
            if (outMode == 0) {
                float* Cf = (float*)Cb;
                *(float2*)(Cf + (size_t)r0 * N + c0)       = make_float2(a0, a1);
                *(float2*)(Cf + (size_t)(r0 + 8) * N + c0) = make_float2(a2, a3);
            } else {
                __half* Ch = (__half*)Cb;
                *(__half2*)(Ch + (size_t)r0 * N + c0)       = __floats2half2_rn(a0, a1);
                *(__half2*)(Ch + (size_t)(r0 + 8) * N + c0) = __floats2half2_rn(a2, a3);
            }
        }
    }
}

// Fused q+kv projection (fp16 outputs): grid.x in [0,24).
__global__ void __launch_bounds__(256, 2)
qkv_gemm(const __half* __restrict__ xh,
         const __half* __restrict__ wqh, const float* __restrict__ bq,
         const __half* __restrict__ wkvh, const float* __restrict__ bkv,
         __half* __restrict__ qh, __half* __restrict__ kvh)
{
    extern __shared__ uint32_t smw[];
    const uint32_t sb = smem_u32(smw);
    const int bx = blockIdx.x;
    const __half* Ab = xh + (size_t)blockIdx.y * 128 * Cc_;

    if (bx < 16) {
        const int cb = bx * 128;
        gemm_core_h<1>(Ab, wqh + cb, bq + cb,
                       qh + (size_t)blockIdx.y * 128 * Cc_ + cb,
                       Cc_, Cc_, sb);
    } else {
        const int cb = (bx - 16) * 128;
        gemm_core_h<1>(Ab, wkvh + cb, bkv + cb,
                       kvh + (size_t)blockIdx.y * 128 * KVN_ + cb,
                       Cc_, KVN_, sb);
    }
}

// Final projection: out = yh @ Wp + bp (fp32 output)
__global__ void __launch_bounds__(256, 2)
pgemm_h(const __half* __restrict__ A, const __half* __restrict__ B,
        const float* __restrict__ bias, float* __restrict__ C)
{
    extern __shared__ uint32_t smw[];
    const uint32_t sb = smem_u32(smw);
    const int cb = blockIdx.x * 128;
    gemm_core_h<0>(A + (size_t)blockIdx.y * 128 * Cc_, B + cb, bias + cb,
                   C + (size_t)blockIdx.y * 128 * Cc_ + cb,
                   Cc_, Cc_, sb);
}

// ---------------------------------------------------------------------------
// Flash attention, fp16 m16n8k16, Bc=128, double-buffered cp.async K/V,
// one __syncthreads per kt. Br=128 (8 warps x 16 rows), HD=128.
// ---------------------------------------------------------------------------
#define LDKH 136                         // K/V smem row stride (halfs)
#define KVB (128 * LDKH * 2)             // 34816 B per K or V buffer
#define STG_FB (2 * KVB)                 // K+V stage: 69632
#define PS_OFF (2 * STG_FB)              // 139264
#define LDPH 136                         // P smem row stride (halfs)
#define FLASH_SMEM (PS_OFF + 128 * LDPH * 2)   // 174080 B

__device__ __forceinline__ void flash_issue_h(uint32_t sb, int buf,
                                              const __half* kvbase, int tid)
{
    const uint32_t kb = sb + buf * STG_FB;
    const uint32_t vb = kb + KVB;
#pragma unroll
    for (int u = 0; u < 8; u++) {
        const int i  = tid + u * 256;     // 0..2047
        const int r  = i >> 4;            // 0..127
        const int c8 = (i & 15) * 8;
        const __half* src = kvbase + (size_t)r * KVN_ + c8;
        cp16(kb + (r * LDKH + c8) * 2, src);
        cp16(vb + (r * LDKH + c8) * 2, src + 512);
    }
}

__global__ void __launch_bounds__(256, 1)
flash_h(const __half* __restrict__ q, const __half* __restrict__ kv,
        __half* __restrict__ y)
{
    extern __shared__ char smc[];
    const uint32_t sb = smem_u32(smc);
    __half* Ps = (__half*)(smc + PS_OFF);
    const uint32_t psb = sb + PS_OFF;

    const int qt = (int)gridDim.x - 1 - (int)blockIdx.x;  // longest-first
    const int h  = blockIdx.y;
    const int b  = blockIdx.z;
    const int kvh = h & (HKV_ - 1);

    const int tid  = threadIdx.x;
    const int w    = tid >> 5;
    const int lane = tid & 31;
    const int g    = lane >> 2;
    const int tg   = lane & 3;
    const int arow_l = (lane & 7) + 8 * ((lane >> 3) & 1);
    const int acol_l = (lane >> 4) * 8;
    const float scale = 0.08838834764831843f;  // 1/sqrt(128)

    const int rloc0 = w * 16 + g;
    const int grow0 = qt * 128 + rloc0;
    const int grow1 = grow0 + 8;

    // ---- load Q once as fp16 A-fragments ----
    uint32_t qf[8][4];
    {
        const __half* qb = q + ((size_t)(b * Tt_) + qt * 128 + w * 16) * Cc_
                             + h * HDv_;
#pragma unroll
        for (int kc = 0; kc < 8; kc++) {
            const int d0 = kc * 16 + tg * 2;
            qf[kc][0] = *(const uint32_t*)(qb + (size_t)g * Cc_ + d0);
            qf[kc][1] = *(const uint32_t*)(qb + (size_t)(g + 8) * Cc_ + d0);
            qf[kc][2] = *(const uint32_t*)(qb + (size_t)g * Cc_ + d0 + 8);
            qf[kc][3] = *(const uint32_t*)(qb + (size_t)(g + 8) * Cc_ + d0 + 8);
        }
    }

    float of[16][4];
#pragma unroll
    for (int ni = 0; ni < 16; ni++)
#pragma unroll
        for (int r = 0; r < 4; r++) of[ni][r] = 0.f;
    float m0 = -INFINITY, m1 = -INFINITY, l0 = 0.f, l1 = 0.f;

    const __half* kvb0 = kv + (size_t)(b * Tt_) * KVN_ + kvh * HDv_;

    flash_issue_h(sb, 0, kvb0, tid);
    CP_COMMIT();

    for (int kt = 0; kt <= qt; ++kt) {
        const int cur = kt & 1;
        CP_WAIT(0);
        __syncthreads();
        if (kt < qt) {
            flash_issue_h(sb, cur ^ 1, kvb0 + (size_t)(kt + 1) * 128 * KVN_, tid);
            CP_COMMIT();
        }

        const uint32_t vbase = sb + cur * STG_FB + KVB;
        const __half* Kb = (const __half*)(smc + cur * STG_FB);

        // ---- S = Q K^T : 8 kc x 16 ni fp16 MMAs ----
        float sf[16][4];
#pragma unroll
        for (int ni = 0; ni < 16; ni++)
#pragma unroll
            for (int r = 0; r < 4; r++) sf[ni][r] = 0.f;

#pragma unroll
        for (int kc = 0; kc < 8; kc++) {
#pragma unroll
            for (int ni = 0; ni < 16; ni++) {
                uint32_t bfr[2];
                const __half* krow = Kb + (ni * 8 + g) * LDKH + kc * 16 + tg * 2;
                bfr[0] = *(const uint32_t*)(krow);
                bfr[1] = *(const uint32_t*)(krow + 8);
                mma_f16(sf[ni], qf[kc], bfr);
            }
        }

        // scale S (fp32)
#pragma unroll
        for (int ni = 0; ni < 16; ni++)
#pragma unroll
            for (int r = 0; r < 4; r++) sf[ni][r] *= scale;

        // ---- causal mask (diagonal tile only) ----
        if (kt == qt) {
#pragma unroll
            for (int ni = 0; ni < 16; ni++) {
                const int c0 = kt * 128 + ni * 8 + tg * 2;
                if (c0 > grow0)     sf[ni][0] = -1e30f;
                if (c0 + 1 > grow0) sf[ni][1] = -1e30f;
                if (c0 > grow1)     sf[ni][2] = -1e30f;
                if (c0 + 1 > grow1) sf[ni][3] = -1e30f;
            }
        }

        // ---- online softmax (rows g, g+8) ----
        float mx0 = -1e30f, mx1 = -1e30f;
#pragma unroll
        for (int ni = 0; ni < 16; ni++) {
            mx0 = fmaxf(mx0, fmaxf(sf[ni][0], sf[ni][1]));
            mx1 = fmaxf(mx1, fmaxf(sf[ni][2], sf[ni][3]));
        }
        mx0 = fmaxf(mx0, __shfl_xor_sync(0xffffffffu, mx0, 1));
        mx0 = fmaxf(mx0, __shfl_xor_sync(0xffffffffu, mx0, 2));
        mx1 = fmaxf(mx1, __shfl_xor_sync(0xffffffffu, mx1, 1));
        mx1 = fmaxf(mx1, __shfl_xor_sync(0xffffffffu, mx1, 2));

        const float nm0 = fmaxf(m0, mx0);
        const float nm1 = fmaxf(m1, mx1);
        float sum0 = 0.f, sum1 = 0.f;
#pragma unroll
        for (int ni = 0; ni < 16; ni++) {
            sf[ni][0] = __expf(sf[ni][0] - nm0);
            sf[ni][1] = __expf(sf[ni][1] - nm0);
            sf[ni][2] = __expf(sf[ni][2] - nm1);
            sf[ni][3] = __expf(sf[ni][3] - nm1);
            sum0 += sf[ni][0] + sf[ni][1];
            sum1 += sf[ni][2] + sf[ni][3];
        }
        sum0 += __shfl_xor_sync(0xffffffffu, sum0, 1);
        sum0 += __shfl_xor_sync(0xffffffffu, sum0, 2);
        sum1 += __shfl_xor_sync(0xffffffffu, sum1, 1);
        sum1 += __shfl_xor_sync(0xffffffffu, sum1, 2);

        const float al0 = __expf(m0 - nm0);
        const float al1 = __expf(m1 - nm1);
        m0 = nm0; m1 = nm1;
        l0 = l0 * al0 + sum0;
        l1 = l1 * al1 + sum1;

        // ---- P -> fp16 warp-private smem strip ----
#pragma unroll
        for (int ni = 0; ni < 16; ni++) {
            *(__half2*)(Ps + (w * 16 + g) * LDPH + ni * 8 + tg * 2) =
                __floats2half2_rn(sf[ni][0], sf[ni][1]);
            *(__half2*)(Ps + (w * 16 + 8 + g) * LDPH + ni * 8 + tg * 2) =
                __floats2half2_rn(sf[ni][2], sf[ni][3]);
        }
        __syncwarp();

        // ---- rescale O ----
        {
            const u64t a0p = pk2(al0, al0);
            const u64t a1p = pk2(al1, al1);
#pragma unroll
            for (int ni = 0; ni < 16; ni++) {
                u64t v01 = pk2(of[ni][0], of[ni][1]);
                u64t v23 = pk2(of[ni][2], of[ni][3]);
                mul2(v01, v01, a0p);
                mul2(v23, v23, a1p);
                const float2 f01 = upk(v01), f23 = upk(v23);
                of[ni][0] = f01.x; of[ni][1] = f01.y;
                of[ni][2] = f23.x; of[ni][3] = f23.y;
            }
        }

        // ---- O += P V : 8 kc x 16 ni fp16 MMAs ----
#pragma unroll
        for (int kc = 0; kc < 8; kc++) {
            uint32_t pa[4];
            ldsm_x4(pa, psb + ((w * 16 + arow_l) * LDPH + kc * 16 + acol_l) * 2);
#pragma unroll
            for (int ni = 0; ni < 16; ni++) {
                uint32_t vb2[2];
                ldsm_x2t(vb2, vbase + ((kc * 16 + arow_l) * LDKH + ni * 8) * 2);
                mma_f16(of[ni], pa, vb2);
            }
        }
    }

    // ---- normalize + store fp16 ----
    const float inv0 = 1.f / l0;
    const float inv1 = 1.f / l1;
    __half* y0 = y + ((size_t)(b * Tt_) + grow0) * Cc_ + h * HDv_;
    __half* y1 = y + ((size_t)(b * Tt_) + grow1) * Cc_ + h * HDv_;
#pragma unroll
    for (int ni = 0; ni < 16; ni++) {
        const int c0 = ni * 8 + tg * 2;
        *(__half2*)(y0 + c0) =
            __floats2half2_rn(of[ni][0] * inv0, of[ni][1] * inv0);
        *(__half2*)(y1 + c0) =
            __floats2half2_rn(of[ni][2] * inv1, of[ni][3] * inv1);
    }
}

// ---------------------------------------------------------------------------
extern "C" void kernel_launch(void* const* d_in, const int* in_sizes, int n_in,
                              void* d_out, int out_size)
{
    const float* x   = (const float*)d_in[0];
    const float* Wkv = (const float*)d_in[1];
    const float* bkv = (const float*)d_in[2];
    const float* Wq  = (const float*)d_in[3];
    const float* bq  = (const float*)d_in[4];
    const float* Wp  = (const float*)d_in[5];
    const float* bp  = (const float*)d_in[6];
    float* out = (float*)d_out;

    __half *qh, *kvh, *yh, *xh, *wqh, *wkvh, *wph;
    cudaGetSymbolAddress((void**)&qh,   g_qh);
    cudaGetSymbolAddress((void**)&kvh,  g_kvh);
    cudaGetSymbolAddress((void**)&yh,   g_yh);
    cudaGetSymbolAddress((void**)&xh,   g_xh);
    cudaGetSymbolAddress((void**)&wqh,  g_wqh);
    cudaGetSymbolAddress((void**)&wkvh, g_wkvh);
    cudaGetSymbolAddress((void**)&wph,  g_wph);

    cudaFuncSetAttribute(qkv_gemm,
                         cudaFuncAttributeMaxDynamicSharedMemorySize,
                         GEMM_SMEM);
    cudaFuncSetAttribute(pgemm_h,
                         cudaFuncAttributeMaxDynamicSharedMemorySize,
                         GEMM_SMEM);
    cudaFuncSetAttribute(flash_h,
                         cudaFuncAttributeMaxDynamicSharedMemorySize,
                         FLASH_SMEM);

    // one-time fp16 conversion of GEMM inputs
    conv_pass<<<(Mm_ * Cc_) / 1024, 256>>>(x, xh);
    conv_pass<<<(Cc_ * Cc_) / 1024, 256>>>(Wq, wqh);
    conv_pass<<<(Cc_ * KVN_) / 1024, 256>>>(Wkv, wkvh);
    conv_pass<<<(Cc_ * Cc_) / 1024, 256>>>(Wp, wph);

    // fused q + kv projections (fp16 outputs)
    qkv_gemm<<<dim3(24, Mm_ / 128), 256, GEMM_SMEM>>>(
        xh, wqh, bq, wkvh, bkv, qh, kvh);
    // attention (fp16 mma, fp32 softmax, Bc=128)
    flash_h<<<dim3(Tt_ / 128, Hh_, Bb_), 256, FLASH_SMEM>>>(qh, kvh, yh);
    // out = y @ Wp + bp
    pgemm_h<<<dim3(Cc_ / 128, Mm_ / 128), 256, GEMM_SMEM>>>(yh, wph, bp, out);
}

// round 15
// speedup vs baseline: 7.5886x; 1.0196x over previous
#include <cuda_runtime.h>
#include <cuda_fp16.h>
#include <math.h>
#include <stdint.h>

// Problem constants
#define Bb_ 2
#define Tt_ 2048
#define Cc_ 2048
#define Hh_ 16
#define HKV_ 4
#define HDv_ 128
#define Mm_ (Bb_ * Tt_)
#define KVN_ 1024

// Scratch (device globals; no allocation allowed)
__device__ __half g_qh[(size_t)Mm_ * Cc_];
__device__ __half g_kvh[(size_t)Mm_ * KVN_];
__device__ __half g_yh[(size_t)Mm_ * Cc_];
__device__ __half g_xh[(size_t)Mm_ * Cc_];
__device__ __half g_wqh[(size_t)Cc_ * Cc_];
__device__ __half g_wkvh[(size_t)Cc_ * KVN_];
__device__ __half g_wph[(size_t)Cc_ * Cc_];

// ---- helpers ----------------------------------------------------------------
typedef unsigned long long u64t;

__device__ __forceinline__ u64t pk2(float lo, float hi) {
    u64t r;
    asm("mov.b64 %0, {%1, %2};" : "=l"(r) : "f"(lo), "f"(hi));
    return r;
}
__device__ __forceinline__ void mul2(u64t& d, u64t a, u64t b) {
    asm("mul.rn.f32x2 %0, %1, %2;" : "=l"(d) : "l"(a), "l"(b));
}
__device__ __forceinline__ float2 upk(u64t v) {
    float2 f;
    asm("mov.b64 {%0, %1}, %2;" : "=f"(f.x), "=f"(f.y) : "l"(v));
    return f;
}
__device__ __forceinline__ uint32_t f2h2(float a, float b) {
    const __half2 h = __floats2half2_rn(a, b);
    return *(const uint32_t*)&h;
}
__device__ __forceinline__ void mma_f16(float (&d)[4],
                                        const uint32_t (&a)[4],
                                        const uint32_t (&b)[2]) {
    asm volatile(
        "mma.sync.aligned.m16n8k16.row.col.f32.f16.f16.f32 "
        "{%0,%1,%2,%3}, {%4,%5,%6,%7}, {%8,%9}, {%0,%1,%2,%3};\n"
        : "+f"(d[0]), "+f"(d[1]), "+f"(d[2]), "+f"(d[3])
        : "r"(a[0]), "r"(a[1]), "r"(a[2]), "r"(a[3]), "r"(b[0]), "r"(b[1]));
}
__device__ __forceinline__ void ldsm_x4(uint32_t (&r)[4], uint32_t addr) {
    asm volatile(
        "ldmatrix.sync.aligned.m8n8.x4.shared.b16 {%0,%1,%2,%3}, [%4];"
        : "=r"(r[0]), "=r"(r[1]), "=r"(r[2]), "=r"(r[3]) : "r"(addr));
}
__device__ __forceinline__ void ldsm_x2t(uint32_t (&r)[2], uint32_t addr) {
    asm volatile(
        "ldmatrix.sync.aligned.m8n8.x2.trans.shared.b16 {%0,%1}, [%2];"
        : "=r"(r[0]), "=r"(r[1]) : "r"(addr));
}
__device__ __forceinline__ uint32_t smem_u32(const void* p) {
    uint32_t a;
    asm("{ .reg .u64 t; cvta.to.shared.u64 t, %1; cvt.u32.u64 %0, t; }"
        : "=r"(a) : "l"(p));
    return a;
}
__device__ __forceinline__ void cp16(uint32_t dst, const void* src) {
    asm volatile("cp.async.cg.shared.global [%0], [%1], 16;"
                 :: "r"(dst), "l"(src));
}
#define CP_COMMIT() asm volatile("cp.async.commit_group;" ::: "memory")
#define CP_WAIT(n)  asm volatile("cp.async.wait_group %0;" :: "n"(n) : "memory")

// ---------------------------------------------------------------------------
// One fused fp32 -> fp16 conversion over all four inputs.
// Segment block ranges: x 8192, Wq 4096, Wkv 2048, Wp 4096 (1024 floats/blk).
// ---------------------------------------------------------------------------
__global__ void __launch_bounds__(256)
conv_all(const float* __restrict__ x,   __half* __restrict__ xh,
         const float* __restrict__ wq,  __half* __restrict__ wqh,
         const float* __restrict__ wkv, __half* __restrict__ wkvh,
         const float* __restrict__ wp,  __half* __restrict__ wph)
{
    const int blk = blockIdx.x;
    const float* in;
    __half* out;
    int rel;
    if (blk < 8192)        { in = x;   out = xh;   rel = blk; }
    else if (blk < 12288)  { in = wq;  out = wqh;  rel = blk - 8192; }
    else if (blk < 14336)  { in = wkv; out = wkvh; rel = blk - 12288; }
    else                   { in = wp;  out = wph;  rel = blk - 14336; }

    const size_t i = ((size_t)rel * 256 + threadIdx.x) * 4;
    const float4 v = *(const float4*)(in + i);
    *(__half2*)(out + i)     = __floats2half2_rn(v.x, v.y);
    *(__half2*)(out + i + 2) = __floats2half2_rn(v.z, v.w);
}

// ---------------------------------------------------------------------------
// fp16 m16n8k16 GEMM core, BK=64, 3-stage cp.async, ldmatrix fragments.
// 128x128 CTA, 8 warps (64x32). One barrier per 64 K.
// ---------------------------------------------------------------------------
#define GSTG 3
#define LDAH 72
#define LDBH 136
#define A_BYTES (128 * LDAH * 2)
#define B_BYTES (64 * LDBH * 2)
#define STG_BYTES (A_BYTES + B_BYTES)
#define GEMM_SMEM (GSTG * STG_BYTES)

__device__ __forceinline__ void gemm_issue_h(uint32_t sb, int buf,
                                             const __half* Ah, const __half* Bh,
                                             int K, int N, int k0, int tid)
{
    const uint32_t base = sb + buf * STG_BYTES;
#pragma unroll
    for (int u = 0; u < 4; u++) {
        const int ia = tid + u * 256;
        const int m  = ia >> 3;
        const int c8 = (ia & 7) * 8;
        cp16(base + (m * LDAH + c8) * 2, Ah + (size_t)m * K + k0 + c8);
        const int ib = tid + u * 256;
        const int k  = ib >> 4;
        const int n8 = (ib & 15) * 8;
        cp16(base + A_BYTES + (k * LDBH + n8) * 2,
             Bh + (size_t)(k0 + k) * N + n8);
    }
}

// outMode: 0 -> fp32 C, 1 -> fp16 C (scaled by outScale)
template <int outMode>
__device__ __forceinline__ void gemm_core_h(const __half* Ah, const __half* Bh,
                                            const float* biasb, void* Cb,
                                            int K, int N, float outScale,
                                            uint32_t sb)
{
    const int tid  = threadIdx.x;
    const int wid  = tid >> 5;
    const int lane = tid & 31;
    const int g    = lane >> 2;
    const int tg   = lane & 3;
    const int wm   = wid & 1;
    const int wn   = wid >> 1;

    const int arow_l = (lane & 7) + 8 * ((lane >> 3) & 1);
    const int acol_l = (lane >> 4) * 8;

    float acc[4][4][4];
#pragma unroll
    for (int mi = 0; mi < 4; mi++)
#pragma unroll
        for (int ni = 0; ni < 4; ni++)
#pragma unroll
            for (int r = 0; r < 4; r++) acc[mi][ni][r] = 0.f;

    const int nt = K / 64;

#pragma unroll
    for (int s = 0; s < GSTG - 1; s++) {
        if (s < nt) gemm_issue_h(sb, s, Ah, Bh, K, N, s * 64, tid);
        CP_COMMIT();
    }

    int buf = 0;
    for (int t = 0; t < nt; ++t) {
        CP_WAIT(1);
        __syncthreads();
        if (t + 2 < nt)
            gemm_issue_h(sb, (t + 2) % GSTG, Ah, Bh, K, N, (t + 2) * 64, tid);
        CP_COMMIT();

        const uint32_t base = sb + buf * STG_BYTES;
#pragma unroll
        for (int kc = 0; kc < 4; kc++) {
            uint32_t afr[4][4];
#pragma unroll
            for (int mi = 0; mi < 4; mi++) {
                const int row = wm * 64 + mi * 16 + arow_l;
                const int col = kc * 16 + acol_l;
                ldsm_x4(afr[mi], base + (row * LDAH + col) * 2);
            }
            uint32_t bfr[4][2];
#pragma unroll
            for (int ni = 0; ni < 4; ni++) {
                const int krow = kc * 16 + arow_l;
                const int ncol = wn * 32 + ni * 8;
                ldsm_x2t(bfr[ni], base + A_BYTES + (krow * LDBH + ncol) * 2);
            }
#pragma unroll
            for (int mi = 0; mi < 4; mi++)
#pragma unroll
                for (int ni = 0; ni < 4; ni++)
                    mma_f16(acc[mi][ni], afr[mi], bfr[ni]);
        }
        buf = (buf + 1 == GSTG) ? 0 : buf + 1;
    }

    // ---- epilogue: fused bias (+ scale for fp16 outputs) ----
#pragma unroll
    for (int mi = 0; mi < 4; mi++) {
        const int r0 = wm * 64 + mi * 16 + g;
#pragma unroll
        for (int ni = 0; ni < 4; ni++) {
            const int c0 = wn * 32 + ni * 8 + tg * 2;
            const float bx0 = biasb[c0], bx1 = biasb[c0 + 1];
            const float a0 = acc[mi][ni][0] + bx0;
            const float a1 = acc[mi][ni][1] + bx1;
            const float a2 = acc[mi][ni][2] + bx0;
            const float a3 = acc[mi][ni][3] + bx1;
            if (outMode == 0) {
                float* Cf = (float*)Cb;
                *(float2*)(Cf + (size_t)r0 * N + c0)       = make_float2(a0, a1);
                *(float2*)(Cf + (size_t)(r0 + 8) * N + c0) = make_float2(a2, a3);
            } else {
                __half* Ch = (__half*)Cb;
                *(__half2*)(Ch + (size_t)r0 * N + c0) =
                    __floats2half2_rn(a0 * outScale, a1 * outScale);
                *(__half2*)(Ch + (size_t)(r0 + 8) * N + c0) =
                    __floats2half2_rn(a2 * outScale, a3 * outScale);
            }
        }
    }
}

// Fused q+kv projection (fp16 outputs): grid.x in [0,24).
// q branch output pre-scaled by 1/sqrt(HD).
__global__ void __launch_bounds__(256, 2)
qkv_gemm(const __half* __restrict__ xh,
         const __half* __restrict__ wqh, const float* __restrict__ bq,
         const __half* __restrict__ wkvh, const float* __restrict__ bkv,
         __half* __restrict__ qh, __half* __restrict__ kvh)
{
    extern __shared__ uint32_t smw[];
    const uint32_t sb = smem_u32(smw);
    const int bx = blockIdx.x;
    const __half* Ab = xh + (size_t)blockIdx.y * 128 * Cc_;

    if (bx < 16) {
        const int cb = bx * 128;
        gemm_core_h<1>(Ab, wqh + cb, bq + cb,
                       qh + (size_t)blockIdx.y * 128 * Cc_ + cb,
                       Cc_, Cc_, 0.08838834764831843f, sb);
    } else {
        const int cb = (bx - 16) * 128;
        gemm_core_h<1>(Ab, wkvh + cb, bkv + cb,
                       kvh + (size_t)blockIdx.y * 128 * KVN_ + cb,
                       Cc_, KVN_, 1.0f, sb);
    }
}

// Final projection: out = yh @ Wp + bp (fp32 output)
__global__ void __launch_bounds__(256, 2)
pgemm_h(const __half* __restrict__ A, const __half* __restrict__ B,
        const float* __restrict__ bias, float* __restrict__ C)
{
    extern __shared__ uint32_t smw[];
    const uint32_t sb = smem_u32(smw);
    const int cb = blockIdx.x * 128;
    gemm_core_h<0>(A + (size_t)blockIdx.y * 128 * Cc_, B + cb, bias + cb,
                   C + (size_t)blockIdx.y * 128 * Cc_ + cb,
                   Cc_, Cc_, 1.0f, sb);
}

// ---------------------------------------------------------------------------
// Flash attention, fp16 m16n8k16, Bc=128, double-buffered cp.async K/V,
// one __syncthreads per kt. P stays in registers (C-frag == A-frag layout).
// Diagonal-tile MMA skipping per warp. Br=128 (8 warps x 16 rows), HD=128.
// ---------------------------------------------------------------------------
#define LDKH 136                         // K/V smem row stride (halfs)
#define KVB (128 * LDKH * 2)             // 34816 B per K or V buffer
#define STG_FB (2 * KVB)                 // K+V stage: 69632
#define FLASH_SMEM (2 * STG_FB)          // 139264 B

__device__ __forceinline__ void flash_issue_h(uint32_t sb, int buf,
                                              const __half* kvbase, int tid)
{
    const uint32_t kb = sb + buf * STG_FB;
    const uint32_t vb = kb + KVB;
#pragma unroll
    for (int u = 0; u < 8; u++) {
        const int i  = tid + u * 256;     // 0..2047
        const int r  = i >> 4;            // 0..127
        const int c8 = (i & 15) * 8;
        const __half* src = kvbase + (size_t)r * KVN_ + c8;
        cp16(kb + (r * LDKH + c8) * 2, src);
        cp16(vb + (r * LDKH + c8) * 2, src + 512);
    }
}

__global__ void __launch_bounds__(256, 1)
flash_h(const __half* __restrict__ q, const __half* __restrict__ kv,
        __half* __restrict__ y)
{
    extern __shared__ char smc[];
    const uint32_t sb = smem_u32(smc);

    const int qt = (int)gridDim.x - 1 - (int)blockIdx.x;  // longest-first
    const int h  = blockIdx.y;
    const int b  = blockIdx.z;
    const int kvh = h & (HKV_ - 1);

    const int tid  = threadIdx.x;
    const int w    = tid >> 5;
    const int lane = tid & 31;
    const int g    = lane >> 2;
    const int tg   = lane & 3;
    const int arow_l = (lane & 7) + 8 * ((lane >> 3) & 1);

    const int rloc0 = w * 16 + g;
    const int grow0 = qt * 128 + rloc0;
    const int grow1 = grow0 + 8;

    // ---- load Q once as fp16 A-fragments (pre-scaled by qkv_gemm) ----
    uint32_t qf[8][4];
    {
        const __half* qb = q + ((size_t)(b * Tt_) + qt * 128 + w * 16) * Cc_
                             + h * HDv_;
#pragma unroll
        for (int kc = 0; kc < 8; kc++) {
            const int d0 = kc * 16 + tg * 2;
            qf[kc][0] = *(const uint32_t*)(qb + (size_t)g * Cc_ + d0);
            qf[kc][1] = *(const uint32_t*)(qb + (size_t)(g + 8) * Cc_ + d0);
            qf[kc][2] = *(const uint32_t*)(qb + (size_t)g * Cc_ + d0 + 8);
            qf[kc][3] = *(const uint32_t*)(qb + (size_t)(g + 8) * Cc_ + d0 + 8);
        }
    }

    float of[16][4];
#pragma unroll
    for (int ni = 0; ni < 16; ni++)
#pragma unroll
        for (int r = 0; r < 4; r++) of[ni][r] = 0.f;
    float m0 = -INFINITY, m1 = -INFINITY, l0 = 0.f, l1 = 0.f;

    const __half* kvb0 = kv + (size_t)(b * Tt_) * KVN_ + kvh * HDv_;

    flash_issue_h(sb, 0, kvb0, tid);
    CP_COMMIT();

    for (int kt = 0; kt <= qt; ++kt) {
        const int cur = kt & 1;
        CP_WAIT(0);
        __syncthreads();
        if (kt < qt) {
            flash_issue_h(sb, cur ^ 1, kvb0 + (size_t)(kt + 1) * 128 * KVN_, tid);
            CP_COMMIT();
        }

        const uint32_t vbase = sb + cur * STG_FB + KVB;
        const __half* Kb = (const __half*)(smc + cur * STG_FB);

        const bool diag = (kt == qt);
        const int nimax = diag ? (2 * w + 2) : 16;   // active S n-tiles
        const int kcmax = diag ? (w + 1) : 8;        // active PV k-chunks

        // ---- S = Q K^T (already scaled via pre-scaled Q) ----
        float sf[16][4];
#pragma unroll
        for (int ni = 0; ni < 16; ni++)
#pragma unroll
            for (int r = 0; r < 4; r++) sf[ni][r] = 0.f;

#pragma unroll
        for (int kc = 0; kc < 8; kc++) {
#pragma unroll
            for (int ni = 0; ni < 16; ni++) {
                if (ni < nimax) {
                    uint32_t bfr[2];
                    const __half* krow =
                        Kb + (ni * 8 + g) * LDKH + kc * 16 + tg * 2;
                    bfr[0] = *(const uint32_t*)(krow);
                    bfr[1] = *(const uint32_t*)(krow + 8);
                    mma_f16(sf[ni], qf[kc], bfr);
                }
            }
        }

        // ---- causal mask (diagonal tile only) ----
        if (diag) {
#pragma unroll
            for (int ni = 0; ni < 16; ni++) {
                if (ni >= nimax) {
                    sf[ni][0] = sf[ni][1] = sf[ni][2] = sf[ni][3] = -1e30f;
                } else {
                    const int c0 = kt * 128 + ni * 8 + tg * 2;
                    if (c0 > grow0)     sf[ni][0] = -1e30f;
                    if (c0 + 1 > grow0) sf[ni][1] = -1e30f;
                    if (c0 > grow1)     sf[ni][2] = -1e30f;
                    if (c0 + 1 > grow1) sf[ni][3] = -1e30f;
                }
            }
        }

        // ---- online softmax (rows g, g+8) ----
        float mx0 = -1e30f, mx1 = -1e30f;
#pragma unroll
        for (int ni = 0; ni < 16; ni++) {
            mx0 = fmaxf(mx0, fmaxf(sf[ni][0], sf[ni][1]));
            mx1 = fmaxf(mx1, fmaxf(sf[ni][2], sf[ni][3]));
        }
        mx0 = fmaxf(mx0, __shfl_xor_sync(0xffffffffu, mx0, 1));
        mx0 = fmaxf(mx0, __shfl_xor_sync(0xffffffffu, mx0, 2));
        mx1 = fmaxf(mx1, __shfl_xor_sync(0xffffffffu, mx1, 1));
        mx1 = fmaxf(mx1, __shfl_xor_sync(0xffffffffu, mx1, 2));

        const float nm0 = fmaxf(m0, mx0);
        const float nm1 = fmaxf(m1, mx1);
        float sum0 = 0.f, sum1 = 0.f;
#pragma unroll
        for (int ni = 0; ni < 16; ni++) {
            sf[ni][0] = __expf(sf[ni][0] - nm0);
            sf[ni][1] = __expf(sf[ni][1] - nm0);
            sf[ni][2] = __expf(sf[ni][2] - nm1);
            sf[ni][3] = __expf(sf[ni][3] - nm1);
            sum0 += sf[ni][0] + sf[ni][1];
            sum1 += sf[ni][2] + sf[ni][3];
        }
        sum0 += __shfl_xor_sync(0xffffffffu, sum0, 1);
        sum0 += __shfl_xor_sync(0xffffffffu, sum0, 2);
        sum1 += __shfl_xor_sync(0xffffffffu, sum1, 1);
        sum1 += __shfl_xor_sync(0xffffffffu, sum1, 2);

        const float al0 = __expf(m0 - nm0);
        const float al1 = __expf(m1 - nm1);
        m0 = nm0; m1 = nm1;
        l0 = l0 * al0 + sum0;
        l1 = l1 * al1 + sum1;

        // ---- rescale O ----
        {
            const u64t a0p = pk2(al0, al0);
            const u64t a1p = pk2(al1, al1);
#pragma unroll
            for (int ni = 0; ni < 16; ni++) {
                u64t v01 = pk2(of[ni][0], of[ni][1]);
                u64t v23 = pk2(of[ni][2], of[ni][3]);
                mul2(v01, v01, a0p);
                mul2(v23, v23, a1p);
                const float2 f01 = upk(v01), f23 = upk(v23);
                of[ni][0] = f01.x; of[ni][1] = f01.y;
                of[ni][2] = f23.x; of[ni][3] = f23.y;
            }
        }

        // ---- O += P V : P built in registers from sf (C-frag == A-frag) ----
#pragma unroll
        for (int kc = 0; kc < 8; kc++) {
            if (kc < kcmax) {
                uint32_t pa[4];
                pa[0] = f2h2(sf[2 * kc][0],     sf[2 * kc][1]);
                pa[1] = f2h2(sf[2 * kc][2],     sf[2 * kc][3]);
                pa[2] = f2h2(sf[2 * kc + 1][0], sf[2 * kc + 1][1]);
                pa[3] = f2h2(sf[2 * kc + 1][2], sf[2 * kc + 1][3]);
#pragma unroll
                for (int ni = 0; ni < 16; ni++) {
                    uint32_t vb2[2];
                    ldsm_x2t(vb2, vbase + ((kc * 16 + arow_l) * LDKH + ni * 8) * 2);
                    mma_f16(of[ni], pa, vb2);
                }
            }
        }
    }

    // ---- normalize + store fp16 ----
    const float inv0 = 1.f / l0;
    const float inv1 = 1.f / l1;
    __half* y0 = y + ((size_t)(b * Tt_) + grow0) * Cc_ + h * HDv_;
    __half* y1 = y + ((size_t)(b * Tt_) + grow1) * Cc_ + h * HDv_;
#pragma unroll
    for (int ni = 0; ni < 16; ni++) {
        const int c0 = ni * 8 + tg * 2;
        *(__half2*)(y0 + c0) =
            __floats2half2_rn(of[ni][0] * inv0, of[ni][1] * inv0);
        *(__half2*)(y1 + c0) =
            __floats2half2_rn(of[ni][2] * inv1, of[ni][3] * inv1);
    }
}

// ---------------------------------------------------------------------------
extern "C" void kernel_launch(void* const* d_in, const int* in_sizes, int n_in,
                              void* d_out, int out_size)
{
    const float* x   = (const float*)d_in[0];
    const float* Wkv = (const float*)d_in[1];
    const float* bkv = (const float*)d_in[2];
    const float* Wq  = (const float*)d_in[3];
    const float* bq  = (const float*)d_in[4];
    const float* Wp  = (const float*)d_in[5];
    const float* bp  = (const float*)d_in[6];
    float* out = (float*)d_out;

    __half *qh, *kvh, *yh, *xh, *wqh, *wkvh, *wph;
    cudaGetSymbolAddress((void**)&qh,   g_qh);
    cudaGetSymbolAddress((void**)&kvh,  g_kvh);
    cudaGetSymbolAddress((void**)&yh,   g_yh);
    cudaGetSymbolAddress((void**)&xh,   g_xh);
    cudaGetSymbolAddress((void**)&wqh,  g_wqh);
    cudaGetSymbolAddress((void**)&wkvh, g_wkvh);
    cudaGetSymbolAddress((void**)&wph,  g_wph);

    cudaFuncSetAttribute(qkv_gemm,
                         cudaFuncAttributeMaxDynamicSharedMemorySize,
                         GEMM_SMEM);
    cudaFuncSetAttribute(pgemm_h,
                         cudaFuncAttributeMaxDynamicSharedMemorySize,
                         GEMM_SMEM);
    cudaFuncSetAttribute(flash_h,
                         cudaFuncAttributeMaxDynamicSharedMemorySize,
                         FLASH_SMEM);

    // one fused fp16 conversion of all GEMM inputs
    conv_all<<<18432, 256>>>(x, xh, Wq, wqh, Wkv, wkvh, Wp, wph);

    // fused q + kv projections (q pre-scaled by 1/sqrt(HD))
    qkv_gemm<<<dim3(24, Mm_ / 128), 256, GEMM_SMEM>>>(
        xh, wqh, bq, wkvh, bkv, qh, kvh);
    // attention (fp16 mma, fp32 softmax, register-resident P)
    flash_h<<<dim3(Tt_ / 128, Hh_, Bb_), 256, FLASH_SMEM>>>(qh, kvh, yh);
    // out = y @ Wp + bp
    pgemm_h<<<dim3(Cc_ / 128, Mm_ / 128), 256, GEMM_SMEM>>>(yh, wph, bp, out);
}